// round 1
// baseline (speedup 1.0000x reference)
#include <cuda_runtime.h>

#define Bc 2
#define Nv 9
#define CBc 80
#define Hh 120
#define Ww 160
#define Dd 64
#define Pp 80000
#define HW (Hh*Ww)            // 19200
#define MTOT (Bc*Nv*HW)       // 345600
#define NEGV -10000.0f

// Scratch (static __device__ arrays — allocation-free per harness rules)
__device__ float g_KM1[(size_t)MTOT*Dd];   // key_maps block 1 (bias included), [pix][d]
__device__ float g_KM2[(size_t)MTOT*Dd];   // key_maps block 2
__device__ float g_F1[(size_t)Pp*Dd];      // intermediate voxel features

// ---------------------------------------------------------------------------
// Kernel 1: key_maps for BOTH blocks in one pass over image features.
// out[pix, d] = sum_c img[bn, c, pix] * Wk[d, c] + bk[d]
// Tile: 64 pixels x 128 d (64 for Wk1, 64 for Wk2). 256 threads, micro 4x8.
// ---------------------------------------------------------------------------
__global__ __launch_bounds__(256) void keymap_kernel(
    const float* __restrict__ img,
    const float* __restrict__ Wk1, const float* __restrict__ bk1,
    const float* __restrict__ Wk2, const float* __restrict__ bk2)
{
    __shared__ __align__(16) float Bsh[CBc*128];   // [c][d]  40 KB
    __shared__ __align__(16) float Ash[16][64];    // [k][pix] 4 KB
    __shared__ float bias_sh[128];

    int tid = threadIdx.x;
    for (int t = tid; t < CBc*128; t += 256) {
        int d = t & 127, c = t >> 7;
        Bsh[t] = (d < 64) ? Wk1[d*CBc + c] : Wk2[(d-64)*CBc + c];
    }
    if (tid < 128) bias_sh[tid] = (tid < 64) ? bk1[tid] : bk2[tid-64];

    int m0   = blockIdx.x * 64;          // global pixel tile start (HW % 64 == 0)
    int bn   = m0 / HW;                  // (b*Nv + n) slab
    int pix0 = m0 - bn*HW;
    const float* Abase = img + (size_t)bn*CBc*HW + pix0;

    int w = tid >> 5, l = tid & 31;
    int dg = l & 15;                     // d group: d = dg*8 .. +7 (of 128)
    int pg = w*2 + (l >> 4);             // pixel group: pix = pg*4 .. +3

    float acc[4][8];
    #pragma unroll
    for (int i = 0; i < 4; i++)
        #pragma unroll
        for (int j = 0; j < 8; j++) acc[i][j] = 0.f;

    #pragma unroll
    for (int kc = 0; kc < 5; kc++) {     // K = 80 = 5 x 16
        __syncthreads();
        #pragma unroll
        for (int r = 0; r < 4; r++) {
            int row = (tid >> 6) + r*4;
            int col = tid & 63;
            Ash[row][col] = Abase[(size_t)(kc*16 + row)*HW + col];
        }
        __syncthreads();
        #pragma unroll
        for (int k = 0; k < 16; k++) {
            float4 a  = *(const float4*)&Ash[k][pg*4];
            const float* bp = &Bsh[(kc*16 + k)*128 + dg*8];
            float4 b0 = *(const float4*)bp;
            float4 b1 = *(const float4*)(bp + 4);
            float av[4] = {a.x, a.y, a.z, a.w};
            float bv[8] = {b0.x, b0.y, b0.z, b0.w, b1.x, b1.y, b1.z, b1.w};
            #pragma unroll
            for (int i = 0; i < 4; i++)
                #pragma unroll
                for (int j = 0; j < 8; j++)
                    acc[i][j] += av[i] * bv[j];
        }
    }

    float* outp  = (dg < 8) ? g_KM1 : g_KM2;
    int    dbase = (dg & 7) * 8;
    float  bv[8];
    #pragma unroll
    for (int j = 0; j < 8; j++) bv[j] = bias_sh[dg*8 + j];
    #pragma unroll
    for (int i = 0; i < 4; i++) {
        size_t m = (size_t)(m0 + pg*4 + i);
        float4 o0 = make_float4(acc[i][0]+bv[0], acc[i][1]+bv[1], acc[i][2]+bv[2], acc[i][3]+bv[3]);
        float4 o1 = make_float4(acc[i][4]+bv[4], acc[i][5]+bv[5], acc[i][6]+bv[6], acc[i][7]+bv[7]);
        *(float4*)&outp[m*64 + dbase]     = o0;
        *(float4*)&outp[m*64 + dbase + 4] = o1;
    }
}

// ---------------------------------------------------------------------------
// Kernel 2: per-point multi-view attention. One warp per point.
// Lane j owns output dims j and j+32.
// ---------------------------------------------------------------------------
__global__ __launch_bounds__(256) void attn_kernel(
    const float* __restrict__ f_in,
    const int*   __restrict__ coords,
    const float* __restrict__ proj,
    const float* __restrict__ origins,
    const int*   __restrict__ cmask,
    const float* __restrict__ Wq, const float* __restrict__ bq,
    int use2,
    float* __restrict__ f_out)
{
    __shared__ float WqT[64*64];          // transposed: WqT[i][j] = Wq[j][i]
    __shared__ float projs[Bc*Nv*12];
    __shared__ float orig_s[Bc*3];
    __shared__ float bq_s[64];

    int tid = threadIdx.x;
    for (int t = tid; t < 4096; t += 256) WqT[(t & 63)*64 + (t >> 6)] = Wq[t];
    if (tid < Bc*Nv*12) projs[tid] = proj[tid];
    if (tid < Bc*3)     orig_s[tid] = origins[tid];
    if (tid < 64)       bq_s[tid] = bq[tid];
    __syncthreads();

    const float* KM = use2 ? g_KM2 : g_KM1;
    int p    = blockIdx.x * 8 + (tid >> 5);
    int lane = tid & 31;

    float v0 = f_in[(size_t)p*64 + lane];
    float v1 = f_in[(size_t)p*64 + 32 + lane];

    // q = Wq @ v + bq
    float q0 = bq_s[lane], q1 = bq_s[32 + lane];
    #pragma unroll
    for (int i = 0; i < 32; i++) {
        float vi = __shfl_sync(0xffffffffu, v0, i);
        q0 += WqT[i*64 + lane]      * vi;
        q1 += WqT[i*64 + 32 + lane] * vi;
    }
    #pragma unroll
    for (int i = 0; i < 32; i++) {
        float vi = __shfl_sync(0xffffffffu, v1, i);
        q0 += WqT[(32+i)*64 + lane]      * vi;
        q1 += WqT[(32+i)*64 + 32 + lane] * vi;
    }

    int4 cc = __ldg((const int4*)coords + p);
    int bi = cc.w;
    float X = (float)cc.x * 0.16f + orig_s[bi*3 + 0];
    float Y = (float)cc.y * 0.16f + orig_s[bi*3 + 1];
    float Z = (float)cc.z * 0.16f + orig_s[bi*3 + 2];

    float k0s[9], k1s[9], lgs[9];

    #pragma unroll
    for (int n = 0; n < Nv; n++) {
        const float* Pm = &projs[(bi*Nv + n)*12];
        float c0 = Pm[0]*X + Pm[1]*Y + Pm[2]*Z  + Pm[3];
        float c1 = Pm[4]*X + Pm[5]*Y + Pm[6]*Z  + Pm[7];
        float c2 = Pm[8]*X + Pm[9]*Y + Pm[10]*Z + Pm[11];
        float tx = __fdiv_rn(c0, c2);
        float ty = __fdiv_rn(c1, c2);
        float gx = __fdiv_rn(2.0f * tx, (float)(Ww - 1)) - 1.0f;
        float gy = __fdiv_rn(2.0f * ty, (float)(Hh - 1)) - 1.0f;
        bool msk = (fabsf(gx) <= 1.0f) && (fabsf(gy) <= 1.0f) && (c2 > 0.0f);

        float k0 = 0.f, k1 = 0.f, lg = NEGV;
        if (msk) {
            float px = (gx + 1.0f) * 0.5f * (float)(Ww - 1);
            float py = (gy + 1.0f) * 0.5f * (float)(Hh - 1);
            float x0f = floorf(px), y0f = floorf(py);
            float fx = px - x0f,    fy = py - y0f;
            int x0 = (int)x0f, y0 = (int)y0f;
            float w00 = (1.f-fx)*(1.f-fy), w01 = fx*(1.f-fy);
            float w10 = (1.f-fx)*fy,       w11 = fx*fy;
            const float* base = KM + ((size_t)(bi*Nv + n) * HW) * 64;
            {
                int xi = x0, yi = y0;
                if (xi >= 0 && xi < Ww && yi >= 0 && yi < Hh) {
                    const float* c = base + ((size_t)yi*Ww + xi)*64;
                    k0 += w00 * c[lane]; k1 += w00 * c[32 + lane];
                }
            }
            {
                int xi = x0+1, yi = y0;
                if (xi >= 0 && xi < Ww && yi >= 0 && yi < Hh) {
                    const float* c = base + ((size_t)yi*Ww + xi)*64;
                    k0 += w01 * c[lane]; k1 += w01 * c[32 + lane];
                }
            }
            {
                int xi = x0, yi = y0+1;
                if (xi >= 0 && xi < Ww && yi >= 0 && yi < Hh) {
                    const float* c = base + ((size_t)yi*Ww + xi)*64;
                    k0 += w10 * c[lane]; k1 += w10 * c[32 + lane];
                }
            }
            {
                int xi = x0+1, yi = y0+1;
                if (xi >= 0 && xi < Ww && yi >= 0 && yi < Hh) {
                    const float* c = base + ((size_t)yi*Ww + xi)*64;
                    k0 += w11 * c[lane]; k1 += w11 * c[32 + lane];
                }
            }
        }
        float part = q0*k0 + q1*k1;
        #pragma unroll
        for (int off = 16; off; off >>= 1)
            part += __shfl_xor_sync(0xffffffffu, part, off);
        if (msk) lg = part * 0.125f;   // 1/sqrt(64)
        k0s[n] = k0; k1s[n] = k1; lgs[n] = lg;
    }

    // softmax over 9 views + weighted sum
    float mx = lgs[0];
    #pragma unroll
    for (int n = 1; n < Nv; n++) mx = fmaxf(mx, lgs[n]);
    float se = 0.f, y0 = 0.f, y1 = 0.f;
    #pragma unroll
    for (int n = 0; n < Nv; n++) {
        float e = expf(lgs[n] - mx);
        se += e; y0 += e * k0s[n]; y1 += e * k1s[n];
    }
    float inv = __fdiv_rn(1.0f, se);
    y0 *= inv; y1 *= inv;

    if (cmask[p] <= 1) { y0 = 0.f; y1 = 0.f; }

    f_out[(size_t)p*64 + lane]      = v0 + y0;
    f_out[(size_t)p*64 + 32 + lane] = v1 + y1;
}

// ---------------------------------------------------------------------------
extern "C" void kernel_launch(void* const* d_in, const int* in_sizes, int n_in,
                              void* d_out, int out_size)
{
    (void)in_sizes; (void)n_in; (void)out_size;
    const float* img    = (const float*)d_in[0];   // Image_Features
    const int*   coords = (const int*)  d_in[1];   // Coordinates
    const float* vox    = (const float*)d_in[2];   // Voxel_Features
    const float* proj   = (const float*)d_in[3];   // Projections
    const float* orig   = (const float*)d_in[4];   // Origins
    const int*   cmask  = (const int*)  d_in[5];   // count_mask
    const float* Wq1 = (const float*)d_in[6];
    const float* bq1 = (const float*)d_in[7];
    const float* Wk1 = (const float*)d_in[8];
    const float* bk1 = (const float*)d_in[9];
    const float* Wq2 = (const float*)d_in[10];
    const float* bq2 = (const float*)d_in[11];
    const float* Wk2 = (const float*)d_in[12];
    const float* bk2 = (const float*)d_in[13];
    float* out = (float*)d_out;

    float* f1 = nullptr;
    cudaGetSymbolAddress((void**)&f1, g_F1);

    keymap_kernel<<<MTOT/64, 256>>>(img, Wk1, bk1, Wk2, bk2);
    attn_kernel<<<Pp/8, 256>>>(vox, coords, proj, orig, cmask, Wq1, bq1, 0, f1);
    attn_kernel<<<Pp/8, 256>>>(f1,  coords, proj, orig, cmask, Wq2, bq2, 1, out);
}

// round 3
// speedup vs baseline: 1.2630x; 1.2630x over previous
#include <cuda_runtime.h>

#define Bc 2
#define Nv 9
#define CBc 80
#define Hh 120
#define Ww 160
#define Dd 64
#define Pp 80000
#define HW (Hh*Ww)            // 19200
#define MTOT (Bc*Nv*HW)       // 345600
#define NEGV -10000.0f

// Scratch (static __device__ arrays — allocation-free per harness rules)
__device__ float g_KM1[(size_t)MTOT*Dd];   // key_maps block 1 (bias included), [pix][d]
__device__ float g_KM2[(size_t)MTOT*Dd];   // key_maps block 2

// ---------------------------------------------------------------------------
// Kernel 1: key_maps for BOTH blocks. Tile 128 px x 128 d, 256 thr, 8x8 micro.
// Thread (tx,ty): d cols {tx*4..+3} (KM1) and {64+tx*4..+3} (KM2);
//                 px rows {ty*4..+3} and {64+ty*4..+3}.  All LDS conflict-free.
// Static smem: 40KB (Bsh) + 4KB (Ash) + 0.5KB = 44.5KB < 48KB cap.
// ---------------------------------------------------------------------------
__global__ __launch_bounds__(256) void keymap_kernel(
    const float* __restrict__ img,
    const float* __restrict__ Wk1, const float* __restrict__ bk1,
    const float* __restrict__ Wk2, const float* __restrict__ bk2)
{
    __shared__ __align__(16) float Bsh[CBc][128];   // [c][d]  40 KB
    __shared__ __align__(16) float Ash[8][128];     // [k][px]  4 KB
    __shared__ float bias_sh[128];

    int tid = threadIdx.x;
    for (int t = tid; t < CBc*128; t += 256) {
        int c = t >> 7, d = t & 127;
        Bsh[c][d] = (d < 64) ? Wk1[d*CBc + c] : Wk2[(d-64)*CBc + c];
    }
    if (tid < 128) bias_sh[tid] = (tid < 64) ? bk1[tid] : bk2[tid-64];

    int m0   = blockIdx.x * 128;         // HW % 128 == 0 -> single bn slab
    int bn   = m0 / HW;
    int pix0 = m0 - bn*HW;
    const float* Abase = img + (size_t)bn*CBc*HW + pix0;

    int tx = tid & 15, ty = tid >> 4;

    float acc[8][8];
    #pragma unroll
    for (int i = 0; i < 8; i++)
        #pragma unroll
        for (int j = 0; j < 8; j++) acc[i][j] = 0.f;

    #pragma unroll
    for (int kc = 0; kc < 10; kc++) {    // K = 80 = 10 x 8
        __syncthreads();
        {
            int k  = tid >> 5;           // 256 float4 slots = 8 rows x 32
            int p4 = tid & 31;
            *(float4*)&Ash[k][p4*4] =
                *(const float4*)&Abase[(size_t)(kc*8 + k)*HW + p4*4];
        }
        __syncthreads();
        #pragma unroll
        for (int k = 0; k < 8; k++) {
            float4 a0 = *(const float4*)&Ash[k][ty*4];
            float4 a1 = *(const float4*)&Ash[k][64 + ty*4];
            float4 b0 = *(const float4*)&Bsh[kc*8 + k][tx*4];
            float4 b1 = *(const float4*)&Bsh[kc*8 + k][64 + tx*4];
            float av[8] = {a0.x,a0.y,a0.z,a0.w, a1.x,a1.y,a1.z,a1.w};
            float bv[8] = {b0.x,b0.y,b0.z,b0.w, b1.x,b1.y,b1.z,b1.w};
            #pragma unroll
            for (int i = 0; i < 8; i++)
                #pragma unroll
                for (int j = 0; j < 8; j++)
                    acc[i][j] += av[i] * bv[j];
        }
    }

    float bj1[4], bj2[4];
    #pragma unroll
    for (int j = 0; j < 4; j++) {
        bj1[j] = bias_sh[tx*4 + j];
        bj2[j] = bias_sh[64 + tx*4 + j];
    }
    #pragma unroll
    for (int i = 0; i < 8; i++) {
        int m = m0 + ((i < 4) ? (ty*4 + i) : (64 + ty*4 + (i - 4)));
        float4 o1 = make_float4(acc[i][0]+bj1[0], acc[i][1]+bj1[1],
                                acc[i][2]+bj1[2], acc[i][3]+bj1[3]);
        float4 o2 = make_float4(acc[i][4]+bj2[0], acc[i][5]+bj2[1],
                                acc[i][6]+bj2[2], acc[i][7]+bj2[3]);
        *(float4*)&g_KM1[(size_t)m*64 + tx*4] = o1;
        *(float4*)&g_KM2[(size_t)m*64 + tx*4] = o2;
    }
}

// ---------------------------------------------------------------------------
// Kernel 2: BOTH attention blocks fused. One warp per point.
// Lane j owns dims {2j, 2j+1} (float2). Geometry computed once; KM1 and KM2
// gathered together (8 independent loads/view); online softmax for block 1;
// k2 kept in registers so block 2 is memory-free.
// ---------------------------------------------------------------------------
__global__ __launch_bounds__(256) void attn_fused_kernel(
    const float* __restrict__ vox,
    const int*   __restrict__ coords,
    const float* __restrict__ proj,
    const float* __restrict__ origins,
    const int*   __restrict__ cmask,
    const float* __restrict__ Wq1, const float* __restrict__ bq1,
    const float* __restrict__ Wq2, const float* __restrict__ bq2,
    float* __restrict__ out)
{
    __shared__ float WqT1[64][64];        // WqT[i][d] = Wq[d][i]
    __shared__ float WqT2[64][64];
    __shared__ float projs[Bc*Nv*12];
    __shared__ float orig_s[Bc*3];
    __shared__ float bq1_s[64], bq2_s[64];

    int tid = threadIdx.x;
    for (int t = tid; t < 4096; t += 256) {
        WqT1[t & 63][t >> 6] = Wq1[t];
        WqT2[t & 63][t >> 6] = Wq2[t];
    }
    if (tid < Bc*Nv*12) projs[tid] = proj[tid];
    if (tid < Bc*3)     orig_s[tid] = origins[tid];
    if (tid < 64) { bq1_s[tid] = bq1[tid]; bq2_s[tid] = bq2[tid]; }
    __syncthreads();

    int p    = blockIdx.x * 8 + (tid >> 5);
    int lane = tid & 31;

    float2 v = *(const float2*)&vox[(size_t)p*64 + 2*lane];

    // q1 = Wq1 @ v + bq1
    float2 q1 = make_float2(bq1_s[2*lane], bq1_s[2*lane+1]);
    #pragma unroll
    for (int s = 0; s < 32; s++) {
        float vx = __shfl_sync(0xffffffffu, v.x, s);
        float vy = __shfl_sync(0xffffffffu, v.y, s);
        float2 w0 = *(const float2*)&WqT1[2*s][2*lane];
        float2 w1 = *(const float2*)&WqT1[2*s+1][2*lane];
        q1.x += w0.x*vx + w1.x*vy;
        q1.y += w0.y*vx + w1.y*vy;
    }

    int4 cc = __ldg((const int4*)coords + p);
    int bi = cc.w;
    float X = (float)cc.x * 0.16f + orig_s[bi*3 + 0];
    float Y = (float)cc.y * 0.16f + orig_s[bi*3 + 1];
    float Z = (float)cc.z * 0.16f + orig_s[bi*3 + 2];

    float2 k2s[9];
    unsigned mbits = 0;
    float  m1 = -1e30f, se1 = 0.f;
    float2 y1 = make_float2(0.f, 0.f);

    #pragma unroll
    for (int n = 0; n < Nv; n++) {
        const float* Pm = &projs[(bi*Nv + n)*12];
        float c0 = Pm[0]*X + Pm[1]*Y + Pm[2]*Z  + Pm[3];
        float c1 = Pm[4]*X + Pm[5]*Y + Pm[6]*Z  + Pm[7];
        float c2 = Pm[8]*X + Pm[9]*Y + Pm[10]*Z + Pm[11];
        float txp = __fdiv_rn(c0, c2);
        float typ = __fdiv_rn(c1, c2);
        float gx = __fdiv_rn(2.0f * txp, (float)(Ww - 1)) - 1.0f;
        float gy = __fdiv_rn(2.0f * typ, (float)(Hh - 1)) - 1.0f;
        bool msk = (fabsf(gx) <= 1.0f) && (fabsf(gy) <= 1.0f) && (c2 > 0.0f);

        float2 k1 = make_float2(0.f, 0.f);
        float2 k2 = make_float2(0.f, 0.f);
        if (msk) {
            float px = (gx + 1.0f) * 0.5f * (float)(Ww - 1);
            float py = (gy + 1.0f) * 0.5f * (float)(Hh - 1);
            float x0f = floorf(px), y0f = floorf(py);
            float fx = px - x0f,    fy = py - y0f;
            int x0 = (int)x0f, y0 = (int)y0f;       // in-range when msk
            float w00 = (1.f-fx)*(1.f-fy), w01 = fx*(1.f-fy);
            float w10 = (1.f-fx)*fy,       w11 = fx*fy;
            size_t base = ((size_t)(bi*Nv + n)*HW + (size_t)y0*Ww + x0)*64 + 2*lane;
            bool vx1 = (x0 + 1) < Ww;
            bool vy1 = (y0 + 1) < Hh;
            {
                float2 a = *(const float2*)(g_KM1 + base);
                float2 b = *(const float2*)(g_KM2 + base);
                k1.x += w00*a.x; k1.y += w00*a.y;
                k2.x += w00*b.x; k2.y += w00*b.y;
            }
            if (vx1) {
                float2 a = *(const float2*)(g_KM1 + base + 64);
                float2 b = *(const float2*)(g_KM2 + base + 64);
                k1.x += w01*a.x; k1.y += w01*a.y;
                k2.x += w01*b.x; k2.y += w01*b.y;
            }
            if (vy1) {
                float2 a = *(const float2*)(g_KM1 + base + (size_t)Ww*64);
                float2 b = *(const float2*)(g_KM2 + base + (size_t)Ww*64);
                k1.x += w10*a.x; k1.y += w10*a.y;
                k2.x += w10*b.x; k2.y += w10*b.y;
            }
            if (vx1 && vy1) {
                float2 a = *(const float2*)(g_KM1 + base + (size_t)Ww*64 + 64);
                float2 b = *(const float2*)(g_KM2 + base + (size_t)Ww*64 + 64);
                k1.x += w11*a.x; k1.y += w11*a.y;
                k2.x += w11*b.x; k2.y += w11*b.y;
            }
        }

        float part = q1.x*k1.x + q1.y*k1.y;
        #pragma unroll
        for (int off = 16; off; off >>= 1)
            part += __shfl_xor_sync(0xffffffffu, part, off);
        float lg = msk ? part * 0.125f : NEGV;

        // online softmax update (block 1)
        float nm = fmaxf(m1, lg);
        float sc = __expf(m1 - nm);
        float e  = __expf(lg - nm);
        se1  = se1*sc + e;
        y1.x = y1.x*sc + e*k1.x;
        y1.y = y1.y*sc + e*k1.y;
        m1 = nm;

        k2s[n] = k2;
        mbits |= (msk ? 1u : 0u) << n;
    }

    bool sel = cmask[p] > 1;
    float inv1 = __fdiv_rn(1.0f, se1);
    float2 f1;
    f1.x = v.x + (sel ? y1.x*inv1 : 0.f);
    f1.y = v.y + (sel ? y1.y*inv1 : 0.f);

    // q2 = Wq2 @ f1 + bq2
    float2 q2 = make_float2(bq2_s[2*lane], bq2_s[2*lane+1]);
    #pragma unroll
    for (int s = 0; s < 32; s++) {
        float vx = __shfl_sync(0xffffffffu, f1.x, s);
        float vy = __shfl_sync(0xffffffffu, f1.y, s);
        float2 w0 = *(const float2*)&WqT2[2*s][2*lane];
        float2 w1 = *(const float2*)&WqT2[2*s+1][2*lane];
        q2.x += w0.x*vx + w1.x*vy;
        q2.y += w0.y*vx + w1.y*vy;
    }

    // block 2: memory-free, keys already in registers
    float  m2 = -1e30f, se2 = 0.f;
    float2 y2 = make_float2(0.f, 0.f);
    #pragma unroll
    for (int n = 0; n < Nv; n++) {
        float2 k2 = k2s[n];
        float part = q2.x*k2.x + q2.y*k2.y;
        #pragma unroll
        for (int off = 16; off; off >>= 1)
            part += __shfl_xor_sync(0xffffffffu, part, off);
        float lg = ((mbits >> n) & 1u) ? part * 0.125f : NEGV;
        float nm = fmaxf(m2, lg);
        float sc = __expf(m2 - nm);
        float e  = __expf(lg - nm);
        se2  = se2*sc + e;
        y2.x = y2.x*sc + e*k2.x;
        y2.y = y2.y*sc + e*k2.y;
        m2 = nm;
    }
    float inv2 = __fdiv_rn(1.0f, se2);
    float2 o;
    o.x = f1.x + (sel ? y2.x*inv2 : 0.f);
    o.y = f1.y + (sel ? y2.y*inv2 : 0.f);
    *(float2*)&out[(size_t)p*64 + 2*lane] = o;
}

// ---------------------------------------------------------------------------
extern "C" void kernel_launch(void* const* d_in, const int* in_sizes, int n_in,
                              void* d_out, int out_size)
{
    (void)in_sizes; (void)n_in; (void)out_size;
    const float* img    = (const float*)d_in[0];
    const int*   coords = (const int*)  d_in[1];
    const float* vox    = (const float*)d_in[2];
    const float* proj   = (const float*)d_in[3];
    const float* orig   = (const float*)d_in[4];
    const int*   cmask  = (const int*)  d_in[5];
    const float* Wq1 = (const float*)d_in[6];
    const float* bq1 = (const float*)d_in[7];
    const float* Wk1 = (const float*)d_in[8];
    const float* bk1 = (const float*)d_in[9];
    const float* Wq2 = (const float*)d_in[10];
    const float* bq2 = (const float*)d_in[11];
    const float* Wk2 = (const float*)d_in[12];
    const float* bk2 = (const float*)d_in[13];
    float* out = (float*)d_out;

    keymap_kernel<<<MTOT/128, 256>>>(img, Wk1, bk1, Wk2, bk2);
    attn_fused_kernel<<<Pp/8, 256>>>(vox, coords, proj, orig, cmask,
                                     Wq1, bq1, Wq2, bq2, out);
}

// round 4
// speedup vs baseline: 1.6369x; 1.2961x over previous
#include <cuda_runtime.h>

#define Bc 2
#define Nv 9
#define CBc 80
#define Hh 120
#define Ww 160
#define Dd 64
#define Pp 80000
#define HW (Hh*Ww)            // 19200
#define MTOT (Bc*Nv*HW)       // 345600
#define NEGV -10000.0f

// Interleaved key maps: [pix][pair j]{KM1[2j],KM1[2j+1],KM2[2j],KM2[2j+1]}
__device__ float g_KMI[(size_t)MTOT*128];
__device__ float g_Q[(size_t)Pp*128];      // [p][0:64]=q1, [p][64:128]=q2v

// ---------------------------------------------------------------------------
// Kernel 1: key_maps for BOTH blocks, interleaved output.
// Tile 128 px x 128 d, 256 thr, 8x8 micro. smem 44.5KB < 48KB.
// ---------------------------------------------------------------------------
__global__ __launch_bounds__(256) void keymap_kernel(
    const float* __restrict__ img,
    const float* __restrict__ Wk1, const float* __restrict__ bk1,
    const float* __restrict__ Wk2, const float* __restrict__ bk2)
{
    __shared__ __align__(16) float Bsh[CBc][128];   // [c][d]  40 KB
    __shared__ __align__(16) float Ash[8][128];     // [k][px]  4 KB
    __shared__ float bias_sh[128];

    int tid = threadIdx.x;
    for (int t = tid; t < CBc*128; t += 256) {
        int c = t >> 7, d = t & 127;
        Bsh[c][d] = (d < 64) ? Wk1[d*CBc + c] : Wk2[(d-64)*CBc + c];
    }
    if (tid < 128) bias_sh[tid] = (tid < 64) ? bk1[tid] : bk2[tid-64];

    int m0   = blockIdx.x * 128;         // HW % 128 == 0 -> single bn slab
    int bn   = m0 / HW;
    int pix0 = m0 - bn*HW;
    const float* Abase = img + (size_t)bn*CBc*HW + pix0;

    int tx = tid & 15, ty = tid >> 4;

    float acc[8][8];
    #pragma unroll
    for (int i = 0; i < 8; i++)
        #pragma unroll
        for (int j = 0; j < 8; j++) acc[i][j] = 0.f;

    #pragma unroll
    for (int kc = 0; kc < 10; kc++) {    // K = 80 = 10 x 8
        __syncthreads();
        {
            int k  = tid >> 5;
            int p4 = tid & 31;
            *(float4*)&Ash[k][p4*4] =
                *(const float4*)&Abase[(size_t)(kc*8 + k)*HW + p4*4];
        }
        __syncthreads();
        #pragma unroll
        for (int k = 0; k < 8; k++) {
            float4 a0 = *(const float4*)&Ash[k][ty*4];
            float4 a1 = *(const float4*)&Ash[k][64 + ty*4];
            float4 b0 = *(const float4*)&Bsh[kc*8 + k][tx*4];
            float4 b1 = *(const float4*)&Bsh[kc*8 + k][64 + tx*4];
            float av[8] = {a0.x,a0.y,a0.z,a0.w, a1.x,a1.y,a1.z,a1.w};
            float bv[8] = {b0.x,b0.y,b0.z,b0.w, b1.x,b1.y,b1.z,b1.w};
            #pragma unroll
            for (int i = 0; i < 8; i++)
                #pragma unroll
                for (int j = 0; j < 8; j++)
                    acc[i][j] += av[i] * bv[j];
        }
    }

    float bj1[4], bj2[4];
    #pragma unroll
    for (int j = 0; j < 4; j++) {
        bj1[j] = bias_sh[tx*4 + j];          // KM1 dims tx*4+j
        bj2[j] = bias_sh[64 + tx*4 + j];     // KM2 dims tx*4+j
    }
    #pragma unroll
    for (int i = 0; i < 8; i++) {
        int m = m0 + ((i < 4) ? (ty*4 + i) : (64 + ty*4 + (i - 4)));
        // interleaved pairs: pair 2tx -> dims {4tx,4tx+1}; pair 2tx+1 -> {4tx+2,4tx+3}
        float4 oA = make_float4(acc[i][0]+bj1[0], acc[i][1]+bj1[1],
                                acc[i][4]+bj2[0], acc[i][5]+bj2[1]);
        float4 oB = make_float4(acc[i][2]+bj1[2], acc[i][3]+bj1[3],
                                acc[i][6]+bj2[2], acc[i][7]+bj2[3]);
        *(float4*)&g_KMI[(size_t)m*128 + (2*tx)*4]     = oA;
        *(float4*)&g_KMI[(size_t)m*128 + (2*tx+1)*4]   = oB;
    }
}

// ---------------------------------------------------------------------------
// Kernel 2: q-GEMM.  g_Q[p][d] = (d<64 ? Wq1@v+bq1 : Wq2@v+bq2)[d%64]
// C = A(vox, row-major [P][64]) x W^T. Tile 128p x 128d, K=64.
// ---------------------------------------------------------------------------
__global__ __launch_bounds__(256) void qgemm_kernel(
    const float* __restrict__ vox,
    const float* __restrict__ Wq1, const float* __restrict__ bq1,
    const float* __restrict__ Wq2, const float* __restrict__ bq2)
{
    __shared__ __align__(16) float BshT[64][132];   // [k][d]  33.8 KB
    __shared__ __align__(16) float Ash[8][132];     // [k][px]  4.2 KB
    __shared__ float bias_sh[128];

    int tid = threadIdx.x;
    // Load W (128 rows x 64 k) transposed into BshT[k][d]
    {
        int d  = tid >> 1;
        const float* src = (d < 64) ? &Wq1[d*64] : &Wq2[(d-64)*64];
        #pragma unroll
        for (int i = 0; i < 8; i++) {
            int k = (tid & 1)*4 + 8*i;
            float4 w = *(const float4*)&src[k];
            BshT[k+0][d] = w.x; BshT[k+1][d] = w.y;
            BshT[k+2][d] = w.z; BshT[k+3][d] = w.w;
        }
    }
    if (tid < 128) bias_sh[tid] = (tid < 64) ? bq1[tid] : bq2[tid-64];

    int p0 = blockIdx.x * 128;
    int tx = tid & 15, ty = tid >> 4;

    float acc[8][8];
    #pragma unroll
    for (int i = 0; i < 8; i++)
        #pragma unroll
        for (int j = 0; j < 8; j++) acc[i][j] = 0.f;

    #pragma unroll
    for (int kc = 0; kc < 8; kc++) {     // K = 64 = 8 x 8
        __syncthreads();
        {
            int px = tid >> 1;
            int k0 = (tid & 1)*4;
            float4 a = *(const float4*)&vox[(size_t)(p0+px)*64 + kc*8 + k0];
            Ash[k0+0][px] = a.x; Ash[k0+1][px] = a.y;
            Ash[k0+2][px] = a.z; Ash[k0+3][px] = a.w;
        }
        __syncthreads();
        #pragma unroll
        for (int k = 0; k < 8; k++) {
            float4 a0 = *(const float4*)&Ash[k][ty*4];
            float4 a1 = *(const float4*)&Ash[k][64 + ty*4];
            float4 b0 = *(const float4*)&BshT[kc*8 + k][tx*4];
            float4 b1 = *(const float4*)&BshT[kc*8 + k][64 + tx*4];
            float av[8] = {a0.x,a0.y,a0.z,a0.w, a1.x,a1.y,a1.z,a1.w};
            float bv[8] = {b0.x,b0.y,b0.z,b0.w, b1.x,b1.y,b1.z,b1.w};
            #pragma unroll
            for (int i = 0; i < 8; i++)
                #pragma unroll
                for (int j = 0; j < 8; j++)
                    acc[i][j] += av[i] * bv[j];
        }
    }

    float bj1[4], bj2[4];
    #pragma unroll
    for (int j = 0; j < 4; j++) {
        bj1[j] = bias_sh[tx*4 + j];
        bj2[j] = bias_sh[64 + tx*4 + j];
    }
    #pragma unroll
    for (int i = 0; i < 8; i++) {
        int p = p0 + ((i < 4) ? (ty*4 + i) : (64 + ty*4 + (i - 4)));
        float4 o1 = make_float4(acc[i][0]+bj1[0], acc[i][1]+bj1[1],
                                acc[i][2]+bj1[2], acc[i][3]+bj1[3]);
        float4 o2 = make_float4(acc[i][4]+bj2[0], acc[i][5]+bj2[1],
                                acc[i][6]+bj2[2], acc[i][7]+bj2[3]);
        *(float4*)&g_Q[(size_t)p*128 + tx*4]      = o1;
        *(float4*)&g_Q[(size_t)p*128 + 64 + tx*4] = o2;
    }
}

// ---------------------------------------------------------------------------
// Kernel 3: fused attention, one warp per point, sel early-exit.
// Lane j owns dims {2j, 2j+1}. One LDG.128 per lane per corner (both KMs).
// ---------------------------------------------------------------------------
__global__ __launch_bounds__(256) void attn_fused_kernel(
    const float* __restrict__ vox,
    const int*   __restrict__ coords,
    const float* __restrict__ proj,
    const float* __restrict__ origins,
    const int*   __restrict__ cmask,
    const float* __restrict__ Wq2,
    float* __restrict__ out)
{
    __shared__ float WqT2[64][64];        // WqT2[i][d] = Wq2[d][i]
    __shared__ float projs[Bc*Nv*12];
    __shared__ float orig_s[Bc*3];

    int tid = threadIdx.x;
    for (int t = tid; t < 4096; t += 256)
        WqT2[t & 63][t >> 6] = Wq2[t];
    if (tid < Bc*Nv*12) projs[tid] = proj[tid];
    if (tid < Bc*3)     orig_s[tid] = origins[tid];
    __syncthreads();

    int p    = blockIdx.x * 8 + (tid >> 5);
    int lane = tid & 31;

    float2 v = *(const float2*)&vox[(size_t)p*64 + 2*lane];

    bool sel = cmask[p] > 1;              // warp-uniform
    if (!sel) {                            // output = input, nothing else matters
        *(float2*)&out[(size_t)p*64 + 2*lane] = v;
        return;
    }

    float2 q1  = *(const float2*)&g_Q[(size_t)p*128 + 2*lane];
    float2 q2v = *(const float2*)&g_Q[(size_t)p*128 + 64 + 2*lane];

    int4 cc = __ldg((const int4*)coords + p);
    int bi = cc.w;
    float X = (float)cc.x * 0.16f + orig_s[bi*3 + 0];
    float Y = (float)cc.y * 0.16f + orig_s[bi*3 + 1];
    float Z = (float)cc.z * 0.16f + orig_s[bi*3 + 2];

    float2 k2s[9];
    unsigned mbits = 0;
    float  m1 = -1e30f, se1 = 0.f;
    float2 y1 = make_float2(0.f, 0.f);

    #pragma unroll
    for (int n = 0; n < Nv; n++) {
        const float* Pm = &projs[(bi*Nv + n)*12];
        float c0 = Pm[0]*X + Pm[1]*Y + Pm[2]*Z  + Pm[3];
        float c1 = Pm[4]*X + Pm[5]*Y + Pm[6]*Z  + Pm[7];
        float c2 = Pm[8]*X + Pm[9]*Y + Pm[10]*Z + Pm[11];
        float txp = __fdiv_rn(c0, c2);
        float typ = __fdiv_rn(c1, c2);
        float gx = __fdiv_rn(2.0f * txp, (float)(Ww - 1)) - 1.0f;
        float gy = __fdiv_rn(2.0f * typ, (float)(Hh - 1)) - 1.0f;
        bool msk = (fabsf(gx) <= 1.0f) && (fabsf(gy) <= 1.0f) && (c2 > 0.0f);

        float2 k1 = make_float2(0.f, 0.f);
        float2 k2 = make_float2(0.f, 0.f);
        if (msk) {
            float px = (gx + 1.0f) * 0.5f * (float)(Ww - 1);
            float py = (gy + 1.0f) * 0.5f * (float)(Hh - 1);
            float x0f = floorf(px), y0f = floorf(py);
            float fx = px - x0f,    fy = py - y0f;
            int x0 = (int)x0f, y0 = (int)y0f;
            float w00 = (1.f-fx)*(1.f-fy), w01 = fx*(1.f-fy);
            float w10 = (1.f-fx)*fy,       w11 = fx*fy;
            const float* base = g_KMI +
                ((size_t)(bi*Nv + n)*HW + (size_t)y0*Ww + x0)*128 + 4*lane;
            bool vx1 = (x0 + 1) < Ww;
            bool vy1 = (y0 + 1) < Hh;
            {
                float4 t = *(const float4*)base;
                k1.x += w00*t.x; k1.y += w00*t.y;
                k2.x += w00*t.z; k2.y += w00*t.w;
            }
            if (vx1) {
                float4 t = *(const float4*)(base + 128);
                k1.x += w01*t.x; k1.y += w01*t.y;
                k2.x += w01*t.z; k2.y += w01*t.w;
            }
            if (vy1) {
                float4 t = *(const float4*)(base + (size_t)Ww*128);
                k1.x += w10*t.x; k1.y += w10*t.y;
                k2.x += w10*t.z; k2.y += w10*t.w;
            }
            if (vx1 && vy1) {
                float4 t = *(const float4*)(base + (size_t)Ww*128 + 128);
                k1.x += w11*t.x; k1.y += w11*t.y;
                k2.x += w11*t.z; k2.y += w11*t.w;
            }
        }

        float part = q1.x*k1.x + q1.y*k1.y;
        #pragma unroll
        for (int off = 16; off; off >>= 1)
            part += __shfl_xor_sync(0xffffffffu, part, off);
        float lg = msk ? part * 0.125f : NEGV;

        float nm = fmaxf(m1, lg);
        float sc = __expf(m1 - nm);
        float e  = __expf(lg - nm);
        se1  = se1*sc + e;
        y1.x = y1.x*sc + e*k1.x;
        y1.y = y1.y*sc + e*k1.y;
        m1 = nm;

        k2s[n] = k2;
        mbits |= (msk ? 1u : 0u) << n;
    }

    float inv1 = __fdiv_rn(1.0f, se1);
    float2 yn = make_float2(y1.x*inv1, y1.y*inv1);
    float2 f1 = make_float2(v.x + yn.x, v.y + yn.y);

    // delta = Wq2 @ yn  (4-way split accumulators)
    float2 d0 = make_float2(0.f,0.f), d1 = d0, d2 = d0, d3 = d0;
    #pragma unroll
    for (int s = 0; s < 16; s++) {
        float aX = __shfl_sync(0xffffffffu, yn.x, s);
        float aY = __shfl_sync(0xffffffffu, yn.y, s);
        float bX = __shfl_sync(0xffffffffu, yn.x, s + 16);
        float bY = __shfl_sync(0xffffffffu, yn.y, s + 16);
        float2 wa0 = *(const float2*)&WqT2[2*s][2*lane];
        float2 wa1 = *(const float2*)&WqT2[2*s+1][2*lane];
        float2 wb0 = *(const float2*)&WqT2[2*s+32][2*lane];
        float2 wb1 = *(const float2*)&WqT2[2*s+33][2*lane];
        d0.x += wa0.x*aX; d0.y += wa0.y*aX;
        d1.x += wa1.x*aY; d1.y += wa1.y*aY;
        d2.x += wb0.x*bX; d2.y += wb0.y*bX;
        d3.x += wb1.x*bY; d3.y += wb1.y*bY;
    }
    float2 q2;
    q2.x = q2v.x + (d0.x + d1.x) + (d2.x + d3.x);
    q2.y = q2v.y + (d0.y + d1.y) + (d2.y + d3.y);

    // block 2 (keys in registers)
    float  m2 = -1e30f, se2 = 0.f;
    float2 y2 = make_float2(0.f, 0.f);
    #pragma unroll
    for (int n = 0; n < Nv; n++) {
        float2 k2 = k2s[n];
        float part = q2.x*k2.x + q2.y*k2.y;
        #pragma unroll
        for (int off = 16; off; off >>= 1)
            part += __shfl_xor_sync(0xffffffffu, part, off);
        float lg = ((mbits >> n) & 1u) ? part * 0.125f : NEGV;
        float nm = fmaxf(m2, lg);
        float sc = __expf(m2 - nm);
        float e  = __expf(lg - nm);
        se2  = se2*sc + e;
        y2.x = y2.x*sc + e*k2.x;
        y2.y = y2.y*sc + e*k2.y;
        m2 = nm;
    }
    float inv2 = __fdiv_rn(1.0f, se2);
    float2 o;
    o.x = f1.x + y2.x*inv2;
    o.y = f1.y + y2.y*inv2;
    *(float2*)&out[(size_t)p*64 + 2*lane] = o;
}

// ---------------------------------------------------------------------------
extern "C" void kernel_launch(void* const* d_in, const int* in_sizes, int n_in,
                              void* d_out, int out_size)
{
    (void)in_sizes; (void)n_in; (void)out_size;
    const float* img    = (const float*)d_in[0];
    const int*   coords = (const int*)  d_in[1];
    const float* vox    = (const float*)d_in[2];
    const float* proj   = (const float*)d_in[3];
    const float* orig   = (const float*)d_in[4];
    const int*   cmask  = (const int*)  d_in[5];
    const float* Wq1 = (const float*)d_in[6];
    const float* bq1 = (const float*)d_in[7];
    const float* Wk1 = (const float*)d_in[8];
    const float* bk1 = (const float*)d_in[9];
    const float* Wq2 = (const float*)d_in[10];
    const float* bq2 = (const float*)d_in[11];
    const float* Wk2 = (const float*)d_in[12];
    const float* bk2 = (const float*)d_in[13];
    float* out = (float*)d_out;

    keymap_kernel<<<MTOT/128, 256>>>(img, Wk1, bk1, Wk2, bk2);
    qgemm_kernel<<<Pp/128, 256>>>(vox, Wq1, bq1, Wq2, bq2);
    attn_fused_kernel<<<Pp/8, 256>>>(vox, coords, proj, orig, cmask, Wq2, out);
}

// round 5
// speedup vs baseline: 1.6591x; 1.0135x over previous
#include <cuda_runtime.h>

#define Bc 2
#define Nv 9
#define CBc 80
#define Hh 120
#define Ww 160
#define Dd 64
#define Pp 80000
#define HW (Hh*Ww)            // 19200
#define MTOT (Bc*Nv*HW)       // 345600
#define NEGV -10000.0f

// Interleaved key maps: [pix][pair j]{KM1[2j],KM1[2j+1],KM2[2j],KM2[2j+1]}
__device__ float g_KMI[(size_t)MTOT*128];
__device__ float g_Q[(size_t)Pp*128];      // [p][0:64]=q1, [p][64:128]=q2v

#define CP_ASYNC16(smem_addr, gptr) \
    asm volatile("cp.async.cg.shared.global [%0], [%1], 16;" \
                 :: "r"(smem_addr), "l"(gptr))

// ---------------------------------------------------------------------------
// Kernel 1: key_maps for BOTH blocks, interleaved output.
// 128px x 128d tile, 8x8 micro. cp.async double-buffered A (16-row chunks).
// Dynamic smem: Bsh 80*128 + Ash 2*16*128 + bias 128 = 14464 fl = 57856 B.
// ---------------------------------------------------------------------------
__global__ __launch_bounds__(256) void keymap_kernel(
    const float* __restrict__ img,
    const float* __restrict__ Wk1, const float* __restrict__ bk1,
    const float* __restrict__ Wk2, const float* __restrict__ bk2)
{
    extern __shared__ __align__(16) float dyn[];
    float* Bsh     = dyn;                       // [80][128]
    float* Ash     = dyn + CBc*128;             // [2][16][128]
    float* bias_sh = Ash + 2*16*128;            // [128]

    int tid = threadIdx.x;
    int m0   = blockIdx.x * 128;                // HW % 128 == 0
    int bn   = m0 / HW;
    int pix0 = m0 - bn*HW;
    const float* Abase = img + (size_t)bn*CBc*HW + pix0;

    // issue chunk 0 (overlaps the Bsh loads below)
    #pragma unroll
    for (int r = 0; r < 2; r++) {
        int idx = tid + r*256;                  // 512 float4 slots
        int k = idx >> 5, p4 = idx & 31;
        unsigned s = (unsigned)__cvta_generic_to_shared(&Ash[k*128 + p4*4]);
        CP_ASYNC16(s, Abase + (size_t)k*HW + p4*4);
    }
    asm volatile("cp.async.commit_group;");

    for (int t = tid; t < CBc*128; t += 256) {
        int c = t >> 7, d = t & 127;
        Bsh[t] = (d < 64) ? Wk1[d*CBc + c] : Wk2[(d-64)*CBc + c];
    }
    if (tid < 128) bias_sh[tid] = (tid < 64) ? bk1[tid] : bk2[tid-64];

    int tx = tid & 15, ty = tid >> 4;

    float acc[8][8];
    #pragma unroll
    for (int i = 0; i < 8; i++)
        #pragma unroll
        for (int j = 0; j < 8; j++) acc[i][j] = 0.f;

    #pragma unroll
    for (int kc = 0; kc < 5; kc++) {            // K = 80 = 5 x 16
        if (kc < 4) {
            #pragma unroll
            for (int r = 0; r < 2; r++) {
                int idx = tid + r*256;
                int k = idx >> 5, p4 = idx & 31;
                unsigned s = (unsigned)__cvta_generic_to_shared(
                    &Ash[(((kc+1)&1)*16 + k)*128 + p4*4]);
                CP_ASYNC16(s, Abase + (size_t)((kc+1)*16 + k)*HW + p4*4);
            }
            asm volatile("cp.async.commit_group;");
            asm volatile("cp.async.wait_group 1;");
        } else {
            asm volatile("cp.async.wait_group 0;");
        }
        __syncthreads();
        const float* A = &Ash[(kc&1)*16*128];
        #pragma unroll
        for (int k = 0; k < 16; k++) {
            float4 a0 = *(const float4*)&A[k*128 + ty*4];
            float4 a1 = *(const float4*)&A[k*128 + 64 + ty*4];
            float4 b0 = *(const float4*)&Bsh[(kc*16 + k)*128 + tx*4];
            float4 b1 = *(const float4*)&Bsh[(kc*16 + k)*128 + 64 + tx*4];
            float av[8] = {a0.x,a0.y,a0.z,a0.w, a1.x,a1.y,a1.z,a1.w};
            float bv[8] = {b0.x,b0.y,b0.z,b0.w, b1.x,b1.y,b1.z,b1.w};
            #pragma unroll
            for (int i = 0; i < 8; i++)
                #pragma unroll
                for (int j = 0; j < 8; j++)
                    acc[i][j] += av[i] * bv[j];
        }
        __syncthreads();
    }

    float bj1[4], bj2[4];
    #pragma unroll
    for (int j = 0; j < 4; j++) {
        bj1[j] = bias_sh[tx*4 + j];
        bj2[j] = bias_sh[64 + tx*4 + j];
    }
    #pragma unroll
    for (int i = 0; i < 8; i++) {
        int m = m0 + ((i < 4) ? (ty*4 + i) : (64 + ty*4 + (i - 4)));
        float4 oA = make_float4(acc[i][0]+bj1[0], acc[i][1]+bj1[1],
                                acc[i][4]+bj2[0], acc[i][5]+bj2[1]);
        float4 oB = make_float4(acc[i][2]+bj1[2], acc[i][3]+bj1[3],
                                acc[i][6]+bj2[2], acc[i][7]+bj2[3]);
        *(float4*)&g_KMI[(size_t)m*128 + (2*tx)*4]   = oA;
        *(float4*)&g_KMI[(size_t)m*128 + (2*tx+1)*4] = oB;
    }
}

// ---------------------------------------------------------------------------
// Kernel 2: q-GEMM.  g_Q[p][d] = (d<64 ? Wq1@v+bq1 : Wq2@v+bq2)[d%64]
// ---------------------------------------------------------------------------
__global__ __launch_bounds__(256) void qgemm_kernel(
    const float* __restrict__ vox,
    const float* __restrict__ Wq1, const float* __restrict__ bq1,
    const float* __restrict__ Wq2, const float* __restrict__ bq2)
{
    __shared__ __align__(16) float BshT[64][132];
    __shared__ __align__(16) float Ash[8][132];
    __shared__ float bias_sh[128];

    int tid = threadIdx.x;
    {
        int d  = tid >> 1;
        const float* src = (d < 64) ? &Wq1[d*64] : &Wq2[(d-64)*64];
        #pragma unroll
        for (int i = 0; i < 8; i++) {
            int k = (tid & 1)*4 + 8*i;
            float4 w = *(const float4*)&src[k];
            BshT[k+0][d] = w.x; BshT[k+1][d] = w.y;
            BshT[k+2][d] = w.z; BshT[k+3][d] = w.w;
        }
    }
    if (tid < 128) bias_sh[tid] = (tid < 64) ? bq1[tid] : bq2[tid-64];

    int p0 = blockIdx.x * 128;
    int tx = tid & 15, ty = tid >> 4;

    float acc[8][8];
    #pragma unroll
    for (int i = 0; i < 8; i++)
        #pragma unroll
        for (int j = 0; j < 8; j++) acc[i][j] = 0.f;

    #pragma unroll
    for (int kc = 0; kc < 8; kc++) {
        __syncthreads();
        {
            int px = tid >> 1;
            int k0 = (tid & 1)*4;
            float4 a = *(const float4*)&vox[(size_t)(p0+px)*64 + kc*8 + k0];
            Ash[k0+0][px] = a.x; Ash[k0+1][px] = a.y;
            Ash[k0+2][px] = a.z; Ash[k0+3][px] = a.w;
        }
        __syncthreads();
        #pragma unroll
        for (int k = 0; k < 8; k++) {
            float4 a0 = *(const float4*)&Ash[k][ty*4];
            float4 a1 = *(const float4*)&Ash[k][64 + ty*4];
            float4 b0 = *(const float4*)&BshT[kc*8 + k][tx*4];
            float4 b1 = *(const float4*)&BshT[kc*8 + k][64 + tx*4];
            float av[8] = {a0.x,a0.y,a0.z,a0.w, a1.x,a1.y,a1.z,a1.w};
            float bv[8] = {b0.x,b0.y,b0.z,b0.w, b1.x,b1.y,b1.z,b1.w};
            #pragma unroll
            for (int i = 0; i < 8; i++)
                #pragma unroll
                for (int j = 0; j < 8; j++)
                    acc[i][j] += av[i] * bv[j];
        }
    }

    float bj1[4], bj2[4];
    #pragma unroll
    for (int j = 0; j < 4; j++) {
        bj1[j] = bias_sh[tx*4 + j];
        bj2[j] = bias_sh[64 + tx*4 + j];
    }
    #pragma unroll
    for (int i = 0; i < 8; i++) {
        int p = p0 + ((i < 4) ? (ty*4 + i) : (64 + ty*4 + (i - 4)));
        float4 o1 = make_float4(acc[i][0]+bj1[0], acc[i][1]+bj1[1],
                                acc[i][2]+bj1[2], acc[i][3]+bj1[3]);
        float4 o2 = make_float4(acc[i][4]+bj2[0], acc[i][5]+bj2[1],
                                acc[i][6]+bj2[2], acc[i][7]+bj2[3]);
        *(float4*)&g_Q[(size_t)p*128 + tx*4]      = o1;
        *(float4*)&g_Q[(size_t)p*128 + 64 + tx*4] = o2;
    }
}

// ---------------------------------------------------------------------------
// Kernel 3: fused attention. One warp/point, sel early-exit, BRANCH-FREE
// clamped gathers (36 independent LDG.128 per point for max MLP).
// ---------------------------------------------------------------------------
__global__ __launch_bounds__(256) void attn_fused_kernel(
    const float* __restrict__ vox,
    const int*   __restrict__ coords,
    const float* __restrict__ proj,
    const float* __restrict__ origins,
    const int*   __restrict__ cmask,
    const float* __restrict__ Wq2,
    float* __restrict__ out)
{
    __shared__ float WqT2[64][64];        // WqT2[i][d] = Wq2[d][i]
    __shared__ float projs[Bc*Nv*12];
    __shared__ float orig_s[Bc*3];

    int tid = threadIdx.x;
    for (int t = tid; t < 4096; t += 256)
        WqT2[t & 63][t >> 6] = Wq2[t];
    if (tid < Bc*Nv*12) projs[tid] = proj[tid];
    if (tid < Bc*3)     orig_s[tid] = origins[tid];
    __syncthreads();

    int p    = blockIdx.x * 8 + (tid >> 5);
    int lane = tid & 31;

    float2 v = *(const float2*)&vox[(size_t)p*64 + 2*lane];

    bool sel = cmask[p] > 1;              // warp-uniform
    if (!sel) {
        *(float2*)&out[(size_t)p*64 + 2*lane] = v;
        return;
    }

    float2 q1  = *(const float2*)&g_Q[(size_t)p*128 + 2*lane];
    float2 q2v = *(const float2*)&g_Q[(size_t)p*128 + 64 + 2*lane];

    int4 cc = __ldg((const int4*)coords + p);
    int bi = cc.w;
    float X = (float)cc.x * 0.16f + orig_s[bi*3 + 0];
    float Y = (float)cc.y * 0.16f + orig_s[bi*3 + 1];
    float Z = (float)cc.z * 0.16f + orig_s[bi*3 + 2];

    float2 k2s[9];
    unsigned mbits = 0;
    float  m1 = -1e30f, se1 = 0.f;
    float2 y1 = make_float2(0.f, 0.f);

    #pragma unroll
    for (int n = 0; n < Nv; n++) {
        const float* Pm = &projs[(bi*Nv + n)*12];
        float c0 = Pm[0]*X + Pm[1]*Y + Pm[2]*Z  + Pm[3];
        float c1 = Pm[4]*X + Pm[5]*Y + Pm[6]*Z  + Pm[7];
        float c2 = Pm[8]*X + Pm[9]*Y + Pm[10]*Z + Pm[11];
        float txp = __fdiv_rn(c0, c2);
        float typ = __fdiv_rn(c1, c2);
        float gx = __fdiv_rn(2.0f * txp, (float)(Ww - 1)) - 1.0f;
        float gy = __fdiv_rn(2.0f * typ, (float)(Hh - 1)) - 1.0f;
        bool msk = (fabsf(gx) <= 1.0f) && (fabsf(gy) <= 1.0f) && (c2 > 0.0f);
        float gxm = msk ? gx : 0.0f;
        float gym = msk ? gy : 0.0f;

        float px = (gxm + 1.0f) * 0.5f * (float)(Ww - 1);
        float py = (gym + 1.0f) * 0.5f * (float)(Hh - 1);
        float x0f = floorf(px), y0f = floorf(py);
        float fx = px - x0f,    fy = py - y0f;
        int x0 = (int)x0f, y0 = (int)y0f;       // in [0, W-1]/[0, H-1]
        bool vx1 = (x0 + 1) < Ww;
        bool vy1 = (y0 + 1) < Hh;
        int x1 = vx1 ? x0 + 1 : x0;
        int y1r = vy1 ? y0 + 1 : y0;
        float mskf = msk ? 1.f : 0.f;
        float w00 = (1.f-fx)*(1.f-fy) * mskf;
        float w01 = (vx1 ? fx*(1.f-fy) : 0.f) * mskf;
        float w10 = (vy1 ? (1.f-fx)*fy : 0.f) * mskf;
        float w11 = ((vx1 && vy1) ? fx*fy : 0.f) * mskf;

        const float* rb = g_KMI + ((size_t)(bi*Nv + n)*HW)*128 + 4*lane;
        // 4 unconditional, in-bounds gathers
        float4 t00 = *(const float4*)(rb + ((size_t)y0 *Ww + x0)*128);
        float4 t01 = *(const float4*)(rb + ((size_t)y0 *Ww + x1)*128);
        float4 t10 = *(const float4*)(rb + ((size_t)y1r*Ww + x0)*128);
        float4 t11 = *(const float4*)(rb + ((size_t)y1r*Ww + x1)*128);

        float2 k1, k2;
        k1.x = w00*t00.x + w01*t01.x + w10*t10.x + w11*t11.x;
        k1.y = w00*t00.y + w01*t01.y + w10*t10.y + w11*t11.y;
        k2.x = w00*t00.z + w01*t01.z + w10*t10.z + w11*t11.z;
        k2.y = w00*t00.w + w01*t01.w + w10*t10.w + w11*t11.w;

        float part = q1.x*k1.x + q1.y*k1.y;
        #pragma unroll
        for (int off = 16; off; off >>= 1)
            part += __shfl_xor_sync(0xffffffffu, part, off);
        float lg = msk ? part * 0.125f : NEGV;

        float nm = fmaxf(m1, lg);
        float sc = __expf(m1 - nm);
        float e  = __expf(lg - nm);
        se1  = se1*sc + e;
        y1.x = y1.x*sc + e*k1.x;
        y1.y = y1.y*sc + e*k1.y;
        m1 = nm;

        k2s[n] = k2;
        mbits |= (msk ? 1u : 0u) << n;
    }

    float inv1 = __fdiv_rn(1.0f, se1);
    float2 yn = make_float2(y1.x*inv1, y1.y*inv1);
    float2 f1 = make_float2(v.x + yn.x, v.y + yn.y);

    // delta = Wq2 @ yn  (4-way split accumulators)
    float2 d0 = make_float2(0.f,0.f), d1 = d0, d2 = d0, d3 = d0;
    #pragma unroll
    for (int s = 0; s < 16; s++) {
        float aX = __shfl_sync(0xffffffffu, yn.x, s);
        float aY = __shfl_sync(0xffffffffu, yn.y, s);
        float bX = __shfl_sync(0xffffffffu, yn.x, s + 16);
        float bY = __shfl_sync(0xffffffffu, yn.y, s + 16);
        float2 wa0 = *(const float2*)&WqT2[2*s][2*lane];
        float2 wa1 = *(const float2*)&WqT2[2*s+1][2*lane];
        float2 wb0 = *(const float2*)&WqT2[2*s+32][2*lane];
        float2 wb1 = *(const float2*)&WqT2[2*s+33][2*lane];
        d0.x += wa0.x*aX; d0.y += wa0.y*aX;
        d1.x += wa1.x*aY; d1.y += wa1.y*aY;
        d2.x += wb0.x*bX; d2.y += wb0.y*bX;
        d3.x += wb1.x*bY; d3.y += wb1.y*bY;
    }
    float2 q2;
    q2.x = q2v.x + (d0.x + d1.x) + (d2.x + d3.x);
    q2.y = q2v.y + (d0.y + d1.y) + (d2.y + d3.y);

    // block 2 (keys in registers)
    float  m2 = -1e30f, se2 = 0.f;
    float2 y2 = make_float2(0.f, 0.f);
    #pragma unroll
    for (int n = 0; n < Nv; n++) {
        float2 k2 = k2s[n];
        float part = q2.x*k2.x + q2.y*k2.y;
        #pragma unroll
        for (int off = 16; off; off >>= 1)
            part += __shfl_xor_sync(0xffffffffu, part, off);
        float lg = ((mbits >> n) & 1u) ? part * 0.125f : NEGV;
        float nm = fmaxf(m2, lg);
        float sc = __expf(m2 - nm);
        float e  = __expf(lg - nm);
        se2  = se2*sc + e;
        y2.x = y2.x*sc + e*k2.x;
        y2.y = y2.y*sc + e*k2.y;
        m2 = nm;
    }
    float inv2 = __fdiv_rn(1.0f, se2);
    float2 o;
    o.x = f1.x + y2.x*inv2;
    o.y = f1.y + y2.y*inv2;
    *(float2*)&out[(size_t)p*64 + 2*lane] = o;
}

// ---------------------------------------------------------------------------
extern "C" void kernel_launch(void* const* d_in, const int* in_sizes, int n_in,
                              void* d_out, int out_size)
{
    (void)in_sizes; (void)n_in; (void)out_size;
    const float* img    = (const float*)d_in[0];
    const int*   coords = (const int*)  d_in[1];
    const float* vox    = (const float*)d_in[2];
    const float* proj   = (const float*)d_in[3];
    const float* orig   = (const float*)d_in[4];
    const int*   cmask  = (const int*)  d_in[5];
    const float* Wq1 = (const float*)d_in[6];
    const float* bq1 = (const float*)d_in[7];
    const float* Wk1 = (const float*)d_in[8];
    const float* bk1 = (const float*)d_in[9];
    const float* Wq2 = (const float*)d_in[10];
    const float* bq2 = (const float*)d_in[11];
    const float* Wk2 = (const float*)d_in[12];
    const float* bk2 = (const float*)d_in[13];
    float* out = (float*)d_out;

    static int smem_set = 0;
    const int KM_SMEM = (CBc*128 + 2*16*128 + 128) * 4;   // 57856 B
    if (!smem_set) {
        cudaFuncSetAttribute(keymap_kernel,
                             cudaFuncAttributeMaxDynamicSharedMemorySize, KM_SMEM);
        smem_set = 1;
    }

    keymap_kernel<<<MTOT/128, 256, KM_SMEM>>>(img, Wk1, bk1, Wk2, bk2);
    qgemm_kernel<<<Pp/128, 256>>>(vox, Wq1, bq1, Wq2, bq2);
    attn_fused_kernel<<<Pp/8, 256>>>(vox, coords, proj, orig, cmask, Wq2, out);
}

// round 6
// speedup vs baseline: 1.8079x; 1.0897x over previous
#include <cuda_runtime.h>
#include <cstdint>

#define Bc 2
#define Nv 9
#define CBc 80
#define Hh 120
#define Ww 160
#define Dd 64
#define Pp 80000
#define HW (Hh*Ww)            // 19200
#define MTOT (Bc*Nv*HW)       // 345600
#define NEGV -10000.0f

#define KM_BLOCKS (MTOT/128)  // 2700
#define QG_BLOCKS (Pp/128)    // 625

// Interleaved key maps: [pix][pair j]{KM1[2j],KM1[2j+1],KM2[2j],KM2[2j+1]}
__device__ float g_KMI[(size_t)MTOT*128];
__device__ float g_Q[(size_t)Pp*128];      // [p][0:64]=q1, [p][64:128]=q2v

#define CP_ASYNC16(smem_addr, gptr) \
    asm volatile("cp.async.cg.shared.global [%0], [%1], 16;" \
                 :: "r"(smem_addr), "l"(gptr))

__device__ __forceinline__ uint32_t f2tf32(float f) {
    uint32_t r;
    asm("cvt.rna.tf32.f32 %0, %1;" : "=r"(r) : "f"(f));
    return r;
}

__device__ __forceinline__ void mma_tf32(float* c, const uint32_t* a,
                                         uint32_t b0, uint32_t b1) {
    asm volatile(
        "mma.sync.aligned.m16n8k8.row.col.f32.tf32.tf32.f32 "
        "{%0,%1,%2,%3},{%4,%5,%6,%7},{%8,%9},{%0,%1,%2,%3};"
        : "+f"(c[0]), "+f"(c[1]), "+f"(c[2]), "+f"(c[3])
        : "r"(a[0]), "r"(a[1]), "r"(a[2]), "r"(a[3]), "r"(b0), "r"(b1));
}

// ---------------------------------------------------------------------------
// Merged kernel 1: blocks [0, 2700) = key_maps (tf32 tensor, 3x split);
//                  blocks [2700, 3325) = q-GEMM (fp32 cores).
// Dyn smem 96256 B (keymap path): Bhi[80][136] Blo[80][136] Ash[2][8][136] bias[128]
// ---------------------------------------------------------------------------
__global__ __launch_bounds__(256) void keymap_qgemm_kernel(
    const float* __restrict__ img,
    const float* __restrict__ Wk1, const float* __restrict__ bk1,
    const float* __restrict__ Wk2, const float* __restrict__ bk2,
    const float* __restrict__ vox,
    const float* __restrict__ Wq1, const float* __restrict__ bq1,
    const float* __restrict__ Wq2, const float* __restrict__ bq2)
{
    extern __shared__ __align__(16) float dyn[];
    int tid = threadIdx.x;

    if (blockIdx.x < KM_BLOCKS) {
        // ================= keymap: tf32 MMA path =================
        float* Bhi     = dyn;                        // [80][136]
        float* Blo     = Bhi + 80*136;               // [80][136]
        float* Ash     = Blo + 80*136;               // [2][8][136]
        float* bias_sh = Ash + 2*8*136;              // [128]

        int m0   = blockIdx.x * 128;
        int bn   = m0 / HW;
        int pix0 = m0 - bn*HW;
        const float* Abase = img + (size_t)bn*CBc*HW + pix0;

        // prefetch A chunk 0
        {
            int kk = tid >> 5, p4 = tid & 31;
            unsigned s = (unsigned)__cvta_generic_to_shared(&Ash[kk*136 + p4*4]);
            CP_ASYNC16(s, Abase + (size_t)kk*HW + p4*4);
            asm volatile("cp.async.commit_group;");
        }

        // weights -> hi/lo tf32 in smem
        for (int t = tid; t < CBc*128; t += 256) {
            int k = t >> 7, d = t & 127;
            float w = (d < 64) ? Wk1[d*CBc + k] : Wk2[(d-64)*CBc + k];
            uint32_t hi = f2tf32(w);
            float lo = w - __uint_as_float(hi);
            Bhi[k*136 + d] = __uint_as_float(hi);
            Blo[k*136 + d] = __uint_as_float(f2tf32(lo));
        }
        if (tid < 128) bias_sh[tid] = (tid < 64) ? bk1[tid] : bk2[tid-64];

        int lane = tid & 31, warp = tid >> 5;
        int g = lane >> 2, tg = lane & 3;
        int wm = warp & 3, wn = warp >> 2;       // wm: 32-px rows, wn: 64-d cols

        float acc[2][8][4];
        #pragma unroll
        for (int mf = 0; mf < 2; mf++)
            #pragma unroll
            for (int nf = 0; nf < 8; nf++)
                #pragma unroll
                for (int i = 0; i < 4; i++) acc[mf][nf][i] = 0.f;

        #pragma unroll
        for (int kc = 0; kc < 10; kc++) {        // K = 80 = 10 x 8
            if (kc < 9) {
                int kk = tid >> 5, p4 = tid & 31;
                unsigned s = (unsigned)__cvta_generic_to_shared(
                    &Ash[(((kc+1)&1)*8 + kk)*136 + p4*4]);
                CP_ASYNC16(s, Abase + (size_t)((kc+1)*8 + kk)*HW + p4*4);
                asm volatile("cp.async.commit_group;");
                asm volatile("cp.async.wait_group 1;");
            } else {
                asm volatile("cp.async.wait_group 0;");
            }
            __syncthreads();

            const float* A = &Ash[(kc&1)*8*136];
            uint32_t ahi[2][4], alo[2][4];
            #pragma unroll
            for (int mf = 0; mf < 2; mf++) {
                int px0 = wm*32 + mf*16;
                float a[4];
                a[0] = A[tg*136     + px0 + g];
                a[1] = A[tg*136     + px0 + g + 8];
                a[2] = A[(tg+4)*136 + px0 + g];
                a[3] = A[(tg+4)*136 + px0 + g + 8];
                #pragma unroll
                for (int i = 0; i < 4; i++) {
                    ahi[mf][i] = f2tf32(a[i]);
                    alo[mf][i] = f2tf32(a[i] - __uint_as_float(ahi[mf][i]));
                }
            }
            #pragma unroll
            for (int nf = 0; nf < 8; nf++) {
                int d0 = wn*64 + nf*8 + g;
                uint32_t bh0 = __float_as_uint(Bhi[(kc*8+tg)*136   + d0]);
                uint32_t bh1 = __float_as_uint(Bhi[(kc*8+tg+4)*136 + d0]);
                uint32_t bl0 = __float_as_uint(Blo[(kc*8+tg)*136   + d0]);
                uint32_t bl1 = __float_as_uint(Blo[(kc*8+tg+4)*136 + d0]);
                #pragma unroll
                for (int mf = 0; mf < 2; mf++) {
                    mma_tf32(acc[mf][nf], ahi[mf], bh0, bh1);
                    mma_tf32(acc[mf][nf], ahi[mf], bl0, bl1);
                    mma_tf32(acc[mf][nf], alo[mf], bh0, bh1);
                }
            }
            __syncthreads();
        }

        // epilogue: bias + interleaved store
        #pragma unroll
        for (int nf = 0; nf < 8; nf++) {
            int dl   = wn*64 + nf*8 + 2*tg;       // 0..127
            float b0 = bias_sh[dl], b1 = bias_sh[dl+1];
            int rec  = (wn == 0) ? ((nf*4 + tg)*4) : ((nf*4 + tg)*4 + 2);
            #pragma unroll
            for (int mf = 0; mf < 2; mf++) {
                int px = m0 + wm*32 + mf*16 + g;
                float2 v0 = make_float2(acc[mf][nf][0]+b0, acc[mf][nf][1]+b1);
                float2 v1 = make_float2(acc[mf][nf][2]+b0, acc[mf][nf][3]+b1);
                *(float2*)&g_KMI[(size_t)px*128 + rec]       = v0;
                *(float2*)&g_KMI[(size_t)(px+8)*128 + rec]   = v1;
            }
        }
        return;
    }

    // ================= q-GEMM path (fp32 cores) =================
    {
        float* BshT    = dyn;                    // [64][132]
        float* Ash2    = BshT + 64*132;          // [8][132]
        float* bias_sh = Ash2 + 8*132;           // [128]

        {
            int d  = tid >> 1;
            const float* src = (d < 64) ? &Wq1[d*64] : &Wq2[(d-64)*64];
            #pragma unroll
            for (int i = 0; i < 8; i++) {
                int k = (tid & 1)*4 + 8*i;
                float4 w = *(const float4*)&src[k];
                BshT[(k+0)*132 + d] = w.x; BshT[(k+1)*132 + d] = w.y;
                BshT[(k+2)*132 + d] = w.z; BshT[(k+3)*132 + d] = w.w;
            }
        }
        if (tid < 128) bias_sh[tid] = (tid < 64) ? bq1[tid] : bq2[tid-64];

        int p0 = (blockIdx.x - KM_BLOCKS) * 128;
        int tx = tid & 15, ty = tid >> 4;

        float acc[8][8];
        #pragma unroll
        for (int i = 0; i < 8; i++)
            #pragma unroll
            for (int j = 0; j < 8; j++) acc[i][j] = 0.f;

        #pragma unroll
        for (int kc = 0; kc < 8; kc++) {
            __syncthreads();
            {
                int px = tid >> 1;
                int k0 = (tid & 1)*4;
                float4 a = *(const float4*)&vox[(size_t)(p0+px)*64 + kc*8 + k0];
                Ash2[(k0+0)*132 + px] = a.x; Ash2[(k0+1)*132 + px] = a.y;
                Ash2[(k0+2)*132 + px] = a.z; Ash2[(k0+3)*132 + px] = a.w;
            }
            __syncthreads();
            #pragma unroll
            for (int k = 0; k < 8; k++) {
                float4 a0 = *(const float4*)&Ash2[k*132 + ty*4];
                float4 a1 = *(const float4*)&Ash2[k*132 + 64 + ty*4];
                float4 b0 = *(const float4*)&BshT[(kc*8+k)*132 + tx*4];
                float4 b1 = *(const float4*)&BshT[(kc*8+k)*132 + 64 + tx*4];
                float av[8] = {a0.x,a0.y,a0.z,a0.w, a1.x,a1.y,a1.z,a1.w};
                float bv[8] = {b0.x,b0.y,b0.z,b0.w, b1.x,b1.y,b1.z,b1.w};
                #pragma unroll
                for (int i = 0; i < 8; i++)
                    #pragma unroll
                    for (int j = 0; j < 8; j++)
                        acc[i][j] += av[i] * bv[j];
            }
        }

        float bj1[4], bj2[4];
        #pragma unroll
        for (int j = 0; j < 4; j++) {
            bj1[j] = bias_sh[tx*4 + j];
            bj2[j] = bias_sh[64 + tx*4 + j];
        }
        #pragma unroll
        for (int i = 0; i < 8; i++) {
            int p = p0 + ((i < 4) ? (ty*4 + i) : (64 + ty*4 + (i - 4)));
            float4 o1 = make_float4(acc[i][0]+bj1[0], acc[i][1]+bj1[1],
                                    acc[i][2]+bj1[2], acc[i][3]+bj1[3]);
            float4 o2 = make_float4(acc[i][4]+bj2[0], acc[i][5]+bj2[1],
                                    acc[i][6]+bj2[2], acc[i][7]+bj2[3]);
            *(float4*)&g_Q[(size_t)p*128 + tx*4]      = o1;
            *(float4*)&g_Q[(size_t)p*128 + 64 + tx*4] = o2;
        }
    }
}

// ---------------------------------------------------------------------------
// Kernel 2: fused attention. One warp/point, sel early-exit, batched
// (latency-decoupled) gathers + reductions.
// ---------------------------------------------------------------------------
__global__ __launch_bounds__(256) void attn_fused_kernel(
    const float* __restrict__ vox,
    const int*   __restrict__ coords,
    const float* __restrict__ proj,
    const float* __restrict__ origins,
    const int*   __restrict__ cmask,
    const float* __restrict__ Wq2,
    float* __restrict__ out)
{
    __shared__ float WqT2[64][64];        // WqT2[i][d] = Wq2[d][i]
    __shared__ float projs[Bc*Nv*12];
    __shared__ float orig_s[Bc*3];

    int tid = threadIdx.x;
    for (int t = tid; t < 4096; t += 256)
        WqT2[t & 63][t >> 6] = Wq2[t];
    if (tid < Bc*Nv*12) projs[tid] = proj[tid];
    if (tid < Bc*3)     orig_s[tid] = origins[tid];
    __syncthreads();

    int p    = blockIdx.x * 8 + (tid >> 5);
    int lane = tid & 31;

    float2 v = *(const float2*)&vox[(size_t)p*64 + 2*lane];

    bool sel = cmask[p] > 1;              // warp-uniform
    if (!sel) {
        *(float2*)&out[(size_t)p*64 + 2*lane] = v;
        return;
    }

    float2 q1  = *(const float2*)&g_Q[(size_t)p*128 + 2*lane];
    float2 q2v = *(const float2*)&g_Q[(size_t)p*128 + 64 + 2*lane];

    int4 cc = __ldg((const int4*)coords + p);
    int bi = cc.w;
    float X = (float)cc.x * 0.16f + orig_s[bi*3 + 0];
    float Y = (float)cc.y * 0.16f + orig_s[bi*3 + 1];
    float Z = (float)cc.z * 0.16f + orig_s[bi*3 + 2];

    float2 k1s[9], k2s[9];
    unsigned mbits = 0;

    // Phase A: gather all views (independent across n -> deep MLP)
    #pragma unroll
    for (int n = 0; n < Nv; n++) {
        const float* Pm = &projs[(bi*Nv + n)*12];
        float c0 = Pm[0]*X + Pm[1]*Y + Pm[2]*Z  + Pm[3];
        float c1 = Pm[4]*X + Pm[5]*Y + Pm[6]*Z  + Pm[7];
        float c2 = Pm[8]*X + Pm[9]*Y + Pm[10]*Z + Pm[11];
        float txp = __fdiv_rn(c0, c2);
        float typ = __fdiv_rn(c1, c2);
        float gx = __fdiv_rn(2.0f * txp, (float)(Ww - 1)) - 1.0f;
        float gy = __fdiv_rn(2.0f * typ, (float)(Hh - 1)) - 1.0f;
        bool msk = (fabsf(gx) <= 1.0f) && (fabsf(gy) <= 1.0f) && (c2 > 0.0f);
        float gxm = msk ? gx : 0.0f;
        float gym = msk ? gy : 0.0f;

        float px = (gxm + 1.0f) * 0.5f * (float)(Ww - 1);
        float py = (gym + 1.0f) * 0.5f * (float)(Hh - 1);
        float x0f = floorf(px), y0f = floorf(py);
        float fx = px - x0f,    fy = py - y0f;
        int x0 = (int)x0f, y0 = (int)y0f;
        bool vx1 = (x0 + 1) < Ww;
        bool vy1 = (y0 + 1) < Hh;
        int x1 = vx1 ? x0 + 1 : x0;
        int y1r = vy1 ? y0 + 1 : y0;
        float mskf = msk ? 1.f : 0.f;
        float w00 = (1.f-fx)*(1.f-fy) * mskf;
        float w01 = (vx1 ? fx*(1.f-fy) : 0.f) * mskf;
        float w10 = (vy1 ? (1.f-fx)*fy : 0.f) * mskf;
        float w11 = ((vx1 && vy1) ? fx*fy : 0.f) * mskf;

        const float* rb = g_KMI + ((size_t)(bi*Nv + n)*HW)*128 + 4*lane;
        float4 t00 = *(const float4*)(rb + ((size_t)y0 *Ww + x0)*128);
        float4 t01 = *(const float4*)(rb + ((size_t)y0 *Ww + x1)*128);
        float4 t10 = *(const float4*)(rb + ((size_t)y1r*Ww + x0)*128);
        float4 t11 = *(const float4*)(rb + ((size_t)y1r*Ww + x1)*128);

        k1s[n].x = w00*t00.x + w01*t01.x + w10*t10.x + w11*t11.x;
        k1s[n].y = w00*t00.y + w01*t01.y + w10*t10.y + w11*t11.y;
        k2s[n].x = w00*t00.z + w01*t01.z + w10*t10.z + w11*t11.z;
        k2s[n].y = w00*t00.w + w01*t01.w + w10*t10.w + w11*t11.w;
        mbits |= (msk ? 1u : 0u) << n;
    }

    // Phase B: batched block-1 logit reductions
    float pt[9];
    #pragma unroll
    for (int n = 0; n < Nv; n++)
        pt[n] = q1.x*k1s[n].x + q1.y*k1s[n].y;
    #pragma unroll
    for (int off = 16; off; off >>= 1)
        #pragma unroll
        for (int n = 0; n < Nv; n++)
            pt[n] += __shfl_xor_sync(0xffffffffu, pt[n], off);

    // softmax 1 + y1
    float lgs[9];
    #pragma unroll
    for (int n = 0; n < Nv; n++)
        lgs[n] = ((mbits >> n) & 1u) ? pt[n]*0.125f : NEGV;
    float mx = lgs[0];
    #pragma unroll
    for (int n = 1; n < Nv; n++) mx = fmaxf(mx, lgs[n]);
    float se = 0.f;
    float2 y1 = make_float2(0.f, 0.f);
    #pragma unroll
    for (int n = 0; n < Nv; n++) {
        float e = __expf(lgs[n] - mx);
        se += e;
        y1.x += e*k1s[n].x;
        y1.y += e*k1s[n].y;
    }
    float inv1 = __fdiv_rn(1.0f, se);
    float2 yn = make_float2(y1.x*inv1, y1.y*inv1);
    float2 f1 = make_float2(v.x + yn.x, v.y + yn.y);

    // q2 = q2v + Wq2 @ yn  (4-way split accumulators)
    float2 d0 = make_float2(0.f,0.f), d1 = d0, d2 = d0, d3 = d0;
    #pragma unroll
    for (int s = 0; s < 16; s++) {
        float aX = __shfl_sync(0xffffffffu, yn.x, s);
        float aY = __shfl_sync(0xffffffffu, yn.y, s);
        float bX = __shfl_sync(0xffffffffu, yn.x, s + 16);
        float bY = __shfl_sync(0xffffffffu, yn.y, s + 16);
        float2 wa0 = *(const float2*)&WqT2[2*s][2*lane];
        float2 wa1 = *(const float2*)&WqT2[2*s+1][2*lane];
        float2 wb0 = *(const float2*)&WqT2[2*s+32][2*lane];
        float2 wb1 = *(const float2*)&WqT2[2*s+33][2*lane];
        d0.x += wa0.x*aX; d0.y += wa0.y*aX;
        d1.x += wa1.x*aY; d1.y += wa1.y*aY;
        d2.x += wb0.x*bX; d2.y += wb0.y*bX;
        d3.x += wb1.x*bY; d3.y += wb1.y*bY;
    }
    float2 q2;
    q2.x = q2v.x + (d0.x + d1.x) + (d2.x + d3.x);
    q2.y = q2v.y + (d0.y + d1.y) + (d2.y + d3.y);

    // Phase D: batched block-2 logits + softmax
    #pragma unroll
    for (int n = 0; n < Nv; n++)
        pt[n] = q2.x*k2s[n].x + q2.y*k2s[n].y;
    #pragma unroll
    for (int off = 16; off; off >>= 1)
        #pragma unroll
        for (int n = 0; n < Nv; n++)
            pt[n] += __shfl_xor_sync(0xffffffffu, pt[n], off);
    #pragma unroll
    for (int n = 0; n < Nv; n++)
        lgs[n] = ((mbits >> n) & 1u) ? pt[n]*0.125f : NEGV;
    float mx2 = lgs[0];
    #pragma unroll
    for (int n = 1; n < Nv; n++) mx2 = fmaxf(mx2, lgs[n]);
    float se2 = 0.f;
    float2 y2 = make_float2(0.f, 0.f);
    #pragma unroll
    for (int n = 0; n < Nv; n++) {
        float e = __expf(lgs[n] - mx2);
        se2 += e;
        y2.x += e*k2s[n].x;
        y2.y += e*k2s[n].y;
    }
    float inv2 = __fdiv_rn(1.0f, se2);
    float2 o;
    o.x = f1.x + y2.x*inv2;
    o.y = f1.y + y2.y*inv2;
    *(float2*)&out[(size_t)p*64 + 2*lane] = o;
}

// ---------------------------------------------------------------------------
extern "C" void kernel_launch(void* const* d_in, const int* in_sizes, int n_in,
                              void* d_out, int out_size)
{
    (void)in_sizes; (void)n_in; (void)out_size;
    const float* img    = (const float*)d_in[0];
    const int*   coords = (const int*)  d_in[1];
    const float* vox    = (const float*)d_in[2];
    const float* proj   = (const float*)d_in[3];
    const float* orig   = (const float*)d_in[4];
    const int*   cmask  = (const int*)  d_in[5];
    const float* Wq1 = (const float*)d_in[6];
    const float* bq1 = (const float*)d_in[7];
    const float* Wk1 = (const float*)d_in[8];
    const float* bk1 = (const float*)d_in[9];
    const float* Wq2 = (const float*)d_in[10];
    const float* bq2 = (const float*)d_in[11];
    const float* Wk2 = (const float*)d_in[12];
    const float* bk2 = (const float*)d_in[13];
    float* out = (float*)d_out;

    const int KQ_SMEM = (2*80*136 + 2*8*136 + 128) * 4;   // 96256 B
    static int smem_set = 0;
    if (!smem_set) {
        cudaFuncSetAttribute(keymap_qgemm_kernel,
                             cudaFuncAttributeMaxDynamicSharedMemorySize, KQ_SMEM);
        smem_set = 1;
    }

    keymap_qgemm_kernel<<<KM_BLOCKS + QG_BLOCKS, 256, KQ_SMEM>>>(
        img, Wk1, bk1, Wk2, bk2, vox, Wq1, bq1, Wq2, bq2);
    attn_fused_kernel<<<Pp/8, 256>>>(vox, coords, proj, orig, cmask, Wq2, out);
}

// round 7
// speedup vs baseline: 2.0516x; 1.1348x over previous
#include <cuda_runtime.h>
#include <cuda_fp16.h>
#include <cstdint>

#define Bc 2
#define Nv 9
#define CBc 80
#define Hh 120
#define Ww 160
#define Dd 64
#define Pp 80000
#define HW (Hh*Ww)            // 19200
#define MTOT (Bc*Nv*HW)       // 345600
#define NEGV -10000.0f

#define KM_BLOCKS (MTOT/128)  // 2700
#define QG_BLOCKS (Pp/128)    // 625

// Interleaved fp16 key maps: record = 64 half2 words per pixel.
// word 2j   = {KM1[2j], KM1[2j+1]},  word 2j+1 = {KM2[2j], KM2[2j+1]}
__device__ __half2 g_KMIh[(size_t)MTOT*64];
__device__ float   g_Q[(size_t)Pp*128];    // [p][0:64]=q1, [p][64:128]=q2v

#define CP_ASYNC16(smem_addr, gptr) \
    asm volatile("cp.async.cg.shared.global [%0], [%1], 16;" \
                 :: "r"(smem_addr), "l"(gptr))

__device__ __forceinline__ uint32_t f2tf32(float f) {
    uint32_t r;
    asm("cvt.rna.tf32.f32 %0, %1;" : "=r"(r) : "f"(f));
    return r;
}

__device__ __forceinline__ void mma_tf32(float* c, const uint32_t* a,
                                         uint32_t b0, uint32_t b1) {
    asm volatile(
        "mma.sync.aligned.m16n8k8.row.col.f32.tf32.tf32.f32 "
        "{%0,%1,%2,%3},{%4,%5,%6,%7},{%8,%9},{%0,%1,%2,%3};"
        : "+f"(c[0]), "+f"(c[1]), "+f"(c[2]), "+f"(c[3])
        : "r"(a[0]), "r"(a[1]), "r"(a[2]), "r"(a[3]), "r"(b0), "r"(b1));
}

// ---------------------------------------------------------------------------
// Merged kernel 1: blocks [0, 2700) = key_maps (tf32 tensor, 3x split, fp16 out);
//                  blocks [2700, 3325) = q-GEMM (fp32 cores).
// ---------------------------------------------------------------------------
__global__ __launch_bounds__(256) void keymap_qgemm_kernel(
    const float* __restrict__ img,
    const float* __restrict__ Wk1, const float* __restrict__ bk1,
    const float* __restrict__ Wk2, const float* __restrict__ bk2,
    const float* __restrict__ vox,
    const float* __restrict__ Wq1, const float* __restrict__ bq1,
    const float* __restrict__ Wq2, const float* __restrict__ bq2)
{
    extern __shared__ __align__(16) float dyn[];
    int tid = threadIdx.x;

    if (blockIdx.x < KM_BLOCKS) {
        // ================= keymap: tf32 MMA path =================
        float* Bhi     = dyn;                        // [80][136]
        float* Blo     = Bhi + 80*136;               // [80][136]
        float* Ash     = Blo + 80*136;               // [2][8][136]
        float* bias_sh = Ash + 2*8*136;              // [128]

        int m0   = blockIdx.x * 128;
        int bn   = m0 / HW;
        int pix0 = m0 - bn*HW;
        const float* Abase = img + (size_t)bn*CBc*HW + pix0;

        // prefetch A chunk 0
        {
            int kk = tid >> 5, p4 = tid & 31;
            unsigned s = (unsigned)__cvta_generic_to_shared(&Ash[kk*136 + p4*4]);
            CP_ASYNC16(s, Abase + (size_t)kk*HW + p4*4);
            asm volatile("cp.async.commit_group;");
        }

        // weights -> hi/lo tf32 in smem
        for (int t = tid; t < CBc*128; t += 256) {
            int k = t >> 7, d = t & 127;
            float w = (d < 64) ? Wk1[d*CBc + k] : Wk2[(d-64)*CBc + k];
            uint32_t hi = f2tf32(w);
            float lo = w - __uint_as_float(hi);
            Bhi[k*136 + d] = __uint_as_float(hi);
            Blo[k*136 + d] = __uint_as_float(f2tf32(lo));
        }
        if (tid < 128) bias_sh[tid] = (tid < 64) ? bk1[tid] : bk2[tid-64];

        int lane = tid & 31, warp = tid >> 5;
        int g = lane >> 2, tg = lane & 3;
        int wm = warp & 3, wn = warp >> 2;       // wm: 32-px rows, wn: 64-d cols

        float acc[2][8][4];
        #pragma unroll
        for (int mf = 0; mf < 2; mf++)
            #pragma unroll
            for (int nf = 0; nf < 8; nf++)
                #pragma unroll
                for (int i = 0; i < 4; i++) acc[mf][nf][i] = 0.f;

        #pragma unroll
        for (int kc = 0; kc < 10; kc++) {        // K = 80 = 10 x 8
            if (kc < 9) {
                int kk = tid >> 5, p4 = tid & 31;
                unsigned s = (unsigned)__cvta_generic_to_shared(
                    &Ash[(((kc+1)&1)*8 + kk)*136 + p4*4]);
                CP_ASYNC16(s, Abase + (size_t)((kc+1)*8 + kk)*HW + p4*4);
                asm volatile("cp.async.commit_group;");
                asm volatile("cp.async.wait_group 1;");
            } else {
                asm volatile("cp.async.wait_group 0;");
            }
            __syncthreads();

            const float* A = &Ash[(kc&1)*8*136];
            uint32_t ahi[2][4], alo[2][4];
            #pragma unroll
            for (int mf = 0; mf < 2; mf++) {
                int px0 = wm*32 + mf*16;
                float a[4];
                a[0] = A[tg*136     + px0 + g];
                a[1] = A[tg*136     + px0 + g + 8];
                a[2] = A[(tg+4)*136 + px0 + g];
                a[3] = A[(tg+4)*136 + px0 + g + 8];
                #pragma unroll
                for (int i = 0; i < 4; i++) {
                    ahi[mf][i] = f2tf32(a[i]);
                    alo[mf][i] = f2tf32(a[i] - __uint_as_float(ahi[mf][i]));
                }
            }
            #pragma unroll
            for (int nf = 0; nf < 8; nf++) {
                int d0 = wn*64 + nf*8 + g;
                uint32_t bh0 = __float_as_uint(Bhi[(kc*8+tg)*136   + d0]);
                uint32_t bh1 = __float_as_uint(Bhi[(kc*8+tg+4)*136 + d0]);
                uint32_t bl0 = __float_as_uint(Blo[(kc*8+tg)*136   + d0]);
                uint32_t bl1 = __float_as_uint(Blo[(kc*8+tg+4)*136 + d0]);
                #pragma unroll
                for (int mf = 0; mf < 2; mf++) {
                    mma_tf32(acc[mf][nf], ahi[mf], bh0, bh1);
                    mma_tf32(acc[mf][nf], ahi[mf], bl0, bl1);
                    mma_tf32(acc[mf][nf], alo[mf], bh0, bh1);
                }
            }
            __syncthreads();
        }

        // epilogue: bias + fp16 interleaved store
        #pragma unroll
        for (int nf = 0; nf < 8; nf++) {
            int dl   = wn*64 + nf*8 + 2*tg;       // 0..127 (logical d, this map)
            float b0 = bias_sh[dl], b1 = bias_sh[dl+1];
            int widx = (wn == 0) ? dl : (dl - 63);  // half2 word in 64-word record
            #pragma unroll
            for (int mf = 0; mf < 2; mf++) {
                int px = m0 + wm*32 + mf*16 + g;
                g_KMIh[(size_t)px*64 + widx] =
                    __floats2half2_rn(acc[mf][nf][0]+b0, acc[mf][nf][1]+b1);
                g_KMIh[(size_t)(px+8)*64 + widx] =
                    __floats2half2_rn(acc[mf][nf][2]+b0, acc[mf][nf][3]+b1);
            }
        }
        return;
    }

    // ================= q-GEMM path (fp32 cores) =================
    {
        float* BshT    = dyn;                    // [64][132]
        float* Ash2    = BshT + 64*132;          // [8][132]
        float* bias_sh = Ash2 + 8*132;           // [128]

        {
            int d  = tid >> 1;
            const float* src = (d < 64) ? &Wq1[d*64] : &Wq2[(d-64)*64];
            #pragma unroll
            for (int i = 0; i < 8; i++) {
                int k = (tid & 1)*4 + 8*i;
                float4 w = *(const float4*)&src[k];
                BshT[(k+0)*132 + d] = w.x; BshT[(k+1)*132 + d] = w.y;
                BshT[(k+2)*132 + d] = w.z; BshT[(k+3)*132 + d] = w.w;
            }
        }
        if (tid < 128) bias_sh[tid] = (tid < 64) ? bq1[tid] : bq2[tid-64];

        int p0 = (blockIdx.x - KM_BLOCKS) * 128;
        int tx = tid & 15, ty = tid >> 4;

        float acc[8][8];
        #pragma unroll
        for (int i = 0; i < 8; i++)
            #pragma unroll
            for (int j = 0; j < 8; j++) acc[i][j] = 0.f;

        #pragma unroll
        for (int kc = 0; kc < 8; kc++) {
            __syncthreads();
            {
                int px = tid >> 1;
                int k0 = (tid & 1)*4;
                float4 a = *(const float4*)&vox[(size_t)(p0+px)*64 + kc*8 + k0];
                Ash2[(k0+0)*132 + px] = a.x; Ash2[(k0+1)*132 + px] = a.y;
                Ash2[(k0+2)*132 + px] = a.z; Ash2[(k0+3)*132 + px] = a.w;
            }
            __syncthreads();
            #pragma unroll
            for (int k = 0; k < 8; k++) {
                float4 a0 = *(const float4*)&Ash2[k*132 + ty*4];
                float4 a1 = *(const float4*)&Ash2[k*132 + 64 + ty*4];
                float4 b0 = *(const float4*)&BshT[(kc*8+k)*132 + tx*4];
                float4 b1 = *(const float4*)&BshT[(kc*8+k)*132 + 64 + tx*4];
                float av[8] = {a0.x,a0.y,a0.z,a0.w, a1.x,a1.y,a1.z,a1.w};
                float bv[8] = {b0.x,b0.y,b0.z,b0.w, b1.x,b1.y,b1.z,b1.w};
                #pragma unroll
                for (int i = 0; i < 8; i++)
                    #pragma unroll
                    for (int j = 0; j < 8; j++)
                        acc[i][j] += av[i] * bv[j];
            }
        }

        float bj1[4], bj2[4];
        #pragma unroll
        for (int j = 0; j < 4; j++) {
            bj1[j] = bias_sh[tx*4 + j];
            bj2[j] = bias_sh[64 + tx*4 + j];
        }
        #pragma unroll
        for (int i = 0; i < 8; i++) {
            int p = p0 + ((i < 4) ? (ty*4 + i) : (64 + ty*4 + (i - 4)));
            float4 o1 = make_float4(acc[i][0]+bj1[0], acc[i][1]+bj1[1],
                                    acc[i][2]+bj1[2], acc[i][3]+bj1[3]);
            float4 o2 = make_float4(acc[i][4]+bj2[0], acc[i][5]+bj2[1],
                                    acc[i][6]+bj2[2], acc[i][7]+bj2[3]);
            *(float4*)&g_Q[(size_t)p*128 + tx*4]      = o1;
            *(float4*)&g_Q[(size_t)p*128 + 64 + tx*4] = o2;
        }
    }
}

// ---------------------------------------------------------------------------
// Kernel 2: fused attention. One warp/point, sel early-exit, fp16 gathers,
// batched reductions, 4 CTAs/SM via launch bounds.
// ---------------------------------------------------------------------------
__global__ __launch_bounds__(256, 4) void attn_fused_kernel(
    const float* __restrict__ vox,
    const int*   __restrict__ coords,
    const float* __restrict__ proj,
    const float* __restrict__ origins,
    const int*   __restrict__ cmask,
    const float* __restrict__ Wq2,
    float* __restrict__ out)
{
    __shared__ float WqT2[64][64];        // WqT2[i][d] = Wq2[d][i]
    __shared__ float projs[Bc*Nv*12];
    __shared__ float orig_s[Bc*3];

    int tid = threadIdx.x;
    for (int t = tid; t < 4096; t += 256)
        WqT2[t & 63][t >> 6] = Wq2[t];
    if (tid < Bc*Nv*12) projs[tid] = proj[tid];
    if (tid < Bc*3)     orig_s[tid] = origins[tid];
    __syncthreads();

    int p    = blockIdx.x * 8 + (tid >> 5);
    int lane = tid & 31;

    float2 v = *(const float2*)&vox[(size_t)p*64 + 2*lane];

    bool sel = cmask[p] > 1;              // warp-uniform
    if (!sel) {
        *(float2*)&out[(size_t)p*64 + 2*lane] = v;
        return;
    }

    float2 q1  = *(const float2*)&g_Q[(size_t)p*128 + 2*lane];
    float2 q2v = *(const float2*)&g_Q[(size_t)p*128 + 64 + 2*lane];

    int4 cc = __ldg((const int4*)coords + p);
    int bi = cc.w;
    float X = (float)cc.x * 0.16f + orig_s[bi*3 + 0];
    float Y = (float)cc.y * 0.16f + orig_s[bi*3 + 1];
    float Z = (float)cc.z * 0.16f + orig_s[bi*3 + 2];

    float2 k1s[9], k2s[9];
    unsigned mbits = 0;

    // Phase A: gather all views (independent across n -> deep MLP)
    #pragma unroll
    for (int n = 0; n < Nv; n++) {
        const float* Pm = &projs[(bi*Nv + n)*12];
        float c0 = Pm[0]*X + Pm[1]*Y + Pm[2]*Z  + Pm[3];
        float c1 = Pm[4]*X + Pm[5]*Y + Pm[6]*Z  + Pm[7];
        float c2 = Pm[8]*X + Pm[9]*Y + Pm[10]*Z + Pm[11];
        float txp = __fdiv_rn(c0, c2);
        float typ = __fdiv_rn(c1, c2);
        float gx = __fdiv_rn(2.0f * txp, (float)(Ww - 1)) - 1.0f;
        float gy = __fdiv_rn(2.0f * typ, (float)(Hh - 1)) - 1.0f;
        bool msk = (fabsf(gx) <= 1.0f) && (fabsf(gy) <= 1.0f) && (c2 > 0.0f);
        float gxm = msk ? gx : 0.0f;
        float gym = msk ? gy : 0.0f;

        float px = (gxm + 1.0f) * 0.5f * (float)(Ww - 1);
        float py = (gym + 1.0f) * 0.5f * (float)(Hh - 1);
        float x0f = floorf(px), y0f = floorf(py);
        float fx = px - x0f,    fy = py - y0f;
        int x0 = (int)x0f, y0 = (int)y0f;
        bool vx1 = (x0 + 1) < Ww;
        bool vy1 = (y0 + 1) < Hh;
        int x1 = vx1 ? x0 + 1 : x0;
        int y1r = vy1 ? y0 + 1 : y0;
        float mskf = msk ? 1.f : 0.f;
        float w00 = (1.f-fx)*(1.f-fy) * mskf;
        float w01 = (vx1 ? fx*(1.f-fy) : 0.f) * mskf;
        float w10 = (vy1 ? (1.f-fx)*fy : 0.f) * mskf;
        float w11 = ((vx1 && vy1) ? fx*fy : 0.f) * mskf;

        const __half2* rb = g_KMIh + ((size_t)(bi*Nv + n)*HW)*64 + 2*lane;
        uint2 u00 = *(const uint2*)(rb + (size_t)(y0 *Ww + x0)*64);
        uint2 u01 = *(const uint2*)(rb + (size_t)(y0 *Ww + x1)*64);
        uint2 u10 = *(const uint2*)(rb + (size_t)(y1r*Ww + x0)*64);
        uint2 u11 = *(const uint2*)(rb + (size_t)(y1r*Ww + x1)*64);

        float2 a00 = __half22float2(*(__half2*)&u00.x);
        float2 b00 = __half22float2(*(__half2*)&u00.y);
        float2 a01 = __half22float2(*(__half2*)&u01.x);
        float2 b01 = __half22float2(*(__half2*)&u01.y);
        float2 a10 = __half22float2(*(__half2*)&u10.x);
        float2 b10 = __half22float2(*(__half2*)&u10.y);
        float2 a11 = __half22float2(*(__half2*)&u11.x);
        float2 b11 = __half22float2(*(__half2*)&u11.y);

        k1s[n].x = w00*a00.x + w01*a01.x + w10*a10.x + w11*a11.x;
        k1s[n].y = w00*a00.y + w01*a01.y + w10*a10.y + w11*a11.y;
        k2s[n].x = w00*b00.x + w01*b01.x + w10*b10.x + w11*b11.x;
        k2s[n].y = w00*b00.y + w01*b01.y + w10*b10.y + w11*b11.y;
        mbits |= (msk ? 1u : 0u) << n;
    }

    // Phase B: batched block-1 logit reductions
    float pt[9];
    #pragma unroll
    for (int n = 0; n < Nv; n++)
        pt[n] = q1.x*k1s[n].x + q1.y*k1s[n].y;
    #pragma unroll
    for (int off = 16; off; off >>= 1)
        #pragma unroll
        for (int n = 0; n < Nv; n++)
            pt[n] += __shfl_xor_sync(0xffffffffu, pt[n], off);

    float lgs[9];
    #pragma unroll
    for (int n = 0; n < Nv; n++)
        lgs[n] = ((mbits >> n) & 1u) ? pt[n]*0.125f : NEGV;
    float mx = lgs[0];
    #pragma unroll
    for (int n = 1; n < Nv; n++) mx = fmaxf(mx, lgs[n]);
    float se = 0.f;
    float2 y1 = make_float2(0.f, 0.f);
    #pragma unroll
    for (int n = 0; n < Nv; n++) {
        float e = __expf(lgs[n] - mx);
        se += e;
        y1.x += e*k1s[n].x;
        y1.y += e*k1s[n].y;
    }
    float inv1 = __fdiv_rn(1.0f, se);
    float2 yn = make_float2(y1.x*inv1, y1.y*inv1);
    float2 f1 = make_float2(v.x + yn.x, v.y + yn.y);

    // q2 = q2v + Wq2 @ yn  (4-way split accumulators)
    float2 d0 = make_float2(0.f,0.f), d1 = d0, d2 = d0, d3 = d0;
    #pragma unroll
    for (int s = 0; s < 16; s++) {
        float aX = __shfl_sync(0xffffffffu, yn.x, s);
        float aY = __shfl_sync(0xffffffffu, yn.y, s);
        float bX = __shfl_sync(0xffffffffu, yn.x, s + 16);
        float bY = __shfl_sync(0xffffffffu, yn.y, s + 16);
        float2 wa0 = *(const float2*)&WqT2[2*s][2*lane];
        float2 wa1 = *(const float2*)&WqT2[2*s+1][2*lane];
        float2 wb0 = *(const float2*)&WqT2[2*s+32][2*lane];
        float2 wb1 = *(const float2*)&WqT2[2*s+33][2*lane];
        d0.x += wa0.x*aX; d0.y += wa0.y*aX;
        d1.x += wa1.x*aY; d1.y += wa1.y*aY;
        d2.x += wb0.x*bX; d2.y += wb0.y*bX;
        d3.x += wb1.x*bY; d3.y += wb1.y*bY;
    }
    float2 q2;
    q2.x = q2v.x + (d0.x + d1.x) + (d2.x + d3.x);
    q2.y = q2v.y + (d0.y + d1.y) + (d2.y + d3.y);

    // Phase D: batched block-2 logits + softmax
    #pragma unroll
    for (int n = 0; n < Nv; n++)
        pt[n] = q2.x*k2s[n].x + q2.y*k2s[n].y;
    #pragma unroll
    for (int off = 16; off; off >>= 1)
        #pragma unroll
        for (int n = 0; n < Nv; n++)
            pt[n] += __shfl_xor_sync(0xffffffffu, pt[n], off);
    #pragma unroll
    for (int n = 0; n < Nv; n++)
        lgs[n] = ((mbits >> n) & 1u) ? pt[n]*0.125f : NEGV;
    float mx2 = lgs[0];
    #pragma unroll
    for (int n = 1; n < Nv; n++) mx2 = fmaxf(mx2, lgs[n]);
    float se2 = 0.f;
    float2 y2 = make_float2(0.f, 0.f);
    #pragma unroll
    for (int n = 0; n < Nv; n++) {
        float e = __expf(lgs[n] - mx2);
        se2 += e;
        y2.x += e*k2s[n].x;
        y2.y += e*k2s[n].y;
    }
    float inv2 = __fdiv_rn(1.0f, se2);
    float2 o;
    o.x = f1.x + y2.x*inv2;
    o.y = f1.y + y2.y*inv2;
    *(float2*)&out[(size_t)p*64 + 2*lane] = o;
}

// ---------------------------------------------------------------------------
extern "C" void kernel_launch(void* const* d_in, const int* in_sizes, int n_in,
                              void* d_out, int out_size)
{
    (void)in_sizes; (void)n_in; (void)out_size;
    const float* img    = (const float*)d_in[0];
    const int*   coords = (const int*)  d_in[1];
    const float* vox    = (const float*)d_in[2];
    const float* proj   = (const float*)d_in[3];
    const float* orig   = (const float*)d_in[4];
    const int*   cmask  = (const int*)  d_in[5];
    const float* Wq1 = (const float*)d_in[6];
    const float* bq1 = (const float*)d_in[7];
    const float* Wk1 = (const float*)d_in[8];
    const float* bk1 = (const float*)d_in[9];
    const float* Wq2 = (const float*)d_in[10];
    const float* bq2 = (const float*)d_in[11];
    const float* Wk2 = (const float*)d_in[12];
    const float* bk2 = (const float*)d_in[13];
    float* out = (float*)d_out;

    const int KQ_SMEM = (2*80*136 + 2*8*136 + 128) * 4;   // 96256 B
    static int smem_set = 0;
    if (!smem_set) {
        cudaFuncSetAttribute(keymap_qgemm_kernel,
                             cudaFuncAttributeMaxDynamicSharedMemorySize, KQ_SMEM);
        smem_set = 1;
    }

    keymap_qgemm_kernel<<<KM_BLOCKS + QG_BLOCKS, 256, KQ_SMEM>>>(
        img, Wk1, bk1, Wk2, bk2, vox, Wq1, bq1, Wq2, bq2);
    attn_fused_kernel<<<Pp/8, 256>>>(vox, coords, proj, orig, cmask, Wq2, out);
}

// round 9
// speedup vs baseline: 2.5036x; 1.2203x over previous
#include <cuda_runtime.h>
#include <cuda_fp16.h>
#include <cstdint>

#define Bc 2
#define Nv 9
#define CBc 80
#define Hh 120
#define Ww 160
#define Dd 64
#define Pp 80000
#define HW (Hh*Ww)            // 19200
#define MTOT (Bc*Nv*HW)       // 345600
#define NEGV -10000.0f

#define KM_BLOCKS (MTOT/128)  // 2700
#define QG_BLOCKS (Pp/128)    // 625

// Interleaved fp16 key maps: record = 64 half2 words per pixel.
// word 2j   = {KM1[2j], KM1[2j+1]},  word 2j+1 = {KM2[2j], KM2[2j+1]}
__device__ __half2 g_KMIh[(size_t)MTOT*64];
__device__ float   g_Q[(size_t)Pp*128];    // [p][0:64]=q1, [p][64:128]=q2v
__device__ int     g_selcnt;
__device__ int     g_selidx[Pp];

#define CP_ASYNC16(smem_addr, gptr) \
    asm volatile("cp.async.cg.shared.global [%0], [%1], 16;" \
                 :: "r"(smem_addr), "l"(gptr))

__device__ __forceinline__ uint32_t f2tf32(float f) {
    uint32_t r;
    asm("cvt.rna.tf32.f32 %0, %1;" : "=r"(r) : "f"(f));
    return r;
}

__device__ __forceinline__ void mma_tf32(float* c, const uint32_t* a,
                                         uint32_t b0, uint32_t b1) {
    asm volatile(
        "mma.sync.aligned.m16n8k8.row.col.f32.tf32.tf32.f32 "
        "{%0,%1,%2,%3},{%4,%5,%6,%7},{%8,%9},{%0,%1,%2,%3};"
        : "+f"(c[0]), "+f"(c[1]), "+f"(c[2]), "+f"(c[3])
        : "r"(a[0]), "r"(a[1]), "r"(a[2]), "r"(a[3]), "r"(b0), "r"(b1));
}

// ---------------------------------------------------------------------------
// Merged kernel 1: blocks [0, 2700) = key_maps (tf32 tensor, 3x split, fp16 out);
//                  blocks [2700, 3325) = q-GEMM (fp32 cores).
// ---------------------------------------------------------------------------
__global__ __launch_bounds__(256) void keymap_qgemm_kernel(
    const float* __restrict__ img,
    const float* __restrict__ Wk1, const float* __restrict__ bk1,
    const float* __restrict__ Wk2, const float* __restrict__ bk2,
    const float* __restrict__ vox,
    const float* __restrict__ Wq1, const float* __restrict__ bq1,
    const float* __restrict__ Wq2, const float* __restrict__ bq2)
{
    extern __shared__ __align__(16) float dyn[];
    int tid = threadIdx.x;

    if (blockIdx.x < KM_BLOCKS) {
        // ================= keymap: tf32 MMA path =================
        float* Bhi     = dyn;                        // [80][136]
        float* Blo     = Bhi + 80*136;               // [80][136]
        float* Ash     = Blo + 80*136;               // [2][8][136]
        float* bias_sh = Ash + 2*8*136;              // [128]

        int m0   = blockIdx.x * 128;
        int bn   = m0 / HW;
        int pix0 = m0 - bn*HW;
        const float* Abase = img + (size_t)bn*CBc*HW + pix0;

        // prefetch A chunk 0
        {
            int kk = tid >> 5, p4 = tid & 31;
            unsigned s = (unsigned)__cvta_generic_to_shared(&Ash[kk*136 + p4*4]);
            CP_ASYNC16(s, Abase + (size_t)kk*HW + p4*4);
            asm volatile("cp.async.commit_group;");
        }

        // weights -> hi/lo tf32 in smem
        for (int t = tid; t < CBc*128; t += 256) {
            int k = t >> 7, d = t & 127;
            float w = (d < 64) ? Wk1[d*CBc + k] : Wk2[(d-64)*CBc + k];
            uint32_t hi = f2tf32(w);
            float lo = w - __uint_as_float(hi);
            Bhi[k*136 + d] = __uint_as_float(hi);
            Blo[k*136 + d] = __uint_as_float(f2tf32(lo));
        }
        if (tid < 128) bias_sh[tid] = (tid < 64) ? bk1[tid] : bk2[tid-64];

        int lane = tid & 31, warp = tid >> 5;
        int g = lane >> 2, tg = lane & 3;
        int wm = warp & 3, wn = warp >> 2;       // wm: 32-px rows, wn: 64-d cols

        float acc[2][8][4];
        #pragma unroll
        for (int mf = 0; mf < 2; mf++)
            #pragma unroll
            for (int nf = 0; nf < 8; nf++)
                #pragma unroll
                for (int i = 0; i < 4; i++) acc[mf][nf][i] = 0.f;

        #pragma unroll
        for (int kc = 0; kc < 10; kc++) {        // K = 80 = 10 x 8
            if (kc < 9) {
                int kk = tid >> 5, p4 = tid & 31;
                unsigned s = (unsigned)__cvta_generic_to_shared(
                    &Ash[(((kc+1)&1)*8 + kk)*136 + p4*4]);
                CP_ASYNC16(s, Abase + (size_t)((kc+1)*8 + kk)*HW + p4*4);
                asm volatile("cp.async.commit_group;");
                asm volatile("cp.async.wait_group 1;");
            } else {
                asm volatile("cp.async.wait_group 0;");
            }
            __syncthreads();

            const float* A = &Ash[(kc&1)*8*136];
            uint32_t ahi[2][4], alo[2][4];
            #pragma unroll
            for (int mf = 0; mf < 2; mf++) {
                int px0 = wm*32 + mf*16;
                float a[4];
                a[0] = A[tg*136     + px0 + g];
                a[1] = A[tg*136     + px0 + g + 8];
                a[2] = A[(tg+4)*136 + px0 + g];
                a[3] = A[(tg+4)*136 + px0 + g + 8];
                #pragma unroll
                for (int i = 0; i < 4; i++) {
                    ahi[mf][i] = f2tf32(a[i]);
                    alo[mf][i] = f2tf32(a[i] - __uint_as_float(ahi[mf][i]));
                }
            }
            #pragma unroll
            for (int nf = 0; nf < 8; nf++) {
                int d0 = wn*64 + nf*8 + g;
                uint32_t bh0 = __float_as_uint(Bhi[(kc*8+tg)*136   + d0]);
                uint32_t bh1 = __float_as_uint(Bhi[(kc*8+tg+4)*136 + d0]);
                uint32_t bl0 = __float_as_uint(Blo[(kc*8+tg)*136   + d0]);
                uint32_t bl1 = __float_as_uint(Blo[(kc*8+tg+4)*136 + d0]);
                #pragma unroll
                for (int mf = 0; mf < 2; mf++) {
                    mma_tf32(acc[mf][nf], ahi[mf], bh0, bh1);
                    mma_tf32(acc[mf][nf], ahi[mf], bl0, bl1);
                    mma_tf32(acc[mf][nf], alo[mf], bh0, bh1);
                }
            }
            __syncthreads();
        }

        // epilogue: bias + fp16 interleaved store
        #pragma unroll
        for (int nf = 0; nf < 8; nf++) {
            int dl   = wn*64 + nf*8 + 2*tg;
            float b0 = bias_sh[dl], b1 = bias_sh[dl+1];
            int widx = (wn == 0) ? dl : (dl - 63);  // half2 word in 64-word record
            #pragma unroll
            for (int mf = 0; mf < 2; mf++) {
                int px = m0 + wm*32 + mf*16 + g;
                g_KMIh[(size_t)px*64 + widx] =
                    __floats2half2_rn(acc[mf][nf][0]+b0, acc[mf][nf][1]+b1);
                g_KMIh[(size_t)(px+8)*64 + widx] =
                    __floats2half2_rn(acc[mf][nf][2]+b0, acc[mf][nf][3]+b1);
            }
        }
        return;
    }

    // ================= q-GEMM path (fp32 cores) =================
    {
        float* BshT    = dyn;                    // [64][132]
        float* Ash2    = BshT + 64*132;          // [8][132]
        float* bias_sh = Ash2 + 8*132;           // [128]

        {
            int d  = tid >> 1;
            const float* src = (d < 64) ? &Wq1[d*64] : &Wq2[(d-64)*64];
            #pragma unroll
            for (int i = 0; i < 8; i++) {
                int k = (tid & 1)*4 + 8*i;
                float4 w = *(const float4*)&src[k];
                BshT[(k+0)*132 + d] = w.x; BshT[(k+1)*132 + d] = w.y;
                BshT[(k+2)*132 + d] = w.z; BshT[(k+3)*132 + d] = w.w;
            }
        }
        if (tid < 128) bias_sh[tid] = (tid < 64) ? bq1[tid] : bq2[tid-64];

        int p0 = (blockIdx.x - KM_BLOCKS) * 128;
        int tx = tid & 15, ty = tid >> 4;

        float acc[8][8];
        #pragma unroll
        for (int i = 0; i < 8; i++)
            #pragma unroll
            for (int j = 0; j < 8; j++) acc[i][j] = 0.f;

        #pragma unroll
        for (int kc = 0; kc < 8; kc++) {
            __syncthreads();
            {
                int px = tid >> 1;
                int k0 = (tid & 1)*4;
                float4 a = *(const float4*)&vox[(size_t)(p0+px)*64 + kc*8 + k0];
                Ash2[(k0+0)*132 + px] = a.x; Ash2[(k0+1)*132 + px] = a.y;
                Ash2[(k0+2)*132 + px] = a.z; Ash2[(k0+3)*132 + px] = a.w;
            }
            __syncthreads();
            #pragma unroll
            for (int k = 0; k < 8; k++) {
                float4 a0 = *(const float4*)&Ash2[k*132 + ty*4];
                float4 a1 = *(const float4*)&Ash2[k*132 + 64 + ty*4];
                float4 b0 = *(const float4*)&BshT[(kc*8+k)*132 + tx*4];
                float4 b1 = *(const float4*)&BshT[(kc*8+k)*132 + 64 + tx*4];
                float av[8] = {a0.x,a0.y,a0.z,a0.w, a1.x,a1.y,a1.z,a1.w};
                float bv[8] = {b0.x,b0.y,b0.z,b0.w, b1.x,b1.y,b1.z,b1.w};
                #pragma unroll
                for (int i = 0; i < 8; i++)
                    #pragma unroll
                    for (int j = 0; j < 8; j++)
                        acc[i][j] += av[i] * bv[j];
            }
        }

        float bj1[4], bj2[4];
        #pragma unroll
        for (int j = 0; j < 4; j++) {
            bj1[j] = bias_sh[tx*4 + j];
            bj2[j] = bias_sh[64 + tx*4 + j];
        }
        #pragma unroll
        for (int i = 0; i < 8; i++) {
            int p = p0 + ((i < 4) ? (ty*4 + i) : (64 + ty*4 + (i - 4)));
            float4 o1 = make_float4(acc[i][0]+bj1[0], acc[i][1]+bj1[1],
                                    acc[i][2]+bj1[2], acc[i][3]+bj1[3]);
            float4 o2 = make_float4(acc[i][4]+bj2[0], acc[i][5]+bj2[1],
                                    acc[i][6]+bj2[2], acc[i][7]+bj2[3]);
            *(float4*)&g_Q[(size_t)p*128 + tx*4]      = o1;
            *(float4*)&g_Q[(size_t)p*128 + 64 + tx*4] = o2;
        }
    }
}

// ---------------------------------------------------------------------------
// Compaction: build dense sel-index list; emit out=v for non-sel points.
// Grid = ceil(Pp/256); fully guarded for the partial last block.
// ---------------------------------------------------------------------------
__global__ __launch_bounds__(256) void compact_kernel(
    const float* __restrict__ vox,
    const int*   __restrict__ cmask,
    float* __restrict__ out)
{
    int tid  = threadIdx.x;
    int p    = blockIdx.x * 256 + tid;
    int lane = tid & 31;

    bool sel = (p < Pp) && (cmask[p] > 1);
    unsigned mask = __ballot_sync(0xffffffffu, sel);

    int wbase = 0;
    if (lane == 0) wbase = atomicAdd(&g_selcnt, __popc(mask));
    wbase = __shfl_sync(0xffffffffu, wbase, 0);
    if (sel)
        g_selidx[wbase + __popc(mask & ((1u << lane) - 1u))] = p;

    // coalesced copy of non-sel rows (warp copies one row at a time)
    int rowbase = blockIdx.x * 256 + (tid >> 5) * 32;
    #pragma unroll 4
    for (int j = 0; j < 32; j++) {
        int pj = rowbase + j;
        if (pj < Pp && !((mask >> j) & 1u)) {
            float2 t = *(const float2*)&vox[(size_t)pj*64 + 2*lane];
            *(float2*)&out[(size_t)pj*64 + 2*lane] = t;
        }
    }
}

// ---------------------------------------------------------------------------
// Kernel 3: fused attention over the DENSE sel list. One warp per sel point.
// ---------------------------------------------------------------------------
__global__ __launch_bounds__(256, 4) void attn_fused_kernel(
    const float* __restrict__ vox,
    const int*   __restrict__ coords,
    const float* __restrict__ proj,
    const float* __restrict__ origins,
    const float* __restrict__ Wq2,
    float* __restrict__ out)
{
    __shared__ float WqT2[64][64];        // WqT2[i][d] = Wq2[d][i]
    __shared__ float projs[Bc*Nv*12];
    __shared__ float orig_s[Bc*3];

    int cnt = g_selcnt;
    if (blockIdx.x * 8 >= cnt) return;    // block-uniform early exit

    int tid = threadIdx.x;
    for (int t = tid; t < 4096; t += 256)
        WqT2[t & 63][t >> 6] = Wq2[t];
    if (tid < Bc*Nv*12) projs[tid] = proj[tid];
    if (tid < Bc*3)     orig_s[tid] = origins[tid];
    __syncthreads();

    int widx = blockIdx.x * 8 + (tid >> 5);
    if (widx >= cnt) return;              // warp-uniform (after sync)
    int p    = g_selidx[widx];
    int lane = tid & 31;

    float2 v = *(const float2*)&vox[(size_t)p*64 + 2*lane];
    float2 q1  = *(const float2*)&g_Q[(size_t)p*128 + 2*lane];
    float2 q2v = *(const float2*)&g_Q[(size_t)p*128 + 64 + 2*lane];

    int4 cc = __ldg((const int4*)coords + p);
    int bi = cc.w;
    float X = (float)cc.x * 0.16f + orig_s[bi*3 + 0];
    float Y = (float)cc.y * 0.16f + orig_s[bi*3 + 1];
    float Z = (float)cc.z * 0.16f + orig_s[bi*3 + 2];

    float2 k1s[9], k2s[9];
    unsigned mbits = 0;

    // Phase A: gather all views (independent across n -> deep MLP)
    #pragma unroll
    for (int n = 0; n < Nv; n++) {
        const float* Pm = &projs[(bi*Nv + n)*12];
        float c0 = Pm[0]*X + Pm[1]*Y + Pm[2]*Z  + Pm[3];
        float c1 = Pm[4]*X + Pm[5]*Y + Pm[6]*Z  + Pm[7];
        float c2 = Pm[8]*X + Pm[9]*Y + Pm[10]*Z + Pm[11];
        float txp = __fdiv_rn(c0, c2);
        float typ = __fdiv_rn(c1, c2);
        float gx = __fdiv_rn(2.0f * txp, (float)(Ww - 1)) - 1.0f;
        float gy = __fdiv_rn(2.0f * typ, (float)(Hh - 1)) - 1.0f;
        bool msk = (fabsf(gx) <= 1.0f) && (fabsf(gy) <= 1.0f) && (c2 > 0.0f);
        float gxm = msk ? gx : 0.0f;
        float gym = msk ? gy : 0.0f;

        float px = (gxm + 1.0f) * 0.5f * (float)(Ww - 1);
        float py = (gym + 1.0f) * 0.5f * (float)(Hh - 1);
        float x0f = floorf(px), y0f = floorf(py);
        float fx = px - x0f,    fy = py - y0f;
        int x0 = (int)x0f, y0 = (int)y0f;
        bool vx1 = (x0 + 1) < Ww;
        bool vy1 = (y0 + 1) < Hh;
        int x1 = vx1 ? x0 + 1 : x0;
        int y1r = vy1 ? y0 + 1 : y0;
        float mskf = msk ? 1.f : 0.f;
        float w00 = (1.f-fx)*(1.f-fy) * mskf;
        float w01 = (vx1 ? fx*(1.f-fy) : 0.f) * mskf;
        float w10 = (vy1 ? (1.f-fx)*fy : 0.f) * mskf;
        float w11 = ((vx1 && vy1) ? fx*fy : 0.f) * mskf;

        const __half2* rb = g_KMIh + ((size_t)(bi*Nv + n)*HW)*64 + 2*lane;
        uint2 u00 = *(const uint2*)(rb + (size_t)(y0 *Ww + x0)*64);
        uint2 u01 = *(const uint2*)(rb + (size_t)(y0 *Ww + x1)*64);
        uint2 u10 = *(const uint2*)(rb + (size_t)(y1r*Ww + x0)*64);
        uint2 u11 = *(const uint2*)(rb + (size_t)(y1r*Ww + x1)*64);

        float2 a00 = __half22float2(*(__half2*)&u00.x);
        float2 b00 = __half22float2(*(__half2*)&u00.y);
        float2 a01 = __half22float2(*(__half2*)&u01.x);
        float2 b01 = __half22float2(*(__half2*)&u01.y);
        float2 a10 = __half22float2(*(__half2*)&u10.x);
        float2 b10 = __half22float2(*(__half2*)&u10.y);
        float2 a11 = __half22float2(*(__half2*)&u11.x);
        float2 b11 = __half22float2(*(__half2*)&u11.y);

        k1s[n].x = w00*a00.x + w01*a01.x + w10*a10.x + w11*a11.x;
        k1s[n].y = w00*a00.y + w01*a01.y + w10*a10.y + w11*a11.y;
        k2s[n].x = w00*b00.x + w01*b01.x + w10*b10.x + w11*b11.x;
        k2s[n].y = w00*b00.y + w01*b01.y + w10*b10.y + w11*b11.y;
        mbits |= (msk ? 1u : 0u) << n;
    }

    // Phase B: batched block-1 logit reductions
    float pt[9];
    #pragma unroll
    for (int n = 0; n < Nv; n++)
        pt[n] = q1.x*k1s[n].x + q1.y*k1s[n].y;
    #pragma unroll
    for (int off = 16; off; off >>= 1)
        #pragma unroll
        for (int n = 0; n < Nv; n++)
            pt[n] += __shfl_xor_sync(0xffffffffu, pt[n], off);

    float lgs[9];
    #pragma unroll
    for (int n = 0; n < Nv; n++)
        lgs[n] = ((mbits >> n) & 1u) ? pt[n]*0.125f : NEGV;
    float mx = lgs[0];
    #pragma unroll
    for (int n = 1; n < Nv; n++) mx = fmaxf(mx, lgs[n]);
    float se = 0.f;
    float2 y1 = make_float2(0.f, 0.f);
    #pragma unroll
    for (int n = 0; n < Nv; n++) {
        float e = __expf(lgs[n] - mx);
        se += e;
        y1.x += e*k1s[n].x;
        y1.y += e*k1s[n].y;
    }
    float inv1 = __fdiv_rn(1.0f, se);
    float2 yn = make_float2(y1.x*inv1, y1.y*inv1);
    float2 f1 = make_float2(v.x + yn.x, v.y + yn.y);

    // q2 = q2v + Wq2 @ yn  (4-way split accumulators)
    float2 d0 = make_float2(0.f,0.f), d1 = d0, d2 = d0, d3 = d0;
    #pragma unroll
    for (int s = 0; s < 16; s++) {
        float aX = __shfl_sync(0xffffffffu, yn.x, s);
        float aY = __shfl_sync(0xffffffffu, yn.y, s);
        float bX = __shfl_sync(0xffffffffu, yn.x, s + 16);
        float bY = __shfl_sync(0xffffffffu, yn.y, s + 16);
        float2 wa0 = *(const float2*)&WqT2[2*s][2*lane];
        float2 wa1 = *(const float2*)&WqT2[2*s+1][2*lane];
        float2 wb0 = *(const float2*)&WqT2[2*s+32][2*lane];
        float2 wb1 = *(const float2*)&WqT2[2*s+33][2*lane];
        d0.x += wa0.x*aX; d0.y += wa0.y*aX;
        d1.x += wa1.x*aY; d1.y += wa1.y*aY;
        d2.x += wb0.x*bX; d2.y += wb0.y*bX;
        d3.x += wb1.x*bY; d3.y += wb1.y*bY;
    }
    float2 q2;
    q2.x = q2v.x + (d0.x + d1.x) + (d2.x + d3.x);
    q2.y = q2v.y + (d0.y + d1.y) + (d2.y + d3.y);

    // Phase D: batched block-2 logits + softmax
    #pragma unroll
    for (int n = 0; n < Nv; n++)
        pt[n] = q2.x*k2s[n].x + q2.y*k2s[n].y;
    #pragma unroll
    for (int off = 16; off; off >>= 1)
        #pragma unroll
        for (int n = 0; n < Nv; n++)
            pt[n] += __shfl_xor_sync(0xffffffffu, pt[n], off);
    #pragma unroll
    for (int n = 0; n < Nv; n++)
        lgs[n] = ((mbits >> n) & 1u) ? pt[n]*0.125f : NEGV;
    float mx2 = lgs[0];
    #pragma unroll
    for (int n = 1; n < Nv; n++) mx2 = fmaxf(mx2, lgs[n]);
    float se2 = 0.f;
    float2 y2 = make_float2(0.f, 0.f);
    #pragma unroll
    for (int n = 0; n < Nv; n++) {
        float e = __expf(lgs[n] - mx2);
        se2 += e;
        y2.x += e*k2s[n].x;
        y2.y += e*k2s[n].y;
    }
    float inv2 = __fdiv_rn(1.0f, se2);
    float2 o;
    o.x = f1.x + y2.x*inv2;
    o.y = f1.y + y2.y*inv2;
    *(float2*)&out[(size_t)p*64 + 2*lane] = o;
}

// ---------------------------------------------------------------------------
extern "C" void kernel_launch(void* const* d_in, const int* in_sizes, int n_in,
                              void* d_out, int out_size)
{
    (void)in_sizes; (void)n_in; (void)out_size;
    const float* img    = (const float*)d_in[0];
    const int*   coords = (const int*)  d_in[1];
    const float* vox    = (const float*)d_in[2];
    const float* proj   = (const float*)d_in[3];
    const float* orig   = (const float*)d_in[4];
    const int*   cmask  = (const int*)  d_in[5];
    const float* Wq1 = (const float*)d_in[6];
    const float* bq1 = (const float*)d_in[7];
    const float* Wk1 = (const float*)d_in[8];
    const float* bk1 = (const float*)d_in[9];
    const float* Wq2 = (const float*)d_in[10];
    const float* bq2 = (const float*)d_in[11];
    const float* Wk2 = (const float*)d_in[12];
    const float* bk2 = (const float*)d_in[13];
    float* out = (float*)d_out;

    const int KQ_SMEM = (2*80*136 + 2*8*136 + 128) * 4;   // 96256 B
    static int smem_set = 0;
    if (!smem_set) {
        cudaFuncSetAttribute(keymap_qgemm_kernel,
                             cudaFuncAttributeMaxDynamicSharedMemorySize, KQ_SMEM);
        smem_set = 1;
    }

    void* cntp = nullptr;
    cudaGetSymbolAddress(&cntp, g_selcnt);
    cudaMemsetAsync(cntp, 0, sizeof(int));

    keymap_qgemm_kernel<<<KM_BLOCKS + QG_BLOCKS, 256, KQ_SMEM>>>(
        img, Wk1, bk1, Wk2, bk2, vox, Wq1, bq1, Wq2, bq2);
    compact_kernel<<<(Pp + 255)/256, 256>>>(vox, cmask, out);
    attn_fused_kernel<<<Pp/8, 256>>>(vox, coords, proj, orig, Wq2, out);
}

// round 10
// speedup vs baseline: 2.7358x; 1.0928x over previous
#include <cuda_runtime.h>
#include <cuda_fp16.h>
#include <cstdint>

#define Bc 2
#define Nv 9
#define CBc 80
#define Hh 120
#define Ww 160
#define Dd 64
#define Pp 80000
#define HW (Hh*Ww)            // 19200
#define MTOT (Bc*Nv*HW)       // 345600
#define NEGV -10000.0f

#define KM_BLOCKS (MTOT/128)  // 2700
#define QG_BLOCKS (Pp/128)    // 625

// Interleaved fp16 key maps: record = 64 half2 words per pixel.
// word 2j   = {KM1[2j], KM1[2j+1]},  word 2j+1 = {KM2[2j], KM2[2j+1]}
__device__ __half2 g_KMIh[(size_t)MTOT*64];
__device__ float   g_Q[(size_t)Pp*128];    // [p][0:64]=q1, [p][64:128]=q2v
__device__ int     g_selcnt;
__device__ int     g_selidx[Pp];

#define CP_ASYNC16(smem_addr, gptr) \
    asm volatile("cp.async.cg.shared.global [%0], [%1], 16;" \
                 :: "r"(smem_addr), "l"(gptr))

__device__ __forceinline__ uint32_t f2tf32(float f) {
    uint32_t r;
    asm("cvt.rna.tf32.f32 %0, %1;" : "=r"(r) : "f"(f));
    return r;
}

__device__ __forceinline__ void mma_tf32(float* c, const uint32_t* a,
                                         uint32_t b0, uint32_t b1) {
    asm volatile(
        "mma.sync.aligned.m16n8k8.row.col.f32.tf32.tf32.f32 "
        "{%0,%1,%2,%3},{%4,%5,%6,%7},{%8,%9},{%0,%1,%2,%3};"
        : "+f"(c[0]), "+f"(c[1]), "+f"(c[2]), "+f"(c[3])
        : "r"(a[0]), "r"(a[1]), "r"(a[2]), "r"(a[3]), "r"(b0), "r"(b1));
}

// ---------------------------------------------------------------------------
// Merged kernel 1: blocks [0, 2700) = key_maps (single tf32 MMA, fp16 out);
//                  blocks [2700, 3325) = q-GEMM (fp32 cores).
// Dyn smem (keymap path): Bhi[80][136] + Ash[2][8][136] + bias[128] = 52736 B.
// ---------------------------------------------------------------------------
__global__ __launch_bounds__(256) void keymap_qgemm_kernel(
    const float* __restrict__ img,
    const float* __restrict__ Wk1, const float* __restrict__ bk1,
    const float* __restrict__ Wk2, const float* __restrict__ bk2,
    const float* __restrict__ vox,
    const float* __restrict__ Wq1, const float* __restrict__ bq1,
    const float* __restrict__ Wq2, const float* __restrict__ bq2)
{
    extern __shared__ __align__(16) float dyn[];
    int tid = threadIdx.x;

    if (blockIdx.x < KM_BLOCKS) {
        // ================= keymap: tf32 MMA path =================
        float* Bhi     = dyn;                        // [80][136] (tf32 bits)
        float* Ash     = Bhi + 80*136;               // [2][8][136]
        float* bias_sh = Ash + 2*8*136;              // [128]

        int m0   = blockIdx.x * 128;
        int bn   = m0 / HW;
        int pix0 = m0 - bn*HW;
        const float* Abase = img + (size_t)bn*CBc*HW + pix0;

        // prefetch A chunk 0
        {
            int kk = tid >> 5, p4 = tid & 31;
            unsigned s = (unsigned)__cvta_generic_to_shared(&Ash[kk*136 + p4*4]);
            CP_ASYNC16(s, Abase + (size_t)kk*HW + p4*4);
            asm volatile("cp.async.commit_group;");
        }

        // weights -> tf32(hi) in smem
        for (int t = tid; t < CBc*128; t += 256) {
            int k = t >> 7, d = t & 127;
            float w = (d < 64) ? Wk1[d*CBc + k] : Wk2[(d-64)*CBc + k];
            Bhi[k*136 + d] = __uint_as_float(f2tf32(w));
        }
        if (tid < 128) bias_sh[tid] = (tid < 64) ? bk1[tid] : bk2[tid-64];

        int lane = tid & 31, warp = tid >> 5;
        int g = lane >> 2, tg = lane & 3;
        int wm = warp & 3, wn = warp >> 2;       // wm: 32-px rows, wn: 64-d cols

        float acc[2][8][4];
        #pragma unroll
        for (int mf = 0; mf < 2; mf++)
            #pragma unroll
            for (int nf = 0; nf < 8; nf++)
                #pragma unroll
                for (int i = 0; i < 4; i++) acc[mf][nf][i] = 0.f;

        #pragma unroll
        for (int kc = 0; kc < 10; kc++) {        // K = 80 = 10 x 8
            if (kc < 9) {
                int kk = tid >> 5, p4 = tid & 31;
                unsigned s = (unsigned)__cvta_generic_to_shared(
                    &Ash[(((kc+1)&1)*8 + kk)*136 + p4*4]);
                CP_ASYNC16(s, Abase + (size_t)((kc+1)*8 + kk)*HW + p4*4);
                asm volatile("cp.async.commit_group;");
                asm volatile("cp.async.wait_group 1;");
            } else {
                asm volatile("cp.async.wait_group 0;");
            }
            __syncthreads();

            const float* A = &Ash[(kc&1)*8*136];
            uint32_t ahi[2][4];
            #pragma unroll
            for (int mf = 0; mf < 2; mf++) {
                int px0 = wm*32 + mf*16;
                ahi[mf][0] = f2tf32(A[tg*136     + px0 + g]);
                ahi[mf][1] = f2tf32(A[tg*136     + px0 + g + 8]);
                ahi[mf][2] = f2tf32(A[(tg+4)*136 + px0 + g]);
                ahi[mf][3] = f2tf32(A[(tg+4)*136 + px0 + g + 8]);
            }
            #pragma unroll
            for (int nf = 0; nf < 8; nf++) {
                int d0 = wn*64 + nf*8 + g;
                uint32_t bh0 = __float_as_uint(Bhi[(kc*8+tg)*136   + d0]);
                uint32_t bh1 = __float_as_uint(Bhi[(kc*8+tg+4)*136 + d0]);
                #pragma unroll
                for (int mf = 0; mf < 2; mf++)
                    mma_tf32(acc[mf][nf], ahi[mf], bh0, bh1);
            }
            __syncthreads();
        }

        // epilogue: bias + fp16 interleaved store
        #pragma unroll
        for (int nf = 0; nf < 8; nf++) {
            int dl   = wn*64 + nf*8 + 2*tg;
            float b0 = bias_sh[dl], b1 = bias_sh[dl+1];
            int widx = (wn == 0) ? dl : (dl - 63);  // half2 word in 64-word record
            #pragma unroll
            for (int mf = 0; mf < 2; mf++) {
                int px = m0 + wm*32 + mf*16 + g;
                g_KMIh[(size_t)px*64 + widx] =
                    __floats2half2_rn(acc[mf][nf][0]+b0, acc[mf][nf][1]+b1);
                g_KMIh[(size_t)(px+8)*64 + widx] =
                    __floats2half2_rn(acc[mf][nf][2]+b0, acc[mf][nf][3]+b1);
            }
        }
        return;
    }

    // ================= q-GEMM path (fp32 cores) =================
    {
        float* BshT    = dyn;                    // [64][132]
        float* Ash2    = BshT + 64*132;          // [8][132]
        float* bias_sh = Ash2 + 8*132;           // [128]

        {
            int d  = tid >> 1;
            const float* src = (d < 64) ? &Wq1[d*64] : &Wq2[(d-64)*64];
            #pragma unroll
            for (int i = 0; i < 8; i++) {
                int k = (tid & 1)*4 + 8*i;
                float4 w = *(const float4*)&src[k];
                BshT[(k+0)*132 + d] = w.x; BshT[(k+1)*132 + d] = w.y;
                BshT[(k+2)*132 + d] = w.z; BshT[(k+3)*132 + d] = w.w;
            }
        }
        if (tid < 128) bias_sh[tid] = (tid < 64) ? bq1[tid] : bq2[tid-64];

        int p0 = (blockIdx.x - KM_BLOCKS) * 128;
        int tx = tid & 15, ty = tid >> 4;

        float acc[8][8];
        #pragma unroll
        for (int i = 0; i < 8; i++)
            #pragma unroll
            for (int j = 0; j < 8; j++) acc[i][j] = 0.f;

        #pragma unroll
        for (int kc = 0; kc < 8; kc++) {
            __syncthreads();
            {
                int px = tid >> 1;
                int k0 = (tid & 1)*4;
                float4 a = *(const float4*)&vox[(size_t)(p0+px)*64 + kc*8 + k0];
                Ash2[(k0+0)*132 + px] = a.x; Ash2[(k0+1)*132 + px] = a.y;
                Ash2[(k0+2)*132 + px] = a.z; Ash2[(k0+3)*132 + px] = a.w;
            }
            __syncthreads();
            #pragma unroll
            for (int k = 0; k < 8; k++) {
                float4 a0 = *(const float4*)&Ash2[k*132 + ty*4];
                float4 a1 = *(const float4*)&Ash2[k*132 + 64 + ty*4];
                float4 b0 = *(const float4*)&BshT[(kc*8+k)*132 + tx*4];
                float4 b1 = *(const float4*)&BshT[(kc*8+k)*132 + 64 + tx*4];
                float av[8] = {a0.x,a0.y,a0.z,a0.w, a1.x,a1.y,a1.z,a1.w};
                float bv[8] = {b0.x,b0.y,b0.z,b0.w, b1.x,b1.y,b1.z,b1.w};
                #pragma unroll
                for (int i = 0; i < 8; i++)
                    #pragma unroll
                    for (int j = 0; j < 8; j++)
                        acc[i][j] += av[i] * bv[j];
            }
        }

        float bj1[4], bj2[4];
        #pragma unroll
        for (int j = 0; j < 4; j++) {
            bj1[j] = bias_sh[tx*4 + j];
            bj2[j] = bias_sh[64 + tx*4 + j];
        }
        #pragma unroll
        for (int i = 0; i < 8; i++) {
            int p = p0 + ((i < 4) ? (ty*4 + i) : (64 + ty*4 + (i - 4)));
            float4 o1 = make_float4(acc[i][0]+bj1[0], acc[i][1]+bj1[1],
                                    acc[i][2]+bj1[2], acc[i][3]+bj1[3]);
            float4 o2 = make_float4(acc[i][4]+bj2[0], acc[i][5]+bj2[1],
                                    acc[i][6]+bj2[2], acc[i][7]+bj2[3]);
            *(float4*)&g_Q[(size_t)p*128 + tx*4]      = o1;
            *(float4*)&g_Q[(size_t)p*128 + 64 + tx*4] = o2;
        }
    }
}

// ---------------------------------------------------------------------------
// Compaction: build dense sel-index list; emit out=v for non-sel points.
// Grid = ceil(Pp/256); fully guarded for the partial last block.
// ---------------------------------------------------------------------------
__global__ __launch_bounds__(256) void compact_kernel(
    const float* __restrict__ vox,
    const int*   __restrict__ cmask,
    float* __restrict__ out)
{
    int tid  = threadIdx.x;
    int p    = blockIdx.x * 256 + tid;
    int lane = tid & 31;

    bool sel = (p < Pp) && (cmask[p] > 1);
    unsigned mask = __ballot_sync(0xffffffffu, sel);

    int wbase = 0;
    if (lane == 0) wbase = atomicAdd(&g_selcnt, __popc(mask));
    wbase = __shfl_sync(0xffffffffu, wbase, 0);
    if (sel)
        g_selidx[wbase + __popc(mask & ((1u << lane) - 1u))] = p;

    // coalesced copy of non-sel rows (warp copies one row at a time)
    int rowbase = blockIdx.x * 256 + (tid >> 5) * 32;
    #pragma unroll 4
    for (int j = 0; j < 32; j++) {
        int pj = rowbase + j;
        if (pj < Pp && !((mask >> j) & 1u)) {
            float2 t = *(const float2*)&vox[(size_t)pj*64 + 2*lane];
            *(float2*)&out[(size_t)pj*64 + 2*lane] = t;
        }
    }
}

// ---------------------------------------------------------------------------
// Kernel 3: fused attention over the DENSE sel list. One warp per sel point.
// ---------------------------------------------------------------------------
__global__ __launch_bounds__(256, 4) void attn_fused_kernel(
    const float* __restrict__ vox,
    const int*   __restrict__ coords,
    const float* __restrict__ proj,
    const float* __restrict__ origins,
    const float* __restrict__ Wq2,
    float* __restrict__ out)
{
    __shared__ float WqT2[64][64];        // WqT2[i][d] = Wq2[d][i]
    __shared__ float projs[Bc*Nv*12];
    __shared__ float orig_s[Bc*3];

    int cnt = g_selcnt;
    if (blockIdx.x * 8 >= cnt) return;    // block-uniform early exit

    int tid = threadIdx.x;
    for (int t = tid; t < 4096; t += 256)
        WqT2[t & 63][t >> 6] = Wq2[t];
    if (tid < Bc*Nv*12) projs[tid] = proj[tid];
    if (tid < Bc*3)     orig_s[tid] = origins[tid];
    __syncthreads();

    int widx = blockIdx.x * 8 + (tid >> 5);
    if (widx >= cnt) return;              // warp-uniform (after sync)
    int p    = g_selidx[widx];
    int lane = tid & 31;

    float2 v = *(const float2*)&vox[(size_t)p*64 + 2*lane];
    float2 q1  = *(const float2*)&g_Q[(size_t)p*128 + 2*lane];
    float2 q2v = *(const float2*)&g_Q[(size_t)p*128 + 64 + 2*lane];

    int4 cc = __ldg((const int4*)coords + p);
    int bi = cc.w;
    float X = (float)cc.x * 0.16f + orig_s[bi*3 + 0];
    float Y = (float)cc.y * 0.16f + orig_s[bi*3 + 1];
    float Z = (float)cc.z * 0.16f + orig_s[bi*3 + 2];

    float2 k1s[9], k2s[9];
    unsigned mbits = 0;

    // Phase A: gather all views (independent across n -> deep MLP)
    #pragma unroll
    for (int n = 0; n < Nv; n++) {
        const float* Pm = &projs[(bi*Nv + n)*12];
        float c0 = Pm[0]*X + Pm[1]*Y + Pm[2]*Z  + Pm[3];
        float c1 = Pm[4]*X + Pm[5]*Y + Pm[6]*Z  + Pm[7];
        float c2 = Pm[8]*X + Pm[9]*Y + Pm[10]*Z + Pm[11];
        float txp = __fdiv_rn(c0, c2);
        float typ = __fdiv_rn(c1, c2);
        float gx = __fdiv_rn(2.0f * txp, (float)(Ww - 1)) - 1.0f;
        float gy = __fdiv_rn(2.0f * typ, (float)(Hh - 1)) - 1.0f;
        bool msk = (fabsf(gx) <= 1.0f) && (fabsf(gy) <= 1.0f) && (c2 > 0.0f);
        float gxm = msk ? gx : 0.0f;
        float gym = msk ? gy : 0.0f;

        float px = (gxm + 1.0f) * 0.5f * (float)(Ww - 1);
        float py = (gym + 1.0f) * 0.5f * (float)(Hh - 1);
        float x0f = floorf(px), y0f = floorf(py);
        float fx = px - x0f,    fy = py - y0f;
        int x0 = (int)x0f, y0 = (int)y0f;
        bool vx1 = (x0 + 1) < Ww;
        bool vy1 = (y0 + 1) < Hh;
        int x1 = vx1 ? x0 + 1 : x0;
        int y1r = vy1 ? y0 + 1 : y0;
        float mskf = msk ? 1.f : 0.f;
        float w00 = (1.f-fx)*(1.f-fy) * mskf;
        float w01 = (vx1 ? fx*(1.f-fy) : 0.f) * mskf;
        float w10 = (vy1 ? (1.f-fx)*fy : 0.f) * mskf;
        float w11 = ((vx1 && vy1) ? fx*fy : 0.f) * mskf;

        const __half2* rb = g_KMIh + ((size_t)(bi*Nv + n)*HW)*64 + 2*lane;
        uint2 u00 = *(const uint2*)(rb + (size_t)(y0 *Ww + x0)*64);
        uint2 u01 = *(const uint2*)(rb + (size_t)(y0 *Ww + x1)*64);
        uint2 u10 = *(const uint2*)(rb + (size_t)(y1r*Ww + x0)*64);
        uint2 u11 = *(const uint2*)(rb + (size_t)(y1r*Ww + x1)*64);

        float2 a00 = __half22float2(*(__half2*)&u00.x);
        float2 b00 = __half22float2(*(__half2*)&u00.y);
        float2 a01 = __half22float2(*(__half2*)&u01.x);
        float2 b01 = __half22float2(*(__half2*)&u01.y);
        float2 a10 = __half22float2(*(__half2*)&u10.x);
        float2 b10 = __half22float2(*(__half2*)&u10.y);
        float2 a11 = __half22float2(*(__half2*)&u11.x);
        float2 b11 = __half22float2(*(__half2*)&u11.y);

        k1s[n].x = w00*a00.x + w01*a01.x + w10*a10.x + w11*a11.x;
        k1s[n].y = w00*a00.y + w01*a01.y + w10*a10.y + w11*a11.y;
        k2s[n].x = w00*b00.x + w01*b01.x + w10*b10.x + w11*b11.x;
        k2s[n].y = w00*b00.y + w01*b01.y + w10*b10.y + w11*b11.y;
        mbits |= (msk ? 1u : 0u) << n;
    }

    // Phase B: batched block-1 logit reductions
    float pt[9];
    #pragma unroll
    for (int n = 0; n < Nv; n++)
        pt[n] = q1.x*k1s[n].x + q1.y*k1s[n].y;
    #pragma unroll
    for (int off = 16; off; off >>= 1)
        #pragma unroll
        for (int n = 0; n < Nv; n++)
            pt[n] += __shfl_xor_sync(0xffffffffu, pt[n], off);

    float lgs[9];
    #pragma unroll
    for (int n = 0; n < Nv; n++)
        lgs[n] = ((mbits >> n) & 1u) ? pt[n]*0.125f : NEGV;
    float mx = lgs[0];
    #pragma unroll
    for (int n = 1; n < Nv; n++) mx = fmaxf(mx, lgs[n]);
    float se = 0.f;
    float2 y1 = make_float2(0.f, 0.f);
    #pragma unroll
    for (int n = 0; n < Nv; n++) {
        float e = __expf(lgs[n] - mx);
        se += e;
        y1.x += e*k1s[n].x;
        y1.y += e*k1s[n].y;
    }
    float inv1 = __fdiv_rn(1.0f, se);
    float2 yn = make_float2(y1.x*inv1, y1.y*inv1);
    float2 f1 = make_float2(v.x + yn.x, v.y + yn.y);

    // q2 = q2v + Wq2 @ yn  (4-way split accumulators)
    float2 d0 = make_float2(0.f,0.f), d1 = d0, d2 = d0, d3 = d0;
    #pragma unroll
    for (int s = 0; s < 16; s++) {
        float aX = __shfl_sync(0xffffffffu, yn.x, s);
        float aY = __shfl_sync(0xffffffffu, yn.y, s);
        float bX = __shfl_sync(0xffffffffu, yn.x, s + 16);
        float bY = __shfl_sync(0xffffffffu, yn.y, s + 16);
        float2 wa0 = *(const float2*)&WqT2[2*s][2*lane];
        float2 wa1 = *(const float2*)&WqT2[2*s+1][2*lane];
        float2 wb0 = *(const float2*)&WqT2[2*s+32][2*lane];
        float2 wb1 = *(const float2*)&WqT2[2*s+33][2*lane];
        d0.x += wa0.x*aX; d0.y += wa0.y*aX;
        d1.x += wa1.x*aY; d1.y += wa1.y*aY;
        d2.x += wb0.x*bX; d2.y += wb0.y*bX;
        d3.x += wb1.x*bY; d3.y += wb1.y*bY;
    }
    float2 q2;
    q2.x = q2v.x + (d0.x + d1.x) + (d2.x + d3.x);
    q2.y = q2v.y + (d0.y + d1.y) + (d2.y + d3.y);

    // Phase D: batched block-2 logits + softmax
    #pragma unroll
    for (int n = 0; n < Nv; n++)
        pt[n] = q2.x*k2s[n].x + q2.y*k2s[n].y;
    #pragma unroll
    for (int off = 16; off; off >>= 1)
        #pragma unroll
        for (int n = 0; n < Nv; n++)
            pt[n] += __shfl_xor_sync(0xffffffffu, pt[n], off);
    #pragma unroll
    for (int n = 0; n < Nv; n++)
        lgs[n] = ((mbits >> n) & 1u) ? pt[n]*0.125f : NEGV;
    float mx2 = lgs[0];
    #pragma unroll
    for (int n = 1; n < Nv; n++) mx2 = fmaxf(mx2, lgs[n]);
    float se2 = 0.f;
    float2 y2 = make_float2(0.f, 0.f);
    #pragma unroll
    for (int n = 0; n < Nv; n++) {
        float e = __expf(lgs[n] - mx2);
        se2 += e;
        y2.x += e*k2s[n].x;
        y2.y += e*k2s[n].y;
    }
    float inv2 = __fdiv_rn(1.0f, se2);
    float2 o;
    o.x = f1.x + y2.x*inv2;
    o.y = f1.y + y2.y*inv2;
    *(float2*)&out[(size_t)p*64 + 2*lane] = o;
}

// ---------------------------------------------------------------------------
extern "C" void kernel_launch(void* const* d_in, const int* in_sizes, int n_in,
                              void* d_out, int out_size)
{
    (void)in_sizes; (void)n_in; (void)out_size;
    const float* img    = (const float*)d_in[0];
    const int*   coords = (const int*)  d_in[1];
    const float* vox    = (const float*)d_in[2];
    const float* proj   = (const float*)d_in[3];
    const float* orig   = (const float*)d_in[4];
    const int*   cmask  = (const int*)  d_in[5];
    const float* Wq1 = (const float*)d_in[6];
    const float* bq1 = (const float*)d_in[7];
    const float* Wk1 = (const float*)d_in[8];
    const float* bk1 = (const float*)d_in[9];
    const float* Wq2 = (const float*)d_in[10];
    const float* bq2 = (const float*)d_in[11];
    const float* Wk2 = (const float*)d_in[12];
    const float* bk2 = (const float*)d_in[13];
    float* out = (float*)d_out;

    const int KQ_SMEM = (80*136 + 2*8*136 + 128) * 4;   // 52736 B
    static int smem_set = 0;
    if (!smem_set) {
        cudaFuncSetAttribute(keymap_qgemm_kernel,
                             cudaFuncAttributeMaxDynamicSharedMemorySize, KQ_SMEM);
        smem_set = 1;
    }

    void* cntp = nullptr;
    cudaGetSymbolAddress(&cntp, g_selcnt);
    cudaMemsetAsync(cntp, 0, sizeof(int));

    keymap_qgemm_kernel<<<KM_BLOCKS + QG_BLOCKS, 256, KQ_SMEM>>>(
        img, Wk1, bk1, Wk2, bk2, vox, Wq1, bq1, Wq2, bq2);
    compact_kernel<<<(Pp + 255)/256, 256>>>(vox, cmask, out);
    attn_fused_kernel<<<Pp/8, 256>>>(vox, coords, proj, orig, Wq2, out);
}

// round 11
// speedup vs baseline: 3.1472x; 1.1504x over previous
#include <cuda_runtime.h>
#include <cuda_fp16.h>
#include <cstdint>

#define Bc 2
#define Nv 9
#define CBc 80
#define Hh 120
#define Ww 160
#define Dd 64
#define Pp 80000
#define HW (Hh*Ww)            // 19200
#define MTOT (Bc*Nv*HW)       // 345600
#define NEGV -10000.0f

#define KM_BLOCKS (MTOT/128)         // 2700
#define QG_BLOCKS (Pp/128)           // 625
#define CP_BLOCKS ((Pp + 255)/256)   // 313

// Interleaved fp16 key maps: record = 64 half2 words per pixel (256 B).
// word 2j   = {KM1[2j], KM1[2j+1]},  word 2j+1 = {KM2[2j], KM2[2j+1]}
__device__ __half2 g_KMIh[(size_t)MTOT*64];
__device__ float   g_Q[(size_t)Pp*128];    // [p][0:64]=q1, [p][64:128]=q2v
__device__ int     g_selcnt;
__device__ int     g_selidx[Pp];

// smem byte layout for keymap path
#define BH_BYTES   (128*176)          // Bh[128 d][88 halfs] (80 used + pad)
#define AH_BYTES   (128*48)           // one A buffer: [128 px][24 halfs] (16 used)
#define KM_SMEM    (BH_BYTES + 2*AH_BYTES + 512)   // 35328
#define QG_SMEM    ((64*132 + 8*132 + 128)*4)      // 38528

__device__ __forceinline__ uint32_t h2u(__half2 h) {
    return *(uint32_t*)&h;
}

__device__ __forceinline__ void mma_f16(float* c,
                                        uint32_t a0, uint32_t a1,
                                        uint32_t a2, uint32_t a3,
                                        uint32_t b0, uint32_t b1) {
    asm volatile(
        "mma.sync.aligned.m16n8k16.row.col.f32.f16.f16.f32 "
        "{%0,%1,%2,%3},{%4,%5,%6,%7},{%8,%9},{%0,%1,%2,%3};"
        : "+f"(c[0]), "+f"(c[1]), "+f"(c[2]), "+f"(c[3])
        : "r"(a0), "r"(a1), "r"(a2), "r"(a3), "r"(b0), "r"(b1));
}

// ---------------------------------------------------------------------------
// Merged kernel 1:
//   blocks [0, KM)          : key_maps (fp16 MMA m16n8k16, fp32 acc, fp16 out)
//   blocks [KM, KM+QG)      : q-GEMM (fp32 cores)
//   blocks [KM+QG, +CP)     : compaction (sel list + passthrough rows)
// ---------------------------------------------------------------------------
__global__ __launch_bounds__(256) void keymap_qgemm_kernel(
    const float* __restrict__ img,
    const float* __restrict__ Wk1, const float* __restrict__ bk1,
    const float* __restrict__ Wk2, const float* __restrict__ bk2,
    const float* __restrict__ vox,
    const float* __restrict__ Wq1, const float* __restrict__ bq1,
    const float* __restrict__ Wq2, const float* __restrict__ bq2,
    const int*   __restrict__ cmask,
    float* __restrict__ out)
{
    extern __shared__ __align__(16) float dyn[];
    int tid = threadIdx.x;

    if (blockIdx.x < KM_BLOCKS) {
        // ================= keymap: fp16 MMA path =================
        char*  smem    = (char*)dyn;
        char*  BhB     = smem;                      // halfs, row stride 176 B
        char*  AhB     = smem + BH_BYTES;           // 2 buffers, row stride 48 B
        float* bias_sh = (float*)(smem + BH_BYTES + 2*AH_BYTES);

        int m0   = blockIdx.x * 128;
        int bn   = m0 / HW;
        int pix0 = m0 - bn*HW;
        const float* Abase = img + (size_t)bn*CBc*HW + pix0;

        int pxl   = tid & 127;        // loader: pixel column
        int khalf = tid >> 7;         // loader: k-octet (0/1)
        const float* lsrc0 = Abase + (size_t)(khalf*8)*HW + pxl;

        // prefetch chunk 0 into registers
        float f[8];
        #pragma unroll
        for (int j = 0; j < 8; j++) f[j] = lsrc0[(size_t)j*HW];

        // weights -> fp16 in smem: Bh[d][k]
        for (int t = tid; t < 128*CBc; t += 256) {
            int d = t / CBc, k = t - d*CBc;
            float w = (d < 64) ? Wk1[d*CBc + k] : Wk2[(d-64)*CBc + k];
            *(__half*)(BhB + d*176 + k*2) = __float2half(w);
        }
        if (tid < 128) bias_sh[tid] = (tid < 64) ? bk1[tid] : bk2[tid-64];

        // store chunk 0
        {
            uint4 u;
            u.x = h2u(__floats2half2_rn(f[0], f[1]));
            u.y = h2u(__floats2half2_rn(f[2], f[3]));
            u.z = h2u(__floats2half2_rn(f[4], f[5]));
            u.w = h2u(__floats2half2_rn(f[6], f[7]));
            *(uint4*)(AhB + pxl*48 + khalf*16) = u;
        }
        __syncthreads();

        int lane = tid & 31, warp = tid >> 5;
        int r4 = lane >> 2, tg = lane & 3;
        int wm = warp & 3, wn = warp >> 2;     // wm: 32-px group, wn: 64-d half

        float acc[2][8][4];
        #pragma unroll
        for (int mf = 0; mf < 2; mf++)
            #pragma unroll
            for (int nf = 0; nf < 8; nf++)
                #pragma unroll
                for (int i = 0; i < 4; i++) acc[mf][nf][i] = 0.f;

        #pragma unroll
        for (int kc = 0; kc < 5; kc++) {       // K = 80 = 5 x 16
            if (kc < 4) {                      // prefetch next chunk (LDG only)
                const float* ls = Abase + (size_t)((kc+1)*16 + khalf*8)*HW + pxl;
                #pragma unroll
                for (int j = 0; j < 8; j++) f[j] = ls[(size_t)j*HW];
            }

            const char* A = AhB + (kc & 1)*AH_BYTES;
            #pragma unroll
            for (int mf = 0; mf < 2; mf++) {
                int px0 = wm*32 + mf*16;
                const char* ar = A + (px0 + r4)*48 + tg*4;
                uint32_t a0 = *(const uint32_t*)(ar);
                uint32_t a1 = *(const uint32_t*)(ar + 8*48);
                uint32_t a2 = *(const uint32_t*)(ar + 16);
                uint32_t a3 = *(const uint32_t*)(ar + 8*48 + 16);
                #pragma unroll
                for (int nf = 0; nf < 8; nf++) {
                    const char* br = BhB + (wn*64 + nf*8 + r4)*176 + kc*32 + tg*4;
                    uint32_t b0 = *(const uint32_t*)(br);
                    uint32_t b1 = *(const uint32_t*)(br + 16);
                    mma_f16(acc[mf][nf], a0, a1, a2, a3, b0, b1);
                }
            }

            if (kc < 4) {                      // store next chunk, then sync
                uint4 u;
                u.x = h2u(__floats2half2_rn(f[0], f[1]));
                u.y = h2u(__floats2half2_rn(f[2], f[3]));
                u.z = h2u(__floats2half2_rn(f[4], f[5]));
                u.w = h2u(__floats2half2_rn(f[6], f[7]));
                *(uint4*)(AhB + ((kc+1)&1)*AH_BYTES + pxl*48 + khalf*16) = u;
                __syncthreads();
            }
        }

        // epilogue: bias + fp16 interleaved store (C layout: rows r4/r4+8, cols 2tg,2tg+1)
        #pragma unroll
        for (int nf = 0; nf < 8; nf++) {
            int dl   = wn*64 + nf*8 + 2*tg;
            float b0 = bias_sh[dl], b1 = bias_sh[dl+1];
            int widx = (wn == 0) ? dl : (dl - 63);  // half2 word in 64-word record
            #pragma unroll
            for (int mf = 0; mf < 2; mf++) {
                int px = m0 + wm*32 + mf*16 + r4;
                g_KMIh[(size_t)px*64 + widx] =
                    __floats2half2_rn(acc[mf][nf][0]+b0, acc[mf][nf][1]+b1);
                g_KMIh[(size_t)(px+8)*64 + widx] =
                    __floats2half2_rn(acc[mf][nf][2]+b0, acc[mf][nf][3]+b1);
            }
        }
        return;
    }

    if (blockIdx.x < KM_BLOCKS + QG_BLOCKS) {
        // ================= q-GEMM path (fp32 cores) =================
        float* BshT    = dyn;                    // [64][132]
        float* Ash2    = BshT + 64*132;          // [8][132]
        float* bias_sh = Ash2 + 8*132;           // [128]

        {
            int d  = tid >> 1;
            const float* src = (d < 64) ? &Wq1[d*64] : &Wq2[(d-64)*64];
            #pragma unroll
            for (int i = 0; i < 8; i++) {
                int k = (tid & 1)*4 + 8*i;
                float4 w = *(const float4*)&src[k];
                BshT[(k+0)*132 + d] = w.x; BshT[(k+1)*132 + d] = w.y;
                BshT[(k+2)*132 + d] = w.z; BshT[(k+3)*132 + d] = w.w;
            }
        }
        if (tid < 128) bias_sh[tid] = (tid < 64) ? bq1[tid] : bq2[tid-64];

        int p0 = (blockIdx.x - KM_BLOCKS) * 128;
        int tx = tid & 15, ty = tid >> 4;

        float acc[8][8];
        #pragma unroll
        for (int i = 0; i < 8; i++)
            #pragma unroll
            for (int j = 0; j < 8; j++) acc[i][j] = 0.f;

        #pragma unroll
        for (int kc = 0; kc < 8; kc++) {
            __syncthreads();
            {
                int px = tid >> 1;
                int k0 = (tid & 1)*4;
                float4 a = *(const float4*)&vox[(size_t)(p0+px)*64 + kc*8 + k0];
                Ash2[(k0+0)*132 + px] = a.x; Ash2[(k0+1)*132 + px] = a.y;
                Ash2[(k0+2)*132 + px] = a.z; Ash2[(k0+3)*132 + px] = a.w;
            }
            __syncthreads();
            #pragma unroll
            for (int k = 0; k < 8; k++) {
                float4 a0 = *(const float4*)&Ash2[k*132 + ty*4];
                float4 a1 = *(const float4*)&Ash2[k*132 + 64 + ty*4];
                float4 b0 = *(const float4*)&BshT[(kc*8+k)*132 + tx*4];
                float4 b1 = *(const float4*)&BshT[(kc*8+k)*132 + 64 + tx*4];
                float av[8] = {a0.x,a0.y,a0.z,a0.w, a1.x,a1.y,a1.z,a1.w};
                float bv[8] = {b0.x,b0.y,b0.z,b0.w, b1.x,b1.y,b1.z,b1.w};
                #pragma unroll
                for (int i = 0; i < 8; i++)
                    #pragma unroll
                    for (int j = 0; j < 8; j++)
                        acc[i][j] += av[i] * bv[j];
            }
        }

        float bj1[4], bj2[4];
        #pragma unroll
        for (int j = 0; j < 4; j++) {
            bj1[j] = bias_sh[tx*4 + j];
            bj2[j] = bias_sh[64 + tx*4 + j];
        }
        #pragma unroll
        for (int i = 0; i < 8; i++) {
            int p = p0 + ((i < 4) ? (ty*4 + i) : (64 + ty*4 + (i - 4)));
            float4 o1 = make_float4(acc[i][0]+bj1[0], acc[i][1]+bj1[1],
                                    acc[i][2]+bj1[2], acc[i][3]+bj1[3]);
            float4 o2 = make_float4(acc[i][4]+bj2[0], acc[i][5]+bj2[1],
                                    acc[i][6]+bj2[2], acc[i][7]+bj2[3]);
            *(float4*)&g_Q[(size_t)p*128 + tx*4]      = o1;
            *(float4*)&g_Q[(size_t)p*128 + 64 + tx*4] = o2;
        }
        return;
    }

    // ================= compaction path =================
    {
        int cb   = blockIdx.x - KM_BLOCKS - QG_BLOCKS;
        int p    = cb * 256 + tid;
        int lane = tid & 31;

        bool sel = (p < Pp) && (cmask[p] > 1);
        unsigned mask = __ballot_sync(0xffffffffu, sel);

        int wbase = 0;
        if (lane == 0) wbase = atomicAdd(&g_selcnt, __popc(mask));
        wbase = __shfl_sync(0xffffffffu, wbase, 0);
        if (sel)
            g_selidx[wbase + __popc(mask & ((1u << lane) - 1u))] = p;

        int rowbase = cb * 256 + (tid >> 5) * 32;
        #pragma unroll 4
        for (int j = 0; j < 32; j++) {
            int pj = rowbase + j;
            if (pj < Pp && !((mask >> j) & 1u)) {
                float2 t = *(const float2*)&vox[(size_t)pj*64 + 2*lane];
                *(float2*)&out[(size_t)pj*64 + 2*lane] = t;
            }
        }
    }
}

// ---------------------------------------------------------------------------
// Kernel 2: fused attention over the DENSE sel list. One warp per sel point.
// ---------------------------------------------------------------------------
__global__ __launch_bounds__(256, 4) void attn_fused_kernel(
    const float* __restrict__ vox,
    const int*   __restrict__ coords,
    const float* __restrict__ proj,
    const float* __restrict__ origins,
    const float* __restrict__ Wq2,
    float* __restrict__ out)
{
    __shared__ float WqT2[64][64];        // WqT2[i][d] = Wq2[d][i]
    __shared__ float projs[Bc*Nv*12];
    __shared__ float orig_s[Bc*3];

    int cnt = g_selcnt;
    if (blockIdx.x * 8 >= cnt) return;    // block-uniform early exit

    int tid = threadIdx.x;
    for (int t = tid; t < 4096; t += 256)
        WqT2[t & 63][t >> 6] = Wq2[t];
    if (tid < Bc*Nv*12) projs[tid] = proj[tid];
    if (tid < Bc*3)     orig_s[tid] = origins[tid];
    __syncthreads();

    int widx = blockIdx.x * 8 + (tid >> 5);
    if (widx >= cnt) return;              // warp-uniform (after sync)
    int p    = g_selidx[widx];
    int lane = tid & 31;

    float2 v = *(const float2*)&vox[(size_t)p*64 + 2*lane];
    float2 q1  = *(const float2*)&g_Q[(size_t)p*128 + 2*lane];
    float2 q2v = *(const float2*)&g_Q[(size_t)p*128 + 64 + 2*lane];

    int4 cc = __ldg((const int4*)coords + p);
    int bi = cc.w;
    float X = (float)cc.x * 0.16f + orig_s[bi*3 + 0];
    float Y = (float)cc.y * 0.16f + orig_s[bi*3 + 1];
    float Z = (float)cc.z * 0.16f + orig_s[bi*3 + 2];

    float2 k1s[9], k2s[9];
    unsigned mbits = 0;

    // Phase A: gather all views (independent across n -> deep MLP)
    #pragma unroll
    for (int n = 0; n < Nv; n++) {
        const float* Pm = &projs[(bi*Nv + n)*12];
        float c0 = Pm[0]*X + Pm[1]*Y + Pm[2]*Z  + Pm[3];
        float c1 = Pm[4]*X + Pm[5]*Y + Pm[6]*Z  + Pm[7];
        float c2 = Pm[8]*X + Pm[9]*Y + Pm[10]*Z + Pm[11];
        float txp = __fdiv_rn(c0, c2);
        float typ = __fdiv_rn(c1, c2);
        float gx = __fdiv_rn(2.0f * txp, (float)(Ww - 1)) - 1.0f;
        float gy = __fdiv_rn(2.0f * typ, (float)(Hh - 1)) - 1.0f;
        bool msk = (fabsf(gx) <= 1.0f) && (fabsf(gy) <= 1.0f) && (c2 > 0.0f);
        float gxm = msk ? gx : 0.0f;
        float gym = msk ? gy : 0.0f;

        float px = (gxm + 1.0f) * 0.5f * (float)(Ww - 1);
        float py = (gym + 1.0f) * 0.5f * (float)(Hh - 1);
        float x0f = floorf(px), y0f = floorf(py);
        float fx = px - x0f,    fy = py - y0f;
        int x0 = (int)x0f, y0 = (int)y0f;
        bool vx1 = (x0 + 1) < Ww;
        bool vy1 = (y0 + 1) < Hh;
        int x1 = vx1 ? x0 + 1 : x0;
        int y1r = vy1 ? y0 + 1 : y0;
        float mskf = msk ? 1.f : 0.f;
        float w00 = (1.f-fx)*(1.f-fy) * mskf;
        float w01 = (vx1 ? fx*(1.f-fy) : 0.f) * mskf;
        float w10 = (vy1 ? (1.f-fx)*fy : 0.f) * mskf;
        float w11 = ((vx1 && vy1) ? fx*fy : 0.f) * mskf;

        const __half2* rb = g_KMIh + ((size_t)(bi*Nv + n)*HW)*64 + 2*lane;
        uint2 u00 = *(const uint2*)(rb + (size_t)(y0 *Ww + x0)*64);
        uint2 u01 = *(const uint2*)(rb + (size_t)(y0 *Ww + x1)*64);
        uint2 u10 = *(const uint2*)(rb + (size_t)(y1r*Ww + x0)*64);
        uint2 u11 = *(const uint2*)(rb + (size_t)(y1r*Ww + x1)*64);

        float2 a00 = __half22float2(*(__half2*)&u00.x);
        float2 b00 = __half22float2(*(__half2*)&u00.y);
        float2 a01 = __half22float2(*(__half2*)&u01.x);
        float2 b01 = __half22float2(*(__half2*)&u01.y);
        float2 a10 = __half22float2(*(__half2*)&u10.x);
        float2 b10 = __half22float2(*(__half2*)&u10.y);
        float2 a11 = __half22float2(*(__half2*)&u11.x);
        float2 b11 = __half22float2(*(__half2*)&u11.y);

        k1s[n].x = w00*a00.x + w01*a01.x + w10*a10.x + w11*a11.x;
        k1s[n].y = w00*a00.y + w01*a01.y + w10*a10.y + w11*a11.y;
        k2s[n].x = w00*b00.x + w01*b01.x + w10*b10.x + w11*b11.x;
        k2s[n].y = w00*b00.y + w01*b01.y + w10*b10.y + w11*b11.y;
        mbits |= (msk ? 1u : 0u) << n;
    }

    // Phase B: batched block-1 logit reductions
    float pt[9];
    #pragma unroll
    for (int n = 0; n < Nv; n++)
        pt[n] = q1.x*k1s[n].x + q1.y*k1s[n].y;
    #pragma unroll
    for (int off = 16; off; off >>= 1)
        #pragma unroll
        for (int n = 0; n < Nv; n++)
            pt[n] += __shfl_xor_sync(0xffffffffu, pt[n], off);

    float lgs[9];
    #pragma unroll
    for (int n = 0; n < Nv; n++)
        lgs[n] = ((mbits >> n) & 1u) ? pt[n]*0.125f : NEGV;
    float mx = lgs[0];
    #pragma unroll
    for (int n = 1; n < Nv; n++) mx = fmaxf(mx, lgs[n]);
    float se = 0.f;
    float2 y1 = make_float2(0.f, 0.f);
    #pragma unroll
    for (int n = 0; n < Nv; n++) {
        float e = __expf(lgs[n] - mx);
        se += e;
        y1.x += e*k1s[n].x;
        y1.y += e*k1s[n].y;
    }
    float inv1 = __fdiv_rn(1.0f, se);
    float2 yn = make_float2(y1.x*inv1, y1.y*inv1);
    float2 f1 = make_float2(v.x + yn.x, v.y + yn.y);

    // q2 = q2v + Wq2 @ yn  (4-way split accumulators)
    float2 d0 = make_float2(0.f,0.f), d1 = d0, d2 = d0, d3 = d0;
    #pragma unroll
    for (int s = 0; s < 16; s++) {
        float aX = __shfl_sync(0xffffffffu, yn.x, s);
        float aY = __shfl_sync(0xffffffffu, yn.y, s);
        float bX = __shfl_sync(0xffffffffu, yn.x, s + 16);
        float bY = __shfl_sync(0xffffffffu, yn.y, s + 16);
        float2 wa0 = *(const float2*)&WqT2[2*s][2*lane];
        float2 wa1 = *(const float2*)&WqT2[2*s+1][2*lane];
        float2 wb0 = *(const float2*)&WqT2[2*s+32][2*lane];
        float2 wb1 = *(const float2*)&WqT2[2*s+33][2*lane];
        d0.x += wa0.x*aX; d0.y += wa0.y*aX;
        d1.x += wa1.x*aY; d1.y += wa1.y*aY;
        d2.x += wb0.x*bX; d2.y += wb0.y*bX;
        d3.x += wb1.x*bY; d3.y += wb1.y*bY;
    }
    float2 q2;
    q2.x = q2v.x + (d0.x + d1.x) + (d2.x + d3.x);
    q2.y = q2v.y + (d0.y + d1.y) + (d2.y + d3.y);

    // Phase D: batched block-2 logits + softmax
    #pragma unroll
    for (int n = 0; n < Nv; n++)
        pt[n] = q2.x*k2s[n].x + q2.y*k2s[n].y;
    #pragma unroll
    for (int off = 16; off; off >>= 1)
        #pragma unroll
        for (int n = 0; n < Nv; n++)
            pt[n] += __shfl_xor_sync(0xffffffffu, pt[n], off);
    #pragma unroll
    for (int n = 0; n < Nv; n++)
        lgs[n] = ((mbits >> n) & 1u) ? pt[n]*0.125f : NEGV;
    float mx2 = lgs[0];
    #pragma unroll
    for (int n = 1; n < Nv; n++) mx2 = fmaxf(mx2, lgs[n]);
    float se2 = 0.f;
    float2 y2 = make_float2(0.f, 0.f);
    #pragma unroll
    for (int n = 0; n < Nv; n++) {
        float e = __expf(lgs[n] - mx2);
        se2 += e;
        y2.x += e*k2s[n].x;
        y2.y += e*k2s[n].y;
    }
    float inv2 = __fdiv_rn(1.0f, se2);
    float2 o;
    o.x = f1.x + y2.x*inv2;
    o.y = f1.y + y2.y*inv2;
    *(float2*)&out[(size_t)p*64 + 2*lane] = o;
}

// ---------------------------------------------------------------------------
extern "C" void kernel_launch(void* const* d_in, const int* in_sizes, int n_in,
                              void* d_out, int out_size)
{
    (void)in_sizes; (void)n_in; (void)out_size;
    const float* img    = (const float*)d_in[0];
    const int*   coords = (const int*)  d_in[1];
    const float* vox    = (const float*)d_in[2];
    const float* proj   = (const float*)d_in[3];
    const float* orig   = (const float*)d_in[4];
    const int*   cmask  = (const int*)  d_in[5];
    const float* Wq1 = (const float*)d_in[6];
    const float* bq1 = (const float*)d_in[7];
    const float* Wk1 = (const float*)d_in[8];
    const float* bk1 = (const float*)d_in[9];
    const float* Wq2 = (const float*)d_in[10];
    const float* bq2 = (const float*)d_in[11];
    const float* Wk2 = (const float*)d_in[12];
    const float* bk2 = (const float*)d_in[13];
    float* out = (float*)d_out;

    const int KQ_SMEM = (KM_SMEM > QG_SMEM) ? KM_SMEM : QG_SMEM;  // 38528
    static int smem_set = 0;
    if (!smem_set) {
        cudaFuncSetAttribute(keymap_qgemm_kernel,
                             cudaFuncAttributeMaxDynamicSharedMemorySize, KQ_SMEM);
        smem_set = 1;
    }

    void* cntp = nullptr;
    cudaGetSymbolAddress(&cntp, g_selcnt);
    cudaMemsetAsync(cntp, 0, sizeof(int));

    keymap_qgemm_kernel<<<KM_BLOCKS + QG_BLOCKS + CP_BLOCKS, 256, KQ_SMEM>>>(
        img, Wk1, bk1, Wk2, bk2, vox, Wq1, bq1, Wq2, bq2, cmask, out);
    attn_fused_kernel<<<Pp/8, 256>>>(vox, coords, proj, orig, Wq2, out);
}

// round 12
// speedup vs baseline: 3.7942x; 1.2056x over previous
#include <cuda_runtime.h>
#include <cuda_fp16.h>
#include <cstdint>

#define Bc 2
#define Nv 9
#define CBc 80
#define Hh 120
#define Ww 160
#define Dd 64
#define Pp 80000
#define HW (Hh*Ww)            // 19200
#define MTOT (Bc*Nv*HW)       // 345600
#define NEGV -10000.0f

#define KM_BLOCKS (MTOT/128)         // 2700
#define QG_BLOCKS (Pp/128)           // 625
#define CP_BLOCKS ((Pp + 255)/256)   // 313
#define AT_BLOCKS ((Pp + 31)/32)     // 2500

// Interleaved fp16 key maps: record = 64 half2 words per pixel (256 B).
// word 2j   = {KM1[2j], KM1[2j+1]},  word 2j+1 = {KM2[2j], KM2[2j+1]}
__device__ __half2 g_KMIh[(size_t)MTOT*64];
__device__ float   g_Q[(size_t)Pp*128];    // [p][0:64]=q1, [p][64:128]=q2v
__device__ int     g_selcnt;
__device__ int     g_selidx[Pp];

// smem byte layout for keymap path
#define BH_BYTES   (128*176)          // Bh[128 d][88 halfs] (80 used + pad)
#define AH_BYTES   (128*48)           // one A buffer: [128 px][24 halfs] (16 used)
#define KM_SMEM    (BH_BYTES + 2*AH_BYTES + 512)   // 35328
#define QG_SMEM    ((64*132 + 8*132 + 128)*4)      // 38528

__device__ __forceinline__ uint32_t h2u(__half2 h) {
    return *(uint32_t*)&h;
}

__device__ __forceinline__ void mma_f16(float* c,
                                        uint32_t a0, uint32_t a1,
                                        uint32_t a2, uint32_t a3,
                                        uint32_t b0, uint32_t b1) {
    asm volatile(
        "mma.sync.aligned.m16n8k16.row.col.f32.f16.f16.f32 "
        "{%0,%1,%2,%3},{%4,%5,%6,%7},{%8,%9},{%0,%1,%2,%3};"
        : "+f"(c[0]), "+f"(c[1]), "+f"(c[2]), "+f"(c[3])
        : "r"(a0), "r"(a1), "r"(a2), "r"(a3), "r"(b0), "r"(b1));
}

// ---------------------------------------------------------------------------
// Merged kernel 1:
//   blocks [0, KM)          : key_maps (fp16 MMA m16n8k16, fp32 acc, fp16 out)
//   blocks [KM, KM+QG)      : q-GEMM (fp32 cores)
//   blocks [KM+QG, +CP)     : compaction (sel list + passthrough rows)
// ---------------------------------------------------------------------------
__global__ __launch_bounds__(256) void keymap_qgemm_kernel(
    const float* __restrict__ img,
    const float* __restrict__ Wk1, const float* __restrict__ bk1,
    const float* __restrict__ Wk2, const float* __restrict__ bk2,
    const float* __restrict__ vox,
    const float* __restrict__ Wq1, const float* __restrict__ bq1,
    const float* __restrict__ Wq2, const float* __restrict__ bq2,
    const int*   __restrict__ cmask,
    float* __restrict__ out)
{
    extern __shared__ __align__(16) float dyn[];
    int tid = threadIdx.x;

    if (blockIdx.x < KM_BLOCKS) {
        // ================= keymap: fp16 MMA path =================
        char*  smem    = (char*)dyn;
        char*  BhB     = smem;                      // halfs, row stride 176 B
        char*  AhB     = smem + BH_BYTES;           // 2 buffers, row stride 48 B
        float* bias_sh = (float*)(smem + BH_BYTES + 2*AH_BYTES);

        int m0   = blockIdx.x * 128;
        int bn   = m0 / HW;
        int pix0 = m0 - bn*HW;
        const float* Abase = img + (size_t)bn*CBc*HW + pix0;

        int pxl   = tid & 127;        // loader: pixel column
        int khalf = tid >> 7;         // loader: k-octet (0/1)
        const float* lsrc0 = Abase + (size_t)(khalf*8)*HW + pxl;

        // prefetch chunk 0 into registers
        float f[8];
        #pragma unroll
        for (int j = 0; j < 8; j++) f[j] = lsrc0[(size_t)j*HW];

        // weights -> fp16 in smem: Bh[d][k]
        for (int t = tid; t < 128*CBc; t += 256) {
            int d = t / CBc, k = t - d*CBc;
            float w = (d < 64) ? Wk1[d*CBc + k] : Wk2[(d-64)*CBc + k];
            *(__half*)(BhB + d*176 + k*2) = __float2half(w);
        }
        if (tid < 128) bias_sh[tid] = (tid < 64) ? bk1[tid] : bk2[tid-64];

        // store chunk 0
        {
            uint4 u;
            u.x = h2u(__floats2half2_rn(f[0], f[1]));
            u.y = h2u(__floats2half2_rn(f[2], f[3]));
            u.z = h2u(__floats2half2_rn(f[4], f[5]));
            u.w = h2u(__floats2half2_rn(f[6], f[7]));
            *(uint4*)(AhB + pxl*48 + khalf*16) = u;
        }
        __syncthreads();

        int lane = tid & 31, warp = tid >> 5;
        int r4 = lane >> 2, tg = lane & 3;
        int wm = warp & 3, wn = warp >> 2;     // wm: 32-px group, wn: 64-d half

        float acc[2][8][4];
        #pragma unroll
        for (int mf = 0; mf < 2; mf++)
            #pragma unroll
            for (int nf = 0; nf < 8; nf++)
                #pragma unroll
                for (int i = 0; i < 4; i++) acc[mf][nf][i] = 0.f;

        #pragma unroll
        for (int kc = 0; kc < 5; kc++) {       // K = 80 = 5 x 16
            if (kc < 4) {                      // prefetch next chunk (LDG only)
                const float* ls = Abase + (size_t)((kc+1)*16 + khalf*8)*HW + pxl;
                #pragma unroll
                for (int j = 0; j < 8; j++) f[j] = ls[(size_t)j*HW];
            }

            const char* A = AhB + (kc & 1)*AH_BYTES;
            #pragma unroll
            for (int mf = 0; mf < 2; mf++) {
                int px0 = wm*32 + mf*16;
                const char* ar = A + (px0 + r4)*48 + tg*4;
                uint32_t a0 = *(const uint32_t*)(ar);
                uint32_t a1 = *(const uint32_t*)(ar + 8*48);
                uint32_t a2 = *(const uint32_t*)(ar + 16);
                uint32_t a3 = *(const uint32_t*)(ar + 8*48 + 16);
                #pragma unroll
                for (int nf = 0; nf < 8; nf++) {
                    const char* br = BhB + (wn*64 + nf*8 + r4)*176 + kc*32 + tg*4;
                    uint32_t b0 = *(const uint32_t*)(br);
                    uint32_t b1 = *(const uint32_t*)(br + 16);
                    mma_f16(acc[mf][nf], a0, a1, a2, a3, b0, b1);
                }
            }

            if (kc < 4) {                      // store next chunk, then sync
                uint4 u;
                u.x = h2u(__floats2half2_rn(f[0], f[1]));
                u.y = h2u(__floats2half2_rn(f[2], f[3]));
                u.z = h2u(__floats2half2_rn(f[4], f[5]));
                u.w = h2u(__floats2half2_rn(f[6], f[7]));
                *(uint4*)(AhB + ((kc+1)&1)*AH_BYTES + pxl*48 + khalf*16) = u;
                __syncthreads();
            }
        }

        // epilogue: bias + fp16 interleaved store
        #pragma unroll
        for (int nf = 0; nf < 8; nf++) {
            int dl   = wn*64 + nf*8 + 2*tg;
            float b0 = bias_sh[dl], b1 = bias_sh[dl+1];
            int widx = (wn == 0) ? dl : (dl - 63);  // half2 word in 64-word record
            #pragma unroll
            for (int mf = 0; mf < 2; mf++) {
                int px = m0 + wm*32 + mf*16 + r4;
                g_KMIh[(size_t)px*64 + widx] =
                    __floats2half2_rn(acc[mf][nf][0]+b0, acc[mf][nf][1]+b1);
                g_KMIh[(size_t)(px+8)*64 + widx] =
                    __floats2half2_rn(acc[mf][nf][2]+b0, acc[mf][nf][3]+b1);
            }
        }
        return;
    }

    if (blockIdx.x < KM_BLOCKS + QG_BLOCKS) {
        // ================= q-GEMM path (fp32 cores) =================
        float* BshT    = dyn;                    // [64][132]
        float* Ash2    = BshT + 64*132;          // [8][132]
        float* bias_sh = Ash2 + 8*132;           // [128]

        {
            int d  = tid >> 1;
            const float* src = (d < 64) ? &Wq1[d*64] : &Wq2[(d-64)*64];
            #pragma unroll
            for (int i = 0; i < 8; i++) {
                int k = (tid & 1)*4 + 8*i;
                float4 w = *(const float4*)&src[k];
                BshT[(k+0)*132 + d] = w.x; BshT[(k+1)*132 + d] = w.y;
                BshT[(k+2)*132 + d] = w.z; BshT[(k+3)*132 + d] = w.w;
            }
        }
        if (tid < 128) bias_sh[tid] = (tid < 64) ? bq1[tid] : bq2[tid-64];

        int p0 = (blockIdx.x - KM_BLOCKS) * 128;
        int tx = tid & 15, ty = tid >> 4;

        float acc[8][8];
        #pragma unroll
        for (int i = 0; i < 8; i++)
            #pragma unroll
            for (int j = 0; j < 8; j++) acc[i][j] = 0.f;

        #pragma unroll
        for (int kc = 0; kc < 8; kc++) {
            __syncthreads();
            {
                int px = tid >> 1;
                int k0 = (tid & 1)*4;
                float4 a = *(const float4*)&vox[(size_t)(p0+px)*64 + kc*8 + k0];
                Ash2[(k0+0)*132 + px] = a.x; Ash2[(k0+1)*132 + px] = a.y;
                Ash2[(k0+2)*132 + px] = a.z; Ash2[(k0+3)*132 + px] = a.w;
            }
            __syncthreads();
            #pragma unroll
            for (int k = 0; k < 8; k++) {
                float4 a0 = *(const float4*)&Ash2[k*132 + ty*4];
                float4 a1 = *(const float4*)&Ash2[k*132 + 64 + ty*4];
                float4 b0 = *(const float4*)&BshT[(kc*8+k)*132 + tx*4];
                float4 b1 = *(const float4*)&BshT[(kc*8+k)*132 + 64 + tx*4];
                float av[8] = {a0.x,a0.y,a0.z,a0.w, a1.x,a1.y,a1.z,a1.w};
                float bv[8] = {b0.x,b0.y,b0.z,b0.w, b1.x,b1.y,b1.z,b1.w};
                #pragma unroll
                for (int i = 0; i < 8; i++)
                    #pragma unroll
                    for (int j = 0; j < 8; j++)
                        acc[i][j] += av[i] * bv[j];
            }
        }

        float bj1[4], bj2[4];
        #pragma unroll
        for (int j = 0; j < 4; j++) {
            bj1[j] = bias_sh[tx*4 + j];
            bj2[j] = bias_sh[64 + tx*4 + j];
        }
        #pragma unroll
        for (int i = 0; i < 8; i++) {
            int p = p0 + ((i < 4) ? (ty*4 + i) : (64 + ty*4 + (i - 4)));
            float4 o1 = make_float4(acc[i][0]+bj1[0], acc[i][1]+bj1[1],
                                    acc[i][2]+bj1[2], acc[i][3]+bj1[3]);
            float4 o2 = make_float4(acc[i][4]+bj2[0], acc[i][5]+bj2[1],
                                    acc[i][6]+bj2[2], acc[i][7]+bj2[3]);
            *(float4*)&g_Q[(size_t)p*128 + tx*4]      = o1;
            *(float4*)&g_Q[(size_t)p*128 + 64 + tx*4] = o2;
        }
        return;
    }

    // ================= compaction path =================
    {
        int cb   = blockIdx.x - KM_BLOCKS - QG_BLOCKS;
        int p    = cb * 256 + tid;
        int lane = tid & 31;

        bool sel = (p < Pp) && (cmask[p] > 1);
        unsigned mask = __ballot_sync(0xffffffffu, sel);

        int wbase = 0;
        if (lane == 0) wbase = atomicAdd(&g_selcnt, __popc(mask));
        wbase = __shfl_sync(0xffffffffu, wbase, 0);
        if (sel)
            g_selidx[wbase + __popc(mask & ((1u << lane) - 1u))] = p;

        int rowbase = cb * 256 + (tid >> 5) * 32;
        #pragma unroll 4
        for (int j = 0; j < 32; j++) {
            int pj = rowbase + j;
            if (pj < Pp && !((mask >> j) & 1u)) {
                float2 t = *(const float2*)&vox[(size_t)pj*64 + 2*lane];
                *(float2*)&out[(size_t)pj*64 + 2*lane] = t;
            }
        }
    }
}

// ---------------------------------------------------------------------------
// Kernel 2: fused attention over DENSE sel list. 4 points per warp
// (amortizes Wq2 staging), 1 reciprocal per view, batched reductions.
// ---------------------------------------------------------------------------
__global__ __launch_bounds__(256, 4) void attn_fused_kernel(
    const float* __restrict__ vox,
    const int*   __restrict__ coords,
    const float* __restrict__ proj,
    const float* __restrict__ origins,
    const float* __restrict__ Wq2,
    float* __restrict__ out)
{
    __shared__ float WqT2[64][64];        // WqT2[i][d] = Wq2[d][i]
    __shared__ float projs[Bc*Nv*12];
    __shared__ float orig_s[Bc*3];

    int cnt = g_selcnt;
    if (blockIdx.x * 32 >= cnt) return;   // block-uniform early exit

    int tid = threadIdx.x;
    // vectorized transpose staging: 4 x LDG.128 + 16 scattered STS per thread
    for (int t = tid; t < 1024; t += 256) {
        int d = t >> 4, i0 = (t & 15) * 4;
        float4 w = *(const float4*)&Wq2[d*64 + i0];
        WqT2[i0+0][d] = w.x; WqT2[i0+1][d] = w.y;
        WqT2[i0+2][d] = w.z; WqT2[i0+3][d] = w.w;
    }
    if (tid < Bc*Nv*12) projs[tid] = proj[tid];
    if (tid < Bc*3)     orig_s[tid] = origins[tid];
    __syncthreads();

    int warp = tid >> 5, lane = tid & 31;

    #pragma unroll 1
    for (int c = 0; c < 4; c++) {
        int widx = blockIdx.x * 32 + c * 8 + warp;
        if (widx >= cnt) break;           // warp-uniform
        int p = g_selidx[widx];

        float2 v   = *(const float2*)&vox[(size_t)p*64 + 2*lane];
        float2 q1  = *(const float2*)&g_Q[(size_t)p*128 + 2*lane];
        float2 q2v = *(const float2*)&g_Q[(size_t)p*128 + 64 + 2*lane];

        int4 cc = __ldg((const int4*)coords + p);
        int bi = cc.w;
        float X = (float)cc.x * 0.16f + orig_s[bi*3 + 0];
        float Y = (float)cc.y * 0.16f + orig_s[bi*3 + 1];
        float Z = (float)cc.z * 0.16f + orig_s[bi*3 + 2];

        float2 k1s[9], k2s[9];
        unsigned mbits = 0;

        // Phase A: gather all views
        #pragma unroll
        for (int n = 0; n < Nv; n++) {
            const float* Pm = &projs[(bi*Nv + n)*12];
            float c0 = Pm[0]*X + Pm[1]*Y + Pm[2]*Z  + Pm[3];
            float c1 = Pm[4]*X + Pm[5]*Y + Pm[6]*Z  + Pm[7];
            float c2 = Pm[8]*X + Pm[9]*Y + Pm[10]*Z + Pm[11];
            float inv = __fdiv_rn(1.0f, c2);
            float txp = c0 * inv;
            float typ = c1 * inv;
            bool msk = (c2 > 0.0f) &&
                       (txp >= 0.0f) && (txp <= (float)(Ww-1)) &&
                       (typ >= 0.0f) && (typ <= (float)(Hh-1));
            float px = msk ? txp : 0.0f;
            float py = msk ? typ : 0.0f;

            float x0f = floorf(px), y0f = floorf(py);
            float fx = px - x0f,    fy = py - y0f;
            int x0 = (int)x0f, y0 = (int)y0f;
            bool vx1 = (x0 + 1) < Ww;
            bool vy1 = (y0 + 1) < Hh;
            int x1 = vx1 ? x0 + 1 : x0;
            int y1r = vy1 ? y0 + 1 : y0;
            float mskf = msk ? 1.f : 0.f;
            float w00 = (1.f-fx)*(1.f-fy) * mskf;
            float w01 = (vx1 ? fx*(1.f-fy) : 0.f) * mskf;
            float w10 = (vy1 ? (1.f-fx)*fy : 0.f) * mskf;
            float w11 = ((vx1 && vy1) ? fx*fy : 0.f) * mskf;

            const __half2* rb = g_KMIh + ((size_t)(bi*Nv + n)*HW)*64 + 2*lane;
            uint2 u00 = *(const uint2*)(rb + (size_t)(y0 *Ww + x0)*64);
            uint2 u01 = *(const uint2*)(rb + (size_t)(y0 *Ww + x1)*64);
            uint2 u10 = *(const uint2*)(rb + (size_t)(y1r*Ww + x0)*64);
            uint2 u11 = *(const uint2*)(rb + (size_t)(y1r*Ww + x1)*64);

            float2 a00 = __half22float2(*(__half2*)&u00.x);
            float2 b00 = __half22float2(*(__half2*)&u00.y);
            float2 a01 = __half22float2(*(__half2*)&u01.x);
            float2 b01 = __half22float2(*(__half2*)&u01.y);
            float2 a10 = __half22float2(*(__half2*)&u10.x);
            float2 b10 = __half22float2(*(__half2*)&u10.y);
            float2 a11 = __half22float2(*(__half2*)&u11.x);
            float2 b11 = __half22float2(*(__half2*)&u11.y);

            k1s[n].x = w00*a00.x + w01*a01.x + w10*a10.x + w11*a11.x;
            k1s[n].y = w00*a00.y + w01*a01.y + w10*a10.y + w11*a11.y;
            k2s[n].x = w00*b00.x + w01*b01.x + w10*b10.x + w11*b11.x;
            k2s[n].y = w00*b00.y + w01*b01.y + w10*b10.y + w11*b11.y;
            mbits |= (msk ? 1u : 0u) << n;
        }

        // Phase B: batched block-1 logit reductions
        float pt[9];
        #pragma unroll
        for (int n = 0; n < Nv; n++)
            pt[n] = q1.x*k1s[n].x + q1.y*k1s[n].y;
        #pragma unroll
        for (int off = 16; off; off >>= 1)
            #pragma unroll
            for (int n = 0; n < Nv; n++)
                pt[n] += __shfl_xor_sync(0xffffffffu, pt[n], off);

        float lgs[9];
        #pragma unroll
        for (int n = 0; n < Nv; n++)
            lgs[n] = ((mbits >> n) & 1u) ? pt[n]*0.125f : NEGV;
        float mx = lgs[0];
        #pragma unroll
        for (int n = 1; n < Nv; n++) mx = fmaxf(mx, lgs[n]);
        float se = 0.f;
        float2 y1 = make_float2(0.f, 0.f);
        #pragma unroll
        for (int n = 0; n < Nv; n++) {
            float e = __expf(lgs[n] - mx);
            se += e;
            y1.x += e*k1s[n].x;
            y1.y += e*k1s[n].y;
        }
        float inv1 = __fdiv_rn(1.0f, se);
        float2 yn = make_float2(y1.x*inv1, y1.y*inv1);
        float2 f1 = make_float2(v.x + yn.x, v.y + yn.y);

        // q2 = q2v + Wq2 @ yn  (4-way split accumulators)
        float2 d0 = make_float2(0.f,0.f), d1 = d0, d2 = d0, d3 = d0;
        #pragma unroll
        for (int s = 0; s < 16; s++) {
            float aX = __shfl_sync(0xffffffffu, yn.x, s);
            float aY = __shfl_sync(0xffffffffu, yn.y, s);
            float bX = __shfl_sync(0xffffffffu, yn.x, s + 16);
            float bY = __shfl_sync(0xffffffffu, yn.y, s + 16);
            float2 wa0 = *(const float2*)&WqT2[2*s][2*lane];
            float2 wa1 = *(const float2*)&WqT2[2*s+1][2*lane];
            float2 wb0 = *(const float2*)&WqT2[2*s+32][2*lane];
            float2 wb1 = *(const float2*)&WqT2[2*s+33][2*lane];
            d0.x += wa0.x*aX; d0.y += wa0.y*aX;
            d1.x += wa1.x*aY; d1.y += wa1.y*aY;
            d2.x += wb0.x*bX; d2.y += wb0.y*bX;
            d3.x += wb1.x*bY; d3.y += wb1.y*bY;
        }
        float2 q2;
        q2.x = q2v.x + (d0.x + d1.x) + (d2.x + d3.x);
        q2.y = q2v.y + (d0.y + d1.y) + (d2.y + d3.y);

        // Phase D: batched block-2 logits + softmax
        #pragma unroll
        for (int n = 0; n < Nv; n++)
            pt[n] = q2.x*k2s[n].x + q2.y*k2s[n].y;
        #pragma unroll
        for (int off = 16; off; off >>= 1)
            #pragma unroll
            for (int n = 0; n < Nv; n++)
                pt[n] += __shfl_xor_sync(0xffffffffu, pt[n], off);
        #pragma unroll
        for (int n = 0; n < Nv; n++)
            lgs[n] = ((mbits >> n) & 1u) ? pt[n]*0.125f : NEGV;
        float mx2 = lgs[0];
        #pragma unroll
        for (int n = 1; n < Nv; n++) mx2 = fmaxf(mx2, lgs[n]);
        float se2 = 0.f;
        float2 y2 = make_float2(0.f, 0.f);
        #pragma unroll
        for (int n = 0; n < Nv; n++) {
            float e = __expf(lgs[n] - mx2);
            se2 += e;
            y2.x += e*k2s[n].x;
            y2.y += e*k2s[n].y;
        }
        float inv2 = __fdiv_rn(1.0f, se2);
        float2 o;
        o.x = f1.x + y2.x*inv2;
        o.y = f1.y + y2.y*inv2;
        *(float2*)&out[(size_t)p*64 + 2*lane] = o;
    }
}

// ---------------------------------------------------------------------------
extern "C" void kernel_launch(void* const* d_in, const int* in_sizes, int n_in,
                              void* d_out, int out_size)
{
    (void)in_sizes; (void)n_in; (void)out_size;
    const float* img    = (const float*)d_in[0];
    const int*   coords = (const int*)  d_in[1];
    const float* vox    = (const float*)d_in[2];
    const float* proj   = (const float*)d_in[3];
    const float* orig   = (const float*)d_in[4];
    const int*   cmask  = (const int*)  d_in[5];
    const float* Wq1 = (const float*)d_in[6];
    const float* bq1 = (const float*)d_in[7];
    const float* Wk1 = (const float*)d_in[8];
    const float* bk1 = (const float*)d_in[9];
    const float* Wq2 = (const float*)d_in[10];
    const float* bq2 = (const float*)d_in[11];
    const float* Wk2 = (const float*)d_in[12];
    const float* bk2 = (const float*)d_in[13];
    float* out = (float*)d_out;

    const int KQ_SMEM = (KM_SMEM > QG_SMEM) ? KM_SMEM : QG_SMEM;  // 38528
    static int smem_set = 0;
    if (!smem_set) {
        cudaFuncSetAttribute(keymap_qgemm_kernel,
                             cudaFuncAttributeMaxDynamicSharedMemorySize, KQ_SMEM);
        smem_set = 1;
    }

    void* cntp = nullptr;
    cudaGetSymbolAddress(&cntp, g_selcnt);
    cudaMemsetAsync(cntp, 0, sizeof(int));

    keymap_qgemm_kernel<<<KM_BLOCKS + QG_BLOCKS + CP_BLOCKS, 256, KQ_SMEM>>>(
        img, Wk1, bk1, Wk2, bk2, vox, Wq1, bq1, Wq2, bq2, cmask, out);
    attn_fused_kernel<<<AT_BLOCKS, 256>>>(vox, coords, proj, orig, Wq2, out);
}

// round 14
// speedup vs baseline: 3.8755x; 1.0214x over previous
#include <cuda_runtime.h>
#include <cuda_fp16.h>
#include <cstdint>

#define Bc 2
#define Nv 9
#define CBc 80
#define Hh 120
#define Ww 160
#define Dd 64
#define Pp 80000
#define HW (Hh*Ww)            // 19200
#define MTOT (Bc*Nv*HW)       // 345600

#define KM_BLOCKS (MTOT/128)         // 2700
#define QG_BLOCKS (Pp/128)           // 625
#define CP_BLOCKS ((Pp + 255)/256)   // 313
#define AT_BLOCKS ((Pp + 31)/32)     // 2500

// Interleaved fp16 key maps: record = 64 half2 words per pixel (256 B).
// word 2j   = {KM1[2j], KM1[2j+1]},  word 2j+1 = {KM2[2j], KM2[2j+1]}
__device__ __half2 g_KMIh[(size_t)MTOT*64];
__device__ float   g_Q[(size_t)Pp*128];    // [p][0:64]=q1, [p][64:128]=q2v
__device__ int     g_selcnt;
__device__ int     g_selidx[Pp];

// smem byte layout for keymap path
#define BH_BYTES   (128*176)          // Bh[128 d][88 halfs] (80 used + pad)
#define AH_BYTES   (128*48)           // one A buffer: [128 px][24 halfs] (16 used)
#define KM_SMEM    (BH_BYTES + 2*AH_BYTES + 512)   // 35328
#define QG_SMEM    ((64*132 + 8*132 + 128)*4)      // 38528

__device__ __forceinline__ uint32_t h2u(__half2 h) {
    return *(uint32_t*)&h;
}

__device__ __forceinline__ float frcp(float x) {
    float r;
    asm("rcp.approx.f32 %0, %1;" : "=f"(r) : "f"(x));
    return r;
}

__device__ __forceinline__ void mma_f16(float* c,
                                        uint32_t a0, uint32_t a1,
                                        uint32_t a2, uint32_t a3,
                                        uint32_t b0, uint32_t b1) {
    asm volatile(
        "mma.sync.aligned.m16n8k16.row.col.f32.f16.f16.f32 "
        "{%0,%1,%2,%3},{%4,%5,%6,%7},{%8,%9},{%0,%1,%2,%3};"
        : "+f"(c[0]), "+f"(c[1]), "+f"(c[2]), "+f"(c[3])
        : "r"(a0), "r"(a1), "r"(a2), "r"(a3), "r"(b0), "r"(b1));
}

// ---------------------------------------------------------------------------
// Merged kernel 1:
//   blocks [0, KM)          : key_maps (fp16 MMA m16n8k16, fp32 acc, fp16 out)
//   blocks [KM, KM+QG)      : q-GEMM (fp32 cores)
//   blocks [KM+QG, +CP)     : compaction (sel list + passthrough rows)
// ---------------------------------------------------------------------------
__global__ __launch_bounds__(256) void keymap_qgemm_kernel(
    const float* __restrict__ img,
    const float* __restrict__ Wk1, const float* __restrict__ bk1,
    const float* __restrict__ Wk2, const float* __restrict__ bk2,
    const float* __restrict__ vox,
    const float* __restrict__ Wq1, const float* __restrict__ bq1,
    const float* __restrict__ Wq2, const float* __restrict__ bq2,
    const int*   __restrict__ cmask,
    float* __restrict__ out)
{
    extern __shared__ __align__(16) float dyn[];
    int tid = threadIdx.x;

    if (blockIdx.x < KM_BLOCKS) {
        // ================= keymap: fp16 MMA path =================
        char*  smem    = (char*)dyn;
        char*  BhB     = smem;                      // halfs, row stride 176 B
        char*  AhB     = smem + BH_BYTES;           // 2 buffers, row stride 48 B
        float* bias_sh = (float*)(smem + BH_BYTES + 2*AH_BYTES);

        int m0   = blockIdx.x * 128;
        int bn   = m0 / HW;
        int pix0 = m0 - bn*HW;
        const float* Abase = img + (size_t)bn*CBc*HW + pix0;

        int pxl   = tid & 127;        // loader: pixel column
        int khalf = tid >> 7;         // loader: k-octet (0/1)
        const float* lsrc0 = Abase + (size_t)(khalf*8)*HW + pxl;

        // prefetch chunk 0 into registers
        float f[8];
        #pragma unroll
        for (int j = 0; j < 8; j++) f[j] = lsrc0[(size_t)j*HW];

        // weights -> fp16 in smem: Bh[d][k]
        for (int t = tid; t < 128*CBc; t += 256) {
            int d = t / CBc, k = t - d*CBc;
            float w = (d < 64) ? Wk1[d*CBc + k] : Wk2[(d-64)*CBc + k];
            *(__half*)(BhB + d*176 + k*2) = __float2half(w);
        }
        if (tid < 128) bias_sh[tid] = (tid < 64) ? bk1[tid] : bk2[tid-64];

        // store chunk 0
        {
            uint4 u;
            u.x = h2u(__floats2half2_rn(f[0], f[1]));
            u.y = h2u(__floats2half2_rn(f[2], f[3]));
            u.z = h2u(__floats2half2_rn(f[4], f[5]));
            u.w = h2u(__floats2half2_rn(f[6], f[7]));
            *(uint4*)(AhB + pxl*48 + khalf*16) = u;
        }
        __syncthreads();

        int lane = tid & 31, warp = tid >> 5;
        int r4 = lane >> 2, tg = lane & 3;
        int wm = warp & 3, wn = warp >> 2;     // wm: 32-px group, wn: 64-d half

        float acc[2][8][4];
        #pragma unroll
        for (int mf = 0; mf < 2; mf++)
            #pragma unroll
            for (int nf = 0; nf < 8; nf++)
                #pragma unroll
                for (int i = 0; i < 4; i++) acc[mf][nf][i] = 0.f;

        #pragma unroll
        for (int kc = 0; kc < 5; kc++) {       // K = 80 = 5 x 16
            if (kc < 4) {                      // prefetch next chunk (LDG only)
                const float* ls = Abase + (size_t)((kc+1)*16 + khalf*8)*HW + pxl;
                #pragma unroll
                for (int j = 0; j < 8; j++) f[j] = ls[(size_t)j*HW];
            }

            const char* A = AhB + (kc & 1)*AH_BYTES;
            // load BOTH A fragment sets first, then stream B once
            uint32_t a[2][4];
            #pragma unroll
            for (int mf = 0; mf < 2; mf++) {
                const char* ar = A + (wm*32 + mf*16 + r4)*48 + tg*4;
                a[mf][0] = *(const uint32_t*)(ar);
                a[mf][1] = *(const uint32_t*)(ar + 8*48);
                a[mf][2] = *(const uint32_t*)(ar + 16);
                a[mf][3] = *(const uint32_t*)(ar + 8*48 + 16);
            }
            #pragma unroll
            for (int nf = 0; nf < 8; nf++) {
                const char* br = BhB + (wn*64 + nf*8 + r4)*176 + kc*32 + tg*4;
                uint32_t b0 = *(const uint32_t*)(br);
                uint32_t b1 = *(const uint32_t*)(br + 16);
                mma_f16(acc[0][nf], a[0][0], a[0][1], a[0][2], a[0][3], b0, b1);
                mma_f16(acc[1][nf], a[1][0], a[1][1], a[1][2], a[1][3], b0, b1);
            }

            if (kc < 4) {                      // store next chunk, then sync
                uint4 u;
                u.x = h2u(__floats2half2_rn(f[0], f[1]));
                u.y = h2u(__floats2half2_rn(f[2], f[3]));
                u.z = h2u(__floats2half2_rn(f[4], f[5]));
                u.w = h2u(__floats2half2_rn(f[6], f[7]));
                *(uint4*)(AhB + ((kc+1)&1)*AH_BYTES + pxl*48 + khalf*16) = u;
                __syncthreads();
            }
        }

        // epilogue: bias + fp16 interleaved store
        #pragma unroll
        for (int nf = 0; nf < 8; nf++) {
            int dl   = wn*64 + nf*8 + 2*tg;
            float b0 = bias_sh[dl], b1 = bias_sh[dl+1];
            int widx = (wn == 0) ? dl : (dl - 63);  // half2 word in 64-word record
            #pragma unroll
            for (int mf = 0; mf < 2; mf++) {
                int px = m0 + wm*32 + mf*16 + r4;
                g_KMIh[(size_t)px*64 + widx] =
                    __floats2half2_rn(acc[mf][nf][0]+b0, acc[mf][nf][1]+b1);
                g_KMIh[(size_t)(px+8)*64 + widx] =
                    __floats2half2_rn(acc[mf][nf][2]+b0, acc[mf][nf][3]+b1);
            }
        }
        return;
    }

    if (blockIdx.x < KM_BLOCKS + QG_BLOCKS) {
        // ================= q-GEMM path (fp32 cores) =================
        float* BshT    = dyn;                    // [64][132]
        float* Ash2    = BshT + 64*132;          // [8][132]
        float* bias_sh = Ash2 + 8*132;           // [128]

        {
            int d  = tid >> 1;
            const float* src = (d < 64) ? &Wq1[d*64] : &Wq2[(d-64)*64];
            #pragma unroll
            for (int i = 0; i < 8; i++) {
                int k = (tid & 1)*4 + 8*i;
                float4 w = *(const float4*)&src[k];
                BshT[(k+0)*132 + d] = w.x; BshT[(k+1)*132 + d] = w.y;
                BshT[(k+2)*132 + d] = w.z; BshT[(k+3)*132 + d] = w.w;
            }
        }
        if (tid < 128) bias_sh[tid] = (tid < 64) ? bq1[tid] : bq2[tid-64];

        int p0 = (blockIdx.x - KM_BLOCKS) * 128;
        int tx = tid & 15, ty = tid >> 4;

        float acc[8][8];
        #pragma unroll
        for (int i = 0; i < 8; i++)
            #pragma unroll
            for (int j = 0; j < 8; j++) acc[i][j] = 0.f;

        #pragma unroll
        for (int kc = 0; kc < 8; kc++) {
            __syncthreads();
            {
                int px = tid >> 1;
                int k0 = (tid & 1)*4;
                float4 a = *(const float4*)&vox[(size_t)(p0+px)*64 + kc*8 + k0];
                Ash2[(k0+0)*132 + px] = a.x; Ash2[(k0+1)*132 + px] = a.y;
                Ash2[(k0+2)*132 + px] = a.z; Ash2[(k0+3)*132 + px] = a.w;
            }
            __syncthreads();
            #pragma unroll
            for (int k = 0; k < 8; k++) {
                float4 a0 = *(const float4*)&Ash2[k*132 + ty*4];
                float4 a1 = *(const float4*)&Ash2[k*132 + 64 + ty*4];
                float4 b0 = *(const float4*)&BshT[(kc*8+k)*132 + tx*4];
                float4 b1 = *(const float4*)&BshT[(kc*8+k)*132 + 64 + tx*4];
                float av[8] = {a0.x,a0.y,a0.z,a0.w, a1.x,a1.y,a1.z,a1.w};
                float bv[8] = {b0.x,b0.y,b0.z,b0.w, b1.x,b1.y,b1.z,b1.w};
                #pragma unroll
                for (int i = 0; i < 8; i++)
                    #pragma unroll
                    for (int j = 0; j < 8; j++)
                        acc[i][j] += av[i] * bv[j];
            }
        }

        float bj1[4], bj2[4];
        #pragma unroll
        for (int j = 0; j < 4; j++) {
            bj1[j] = bias_sh[tx*4 + j];
            bj2[j] = bias_sh[64 + tx*4 + j];
        }
        #pragma unroll
        for (int i = 0; i < 8; i++) {
            int p = p0 + ((i < 4) ? (ty*4 + i) : (64 + ty*4 + (i - 4)));
            float4 o1 = make_float4(acc[i][0]+bj1[0], acc[i][1]+bj1[1],
                                    acc[i][2]+bj1[2], acc[i][3]+bj1[3]);
            float4 o2 = make_float4(acc[i][4]+bj2[0], acc[i][5]+bj2[1],
                                    acc[i][6]+bj2[2], acc[i][7]+bj2[3]);
            *(float4*)&g_Q[(size_t)p*128 + tx*4]      = o1;
            *(float4*)&g_Q[(size_t)p*128 + 64 + tx*4] = o2;
        }
        return;
    }

    // ================= compaction path =================
    {
        int cb   = blockIdx.x - KM_BLOCKS - QG_BLOCKS;
        int p    = cb * 256 + tid;
        int lane = tid & 31;

        bool sel = (p < Pp) && (cmask[p] > 1);
        unsigned mask = __ballot_sync(0xffffffffu, sel);

        int wbase = 0;
        if (lane == 0) wbase = atomicAdd(&g_selcnt, __popc(mask));
        wbase = __shfl_sync(0xffffffffu, wbase, 0);
        if (sel)
            g_selidx[wbase + __popc(mask & ((1u << lane) - 1u))] = p;

        int rowbase = cb * 256 + (tid >> 5) * 32;
        #pragma unroll 4
        for (int j = 0; j < 32; j++) {
            int pj = rowbase + j;
            if (pj < Pp && !((mask >> j) & 1u)) {
                float2 t = *(const float2*)&vox[(size_t)pj*64 + 2*lane];
                *(float2*)&out[(size_t)pj*64 + 2*lane] = t;
            }
        }
    }
}

// ---------------------------------------------------------------------------
// Kernel 2: fused attention over DENSE sel list. 4 points per warp,
// rcp.approx projection, no-max softmax with zero-denominator guard.
// ---------------------------------------------------------------------------
__global__ __launch_bounds__(256, 4) void attn_fused_kernel(
    const float* __restrict__ vox,
    const int*   __restrict__ coords,
    const float* __restrict__ proj,
    const float* __restrict__ origins,
    const float* __restrict__ Wq2,
    float* __restrict__ out)
{
    __shared__ float WqT2[64][64];        // WqT2[i][d] = Wq2[d][i]
    __shared__ float projs[Bc*Nv*12];
    __shared__ float orig_s[Bc*3];

    int cnt = g_selcnt;
    if (blockIdx.x * 32 >= cnt) return;   // block-uniform early exit

    int tid = threadIdx.x;
    for (int t = tid; t < 1024; t += 256) {
        int d = t >> 4, i0 = (t & 15) * 4;
        float4 w = *(const float4*)&Wq2[d*64 + i0];
        WqT2[i0+0][d] = w.x; WqT2[i0+1][d] = w.y;
        WqT2[i0+2][d] = w.z; WqT2[i0+3][d] = w.w;
    }
    if (tid < Bc*Nv*12) projs[tid] = proj[tid];
    if (tid < Bc*3)     orig_s[tid] = origins[tid];
    __syncthreads();

    int warp = tid >> 5, lane = tid & 31;

    #pragma unroll 1
    for (int c = 0; c < 4; c++) {
        int widx = blockIdx.x * 32 + c * 8 + warp;
        if (widx >= cnt) break;           // warp-uniform
        int p = g_selidx[widx];

        float2 v   = *(const float2*)&vox[(size_t)p*64 + 2*lane];
        float2 q1  = *(const float2*)&g_Q[(size_t)p*128 + 2*lane];
        float2 q2v = *(const float2*)&g_Q[(size_t)p*128 + 64 + 2*lane];

        int4 cc = __ldg((const int4*)coords + p);
        int bi = cc.w;
        float X = (float)cc.x * 0.16f + orig_s[bi*3 + 0];
        float Y = (float)cc.y * 0.16f + orig_s[bi*3 + 1];
        float Z = (float)cc.z * 0.16f + orig_s[bi*3 + 2];

        float2 k1s[9], k2s[9];
        unsigned mbits = 0;

        // Phase A: gather all views
        #pragma unroll
        for (int n = 0; n < Nv; n++) {
            const float* Pm = &projs[(bi*Nv + n)*12];
            float c0 = Pm[0]*X + Pm[1]*Y + Pm[2]*Z  + Pm[3];
            float c1 = Pm[4]*X + Pm[5]*Y + Pm[6]*Z  + Pm[7];
            float c2 = Pm[8]*X + Pm[9]*Y + Pm[10]*Z + Pm[11];
            float inv = frcp(c2);
            float txp = c0 * inv;
            float typ = c1 * inv;
            bool msk = (c2 > 0.0f) &&
                       (txp >= 0.0f) && (txp <= (float)(Ww-1)) &&
                       (typ >= 0.0f) && (typ <= (float)(Hh-1));
            float px = msk ? txp : 0.0f;
            float py = msk ? typ : 0.0f;

            float x0f = floorf(px), y0f = floorf(py);
            float fx = px - x0f,    fy = py - y0f;
            int x0 = (int)x0f, y0 = (int)y0f;
            bool vx1 = (x0 + 1) < Ww;
            bool vy1 = (y0 + 1) < Hh;
            int x1 = vx1 ? x0 + 1 : x0;
            int y1r = vy1 ? y0 + 1 : y0;
            float mskf = msk ? 1.f : 0.f;
            float w00 = (1.f-fx)*(1.f-fy) * mskf;
            float w01 = (vx1 ? fx*(1.f-fy) : 0.f) * mskf;
            float w10 = (vy1 ? (1.f-fx)*fy : 0.f) * mskf;
            float w11 = ((vx1 && vy1) ? fx*fy : 0.f) * mskf;

            const __half2* rb = g_KMIh + ((size_t)(bi*Nv + n)*HW)*64 + 2*lane;
            uint2 u00 = *(const uint2*)(rb + (size_t)(y0 *Ww + x0)*64);
            uint2 u01 = *(const uint2*)(rb + (size_t)(y0 *Ww + x1)*64);
            uint2 u10 = *(const uint2*)(rb + (size_t)(y1r*Ww + x0)*64);
            uint2 u11 = *(const uint2*)(rb + (size_t)(y1r*Ww + x1)*64);

            float2 a00 = __half22float2(*(__half2*)&u00.x);
            float2 b00 = __half22float2(*(__half2*)&u00.y);
            float2 a01 = __half22float2(*(__half2*)&u01.x);
            float2 b01 = __half22float2(*(__half2*)&u01.y);
            float2 a10 = __half22float2(*(__half2*)&u10.x);
            float2 b10 = __half22float2(*(__half2*)&u10.y);
            float2 a11 = __half22float2(*(__half2*)&u11.x);
            float2 b11 = __half22float2(*(__half2*)&u11.y);

            k1s[n].x = w00*a00.x + w01*a01.x + w10*a10.x + w11*a11.x;
            k1s[n].y = w00*a00.y + w01*a01.y + w10*a10.y + w11*a11.y;
            k2s[n].x = w00*b00.x + w01*b01.x + w10*b10.x + w11*b11.x;
            k2s[n].y = w00*b00.y + w01*b01.y + w10*b10.y + w11*b11.y;
            mbits |= (msk ? 1u : 0u) << n;
        }

        // Phase B: batched block-1 logit reductions
        float pt[9];
        #pragma unroll
        for (int n = 0; n < Nv; n++)
            pt[n] = q1.x*k1s[n].x + q1.y*k1s[n].y;
        #pragma unroll
        for (int off = 16; off; off >>= 1)
            #pragma unroll
            for (int n = 0; n < Nv; n++)
                pt[n] += __shfl_xor_sync(0xffffffffu, pt[n], off);

        // softmax 1 (no max-sub: logits bounded; masked -> exactly 0;
        // empty-mask guard: inv = 0 when se == 0)
        float se = 0.f;
        float2 y1 = make_float2(0.f, 0.f);
        #pragma unroll
        for (int n = 0; n < Nv; n++) {
            float e = ((mbits >> n) & 1u) ? __expf(pt[n]*0.125f) : 0.f;
            se += e;
            y1.x += e*k1s[n].x;
            y1.y += e*k1s[n].y;
        }
        float inv1 = (se > 0.f) ? __fdiv_rn(1.0f, se) : 0.f;
        float2 yn = make_float2(y1.x*inv1, y1.y*inv1);
        float2 f1 = make_float2(v.x + yn.x, v.y + yn.y);

        // q2 = q2v + Wq2 @ yn  (4-way split accumulators)
        float2 d0 = make_float2(0.f,0.f), d1 = d0, d2 = d0, d3 = d0;
        #pragma unroll
        for (int s = 0; s < 16; s++) {
            float aX = __shfl_sync(0xffffffffu, yn.x, s);
            float aY = __shfl_sync(0xffffffffu, yn.y, s);
            float bX = __shfl_sync(0xffffffffu, yn.x, s + 16);
            float bY = __shfl_sync(0xffffffffu, yn.y, s + 16);
            float2 wa0 = *(const float2*)&WqT2[2*s][2*lane];
            float2 wa1 = *(const float2*)&WqT2[2*s+1][2*lane];
            float2 wb0 = *(const float2*)&WqT2[2*s+32][2*lane];
            float2 wb1 = *(const float2*)&WqT2[2*s+33][2*lane];
            d0.x += wa0.x*aX; d0.y += wa0.y*aX;
            d1.x += wa1.x*aY; d1.y += wa1.y*aY;
            d2.x += wb0.x*bX; d2.y += wb0.y*bX;
            d3.x += wb1.x*bY; d3.y += wb1.y*bY;
        }
        float2 q2;
        q2.x = q2v.x + (d0.x + d1.x) + (d2.x + d3.x);
        q2.y = q2v.y + (d0.y + d1.y) + (d2.y + d3.y);

        // Phase D: batched block-2 logits + softmax
        #pragma unroll
        for (int n = 0; n < Nv; n++)
            pt[n] = q2.x*k2s[n].x + q2.y*k2s[n].y;
        #pragma unroll
        for (int off = 16; off; off >>= 1)
            #pragma unroll
            for (int n = 0; n < Nv; n++)
                pt[n] += __shfl_xor_sync(0xffffffffu, pt[n], off);
        float se2 = 0.f;
        float2 y2 = make_float2(0.f, 0.f);
        #pragma unroll
        for (int n = 0; n < Nv; n++) {
            float e = ((mbits >> n) & 1u) ? __expf(pt[n]*0.125f) : 0.f;
            se2 += e;
            y2.x += e*k2s[n].x;
            y2.y += e*k2s[n].y;
        }
        float inv2 = (se2 > 0.f) ? __fdiv_rn(1.0f, se2) : 0.f;
        float2 o;
        o.x = f1.x + y2.x*inv2;
        o.y = f1.y + y2.y*inv2;
        *(float2*)&out[(size_t)p*64 + 2*lane] = o;
    }
}

// ---------------------------------------------------------------------------
extern "C" void kernel_launch(void* const* d_in, const int* in_sizes, int n_in,
                              void* d_out, int out_size)
{
    (void)in_sizes; (void)n_in; (void)out_size;
    const float* img    = (const float*)d_in[0];
    const int*   coords = (const int*)  d_in[1];
    const float* vox    = (const float*)d_in[2];
    const float* proj   = (const float*)d_in[3];
    const float* orig   = (const float*)d_in[4];
    const int*   cmask  = (const int*)  d_in[5];
    const float* Wq1 = (const float*)d_in[6];
    const float* bq1 = (const float*)d_in[7];
    const float* Wk1 = (const float*)d_in[8];
    const float* bk1 = (const float*)d_in[9];
    const float* Wq2 = (const float*)d_in[10];
    const float* bq2 = (const float*)d_in[11];
    const float* Wk2 = (const float*)d_in[12];
    const float* bk2 = (const float*)d_in[13];
    float* out = (float*)d_out;

    const int KQ_SMEM = (KM_SMEM > QG_SMEM) ? KM_SMEM : QG_SMEM;  // 38528
    static int smem_set = 0;
    if (!smem_set) {
        cudaFuncSetAttribute(keymap_qgemm_kernel,
                             cudaFuncAttributeMaxDynamicSharedMemorySize, KQ_SMEM);
        smem_set = 1;
    }

    void* cntp = nullptr;
    cudaGetSymbolAddress(&cntp, g_selcnt);
    cudaMemsetAsync(cntp, 0, sizeof(int));

    keymap_qgemm_kernel<<<KM_BLOCKS + QG_BLOCKS + CP_BLOCKS, 256, KQ_SMEM>>>(
        img, Wk1, bk1, Wk2, bk2, vox, Wq1, bq1, Wq2, bq2, cmask, out);
    attn_fused_kernel<<<AT_BLOCKS, 256>>>(vox, coords, proj, orig, Wq2, out);
}